// round 10
// baseline (speedup 1.0000x reference)
#include <cuda_runtime.h>
#include <cuda_fp16.h>
#include <math.h>
#include <stdint.h>

// ---------------- Problem constants ----------------
#define BATCH 4
#define LSEQ  1024
#define DMODEL 1024
#define HEADS 16
#define DKV   64
#define DFF   4096
#define TOK   (BATCH * LSEQ)
#define NBUCK 32
#define NEGINF (-1e9f)

// ---------------- Scratch ----------------
__device__ __half g_xnorm[TOK * DMODEL];
__device__ __half g_qkv[TOK * 3072];
__device__ __half g_kvx[TOK * 2048];
__device__ __half g_att[TOK * DMODEL];
__device__ float  g_h[TOK * DMODEL];
__device__ __half g_encr[TOK * DMODEL];
__device__ __half g_ffn[TOK * DFF];
__device__ __half g_wh[16 * 1024 * 1024];   // fp16 weights, transposed [N][K]
__device__ int    g_bucket[LSEQ];

#define WH_QKV 0                        // [3072][1024]
#define WH_CAQ (3 * 1048576)            // [1024][1024]
#define WH_KVX (4 * 1048576)            // [2048][1024]
#define WH_SAO (6 * 1048576)
#define WH_CAO (7 * 1048576)
#define WH_WI  (8 * 1048576)            // [4096][1024]
#define WH_WO  (12 * 1048576)           // [1024][4096]

// ---------------- helpers ----------------
__device__ __forceinline__ void mma_f16(float (&d)[4], const uint32_t (&a)[4],
                                        uint32_t b0, uint32_t b1) {
    asm volatile(
        "mma.sync.aligned.m16n8k16.row.col.f32.f16.f16.f32 "
        "{%0,%1,%2,%3}, {%4,%5,%6,%7}, {%8,%9}, {%0,%1,%2,%3};"
        : "+f"(d[0]), "+f"(d[1]), "+f"(d[2]), "+f"(d[3])
        : "r"(a[0]), "r"(a[1]), "r"(a[2]), "r"(a[3]), "r"(b0), "r"(b1));
}
__device__ __forceinline__ void ldsm4(uint32_t (&r)[4], uint32_t addr) {
    asm volatile("ldmatrix.sync.aligned.m8n8.x4.shared.b16 {%0,%1,%2,%3}, [%4];"
                 : "=r"(r[0]), "=r"(r[1]), "=r"(r[2]), "=r"(r[3]) : "r"(addr));
}
__device__ __forceinline__ void ldsm4t(uint32_t (&r)[4], uint32_t addr) {
    asm volatile("ldmatrix.sync.aligned.m8n8.x4.trans.shared.b16 {%0,%1,%2,%3}, [%4];"
                 : "=r"(r[0]), "=r"(r[1]), "=r"(r[2]), "=r"(r[3]) : "r"(addr));
}
__device__ __forceinline__ void cp16s(uint32_t dst, const void* src) {
    asm volatile("cp.async.cg.shared.global [%0], [%1], 16;" :: "r"(dst), "l"(src));
}
__device__ __forceinline__ void cp_commit() { asm volatile("cp.async.commit_group;"); }
__device__ __forceinline__ void cp_wait0()  { asm volatile("cp.async.wait_group 0;" ::: "memory"); }

// ---------------- prep: batched 64x64 transpose fp32[1024][1024] -> fp16 ---
struct TP8 {
    const float* src[8];
    unsigned dst_off[8];
};

__global__ void __launch_bounds__(256)
transpose_batch(TP8 args, __half* __restrict__ whbase) {
    __shared__ float t[64][65];
    int z = blockIdx.z;
    const float* W = args.src[z];
    __half* Wt = whbase + args.dst_off[z];
    int n0 = blockIdx.x * 64, k0 = blockIdx.y * 64;
    int tid = threadIdx.x;
    int row = tid >> 2;
    int qc  = tid & 3;
    #pragma unroll
    for (int j = 0; j < 4; j++) {
        float4 v = *(const float4*)(W + (size_t)(k0 + row) * 1024 + n0 + qc * 16 + j * 4);
        t[row][qc * 16 + j * 4 + 0] = v.x;
        t[row][qc * 16 + j * 4 + 1] = v.y;
        t[row][qc * 16 + j * 4 + 2] = v.z;
        t[row][qc * 16 + j * 4 + 3] = v.w;
    }
    __syncthreads();
    #pragma unroll
    for (int j = 0; j < 2; j++) {
        __half hbuf[8];
        #pragma unroll
        for (int e = 0; e < 8; e++)
            hbuf[e] = __float2half(t[qc * 16 + j * 8 + e][row]);
        *(uint4*)(Wt + (size_t)(n0 + row) * 1024 + k0 + qc * 16 + j * 8) = *(uint4*)hbuf;
    }
}

__global__ void __launch_bounds__(256)
transpose_h2(const float* __restrict__ W, __half* __restrict__ Wt,
             int K, int N) {
    __shared__ float t[64][65];
    int n0 = blockIdx.x * 64, k0 = blockIdx.y * 64;
    int tid = threadIdx.x;
    int row = tid >> 2;
    int qc  = tid & 3;
    #pragma unroll
    for (int j = 0; j < 4; j++) {
        float4 v = *(const float4*)(W + (size_t)(k0 + row) * N + n0 + qc * 16 + j * 4);
        t[row][qc * 16 + j * 4 + 0] = v.x;
        t[row][qc * 16 + j * 4 + 1] = v.y;
        t[row][qc * 16 + j * 4 + 2] = v.z;
        t[row][qc * 16 + j * 4 + 3] = v.w;
    }
    __syncthreads();
    #pragma unroll
    for (int j = 0; j < 2; j++) {
        __half hbuf[8];
        #pragma unroll
        for (int e = 0; e < 8; e++)
            hbuf[e] = __float2half(t[qc * 16 + j * 8 + e][row]);
        *(uint4*)(Wt + (size_t)(n0 + row) * K + k0 + qc * 16 + j * 8) = *(uint4*)hbuf;
    }
}

__global__ void conv_half(const float* __restrict__ src, __half* __restrict__ dst, int n4) {
    int i = blockIdx.x * 256 + threadIdx.x;
    if (i < n4) {
        float4 v = ((const float4*)src)[i];
        __half2* d = (__half2*)(dst + (size_t)i * 4);
        d[0] = __floats2half2_rn(v.x, v.y);
        d[1] = __floats2half2_rn(v.z, v.w);
    }
}

// ---------------- RMS norm (vectorized) ----------------
template<bool HOUT>
__global__ void rms_kernel(const float* __restrict__ x,
                           const float* __restrict__ w, void* __restrict__ yv) {
    int row = blockIdx.x;
    int tid = threadIdx.x;
    float4 v = ((const float4*)(x + (size_t)row * DMODEL))[tid];
    float s = v.x * v.x + v.y * v.y + v.z * v.z + v.w * v.w;
    __shared__ float red[8];
    #pragma unroll
    for (int o = 16; o; o >>= 1) s += __shfl_xor_sync(0xffffffffu, s, o);
    if ((tid & 31) == 0) red[tid >> 5] = s;
    __syncthreads();
    if (tid < 8) {
        float t = red[tid];
        #pragma unroll
        for (int o = 4; o; o >>= 1) t += __shfl_xor_sync(0xffu, t, o);
        if (tid == 0) red[0] = rsqrtf(t * (1.0f / DMODEL) + 1e-6f);
    }
    __syncthreads();
    float inv = red[0];
    float4 wv = ((const float4*)w)[tid];
    float a = v.x * inv * wv.x, b = v.y * inv * wv.y;
    float c = v.z * inv * wv.z, d = v.w * inv * wv.w;
    if (HOUT) {
        __half2* yr = (__half2*)yv + (size_t)row * (DMODEL / 2);
        yr[tid * 2]     = __floats2half2_rn(a, b);
        yr[tid * 2 + 1] = __floats2half2_rn(c, d);
    } else {
        ((float4*)yv)[(size_t)row * (DMODEL / 4) + tid] = make_float4(a, b, c, d);
    }
}

// ---------------- fp16 GEMM: block 128x256x64, 8 warps 2Mx4N, warp 64x64 --
// A smem 128x144B, B smem 256x144B, 2-stage cp.async, single-buffer frags.
#define GA_TILE 18432
#define GB_TILE 36864
#define GEMM_SMEM (2 * GA_TILE + 2 * GB_TILE)

template<bool RELU, bool RES, bool HOUT>
__global__ void __launch_bounds__(256)
hgemm(const __half* __restrict__ A, const __half* __restrict__ B,
      const float* __restrict__ R, void* __restrict__ Cv,
      int M, int N, int K) {
    extern __shared__ char smc[];
    uint32_t S = (uint32_t)__cvta_generic_to_shared(smc);
    const uint32_t SB = S + 2 * GA_TILE;
    const int tid = threadIdx.x;
    const int warp = tid >> 5, lane = tid & 31;
    const int gid = lane >> 2, tg = lane & 3;
    const int wm = warp & 1, wn = warp >> 1;
    const int m0 = blockIdx.y * 128, n0 = blockIdx.x * 256;
    const __half* Ag = A + (size_t)m0 * K;
    const __half* Bg = B + (size_t)n0 * K;

    float acc[4][8][4];
    #pragma unroll
    for (int i = 0; i < 4; i++)
        #pragma unroll
        for (int j = 0; j < 8; j++)
            #pragma unroll
            for (int l = 0; l < 4; l++) acc[i][j][l] = 0.f;

    #define GLOAD(kt, s) do {                                                 \
        uint32_t ab = S + (s) * GA_TILE;                                      \
        uint32_t bb = SB + (s) * GB_TILE;                                     \
        _Pragma("unroll")                                                     \
        for (int i = 0; i < 4; i++) {                                         \
            int idx = tid + i * 256;                                          \
            int r = idx >> 3, c = idx & 7;                                    \
            cp16s(ab + r * 144 + c * 16, Ag + (size_t)r * K + (kt) + c * 8);  \
        }                                                                     \
        _Pragma("unroll")                                                     \
        for (int i = 0; i < 8; i++) {                                         \
            int idx = tid + i * 256;                                          \
            int r = idx >> 3, c = idx & 7;                                    \
            cp16s(bb + r * 144 + c * 16, Bg + (size_t)r * K + (kt) + c * 8);  \
        }                                                                     \
        cp_commit();                                                          \
    } while (0)

    GLOAD(0, 0);
    cp_wait0();
    __syncthreads();

    int s = 0;
    for (int kt = 0; kt < K; kt += 64) {
        bool more = (kt + 64 < K);
        if (more) GLOAD(kt + 64, s ^ 1);
        uint32_t ab = S + s * GA_TILE;
        uint32_t bb = SB + s * GB_TILE;
        #pragma unroll
        for (int ks = 0; ks < 4; ks++) {
            uint32_t af[4][4], bf[4][4];
            #pragma unroll
            for (int mt = 0; mt < 4; mt++)
                ldsm4(af[mt], ab + (wm * 64 + mt * 16 + (lane & 15)) * 144
                              + ks * 32 + (lane >> 4) * 16);
            #pragma unroll
            for (int g = 0; g < 4; g++)
                ldsm4(bf[g], bb + (wn * 64 + g * 16 + ((lane >> 4) << 3) + (lane & 7)) * 144
                             + ks * 32 + ((lane >> 3) & 1) * 16);
            #pragma unroll
            for (int mt = 0; mt < 4; mt++)
                #pragma unroll
                for (int nt = 0; nt < 8; nt++)
                    mma_f16(acc[mt][nt], af[mt],
                            bf[nt >> 1][(nt & 1) * 2], bf[nt >> 1][(nt & 1) * 2 + 1]);
        }
        if (more) cp_wait0();
        __syncthreads();
        s ^= 1;
    }

    #pragma unroll
    for (int mt = 0; mt < 4; mt++) {
        #pragma unroll
        for (int nt = 0; nt < 8; nt++) {
            int r0 = m0 + wm * 64 + mt * 16 + gid;
            int c  = n0 + wn * 64 + nt * 8 + tg * 2;
            float2 v0 = make_float2(acc[mt][nt][0], acc[mt][nt][1]);
            float2 v1 = make_float2(acc[mt][nt][2], acc[mt][nt][3]);
            if (RES) {
                float2 a0 = *(const float2*)(R + (size_t)r0 * N + c);
                float2 a1 = *(const float2*)(R + (size_t)(r0 + 8) * N + c);
                v0.x += a0.x; v0.y += a0.y; v1.x += a1.x; v1.y += a1.y;
            }
            if (RELU) {
                v0.x = fmaxf(v0.x, 0.f); v0.y = fmaxf(v0.y, 0.f);
                v1.x = fmaxf(v1.x, 0.f); v1.y = fmaxf(v1.y, 0.f);
            }
            if (HOUT) {
                __half* C = (__half*)Cv;
                *(__half2*)(C + (size_t)r0 * N + c)       = __floats2half2_rn(v0.x, v0.y);
                *(__half2*)(C + (size_t)(r0 + 8) * N + c) = __floats2half2_rn(v1.x, v1.y);
            } else {
                float* C = (float*)Cv;
                *(float2*)(C + (size_t)r0 * N + c) = v0;
                *(float2*)(C + (size_t)(r0 + 8) * N + c) = v1;
            }
        }
    }
    #undef GLOAD
}

// ---------------- T5 relative bucket table ----------------
__global__ void bucket_kernel() {
    int n = threadIdx.x;
    int b;
    if (n < 16) {
        b = n;
    } else {
        float nf = (float)n;
        int vl = 16 + (int)(logf(nf / 16.0f) / logf(8.0f) * 16.0f);
        b = vl < (NBUCK - 1) ? vl : (NBUCK - 1);
    }
    g_bucket[n] = b;
}

// ---------------- Fused fp16 flash attention (unchanged) ------------------
#define FQ_OFF 0
#define FK_OFF 18432
#define FV_OFF 36864
#define FP_OFF 55296
#define FMP_OFF 90112
#define FLP_OFF 92160
#define FMR_OFF 94208
#define FLR_OFF 95232
#define FL_SMEM 95744

template<bool SELF>
__global__ void __launch_bounds__(256)
flash_h(const __half* __restrict__ Qp, int qstride,
        const __half* __restrict__ Kp, int kstride,
        const __half* __restrict__ Vp, int vstride,
        const float* __restrict__ relb, const int* __restrict__ mask,
        __half* __restrict__ O) {
    extern __shared__ char smc[];
    uint32_t S = (uint32_t)__cvta_generic_to_shared(smc);
    float* mpart = (float*)(smc + FMP_OFF);
    float* lpart = (float*)(smc + FLP_OFF);
    float* mrun  = (float*)(smc + FMR_OFF);
    float* lrun  = (float*)(smc + FLR_OFF);

    int tid = threadIdx.x;
    int warp = tid >> 5, lane = tid & 31;
    int gid = lane >> 2, tg = lane & 3;
    int wm = warp & 1, wn = warp >> 1;
    int pm = warp & 3, pn = warp >> 2;
    int qt = blockIdx.x;
    int q0 = qt * 128;
    int bh = blockIdx.y;
    int b = bh >> 4, h = bh & 15;

    const __half* Qg = Qp + (size_t)(b * LSEQ + q0) * qstride + h * DKV;
    const __half* Kg = Kp + (size_t)(b * LSEQ) * kstride + h * DKV;
    const __half* Vg = Vp + (size_t)(b * LSEQ) * vstride + h * DKV;

    if (tid < 128) { mrun[tid] = -1e30f; lrun[tid] = 0.f; }

    #pragma unroll
    for (int i = 0; i < 4; i++) {
        int idx = tid + i * 256;
        int r = idx >> 3, c = idx & 7;
        cp16s(S + FQ_OFF + r * 144 + c * 16, Qg + (size_t)r * qstride + c * 8);
    }
    cp_commit();

    float oacc[2][4][4];
    #pragma unroll
    for (int i = 0; i < 2; i++)
        #pragma unroll
        for (int j = 0; j < 4; j++)
            #pragma unroll
            for (int l = 0; l < 4; l++) oacc[i][j][l] = 0.f;

    const int niter = SELF ? (qt + 1) : (LSEQ / 128);
    int p = 0;

    for (int it = 0; it < niter; it++) {
        int k0 = it * 128;
        #pragma unroll
        for (int i = 0; i < 4; i++) {
            int idx = tid + i * 256;
            int r = idx >> 3, c = idx & 7;
            cp16s(S + FK_OFF + r * 144 + c * 16, Kg + (size_t)(k0 + r) * kstride + c * 8);
            cp16s(S + FV_OFF + r * 144 + c * 16, Vg + (size_t)(k0 + r) * vstride + c * 8);
        }
        cp_commit();
        cp_wait0();
        __syncthreads();

        // ---- QK^T ----
        float sacc[4][4][4];
        #pragma unroll
        for (int i = 0; i < 4; i++)
            #pragma unroll
            for (int j = 0; j < 4; j++)
                #pragma unroll
                for (int l = 0; l < 4; l++) sacc[i][j][l] = 0.f;

        #pragma unroll
        for (int ks = 0; ks < 4; ks++) {
            uint32_t af[4][4], bf[2][4];
            #pragma unroll
            for (int mt = 0; mt < 4; mt++)
                ldsm4(af[mt], S + FQ_OFF + (wm * 64 + mt * 16 + (lane & 15)) * 144
                              + ks * 32 + (lane >> 4) * 16);
            #pragma unroll
            for (int g = 0; g < 2; g++)
                ldsm4(bf[g], S + FK_OFF + (wn * 32 + g * 16 + ((lane >> 4) << 3) + (lane & 7)) * 144
                             + ks * 32 + ((lane >> 3) & 1) * 16);
            #pragma unroll
            for (int mt = 0; mt < 4; mt++)
                #pragma unroll
                for (int nt = 0; nt < 4; nt++)
                    mma_f16(sacc[mt][nt], af[mt],
                            bf[nt >> 1][(nt & 1) * 2], bf[nt >> 1][(nt & 1) * 2 + 1]);
        }

        // ---- bias + mask ----
        bool cok[4][2];
        int ccol[4];
        #pragma unroll
        for (int nf = 0; nf < 4; nf++) {
            int c = k0 + wn * 32 + nf * 8 + tg * 2;
            ccol[nf] = c;
            cok[nf][0] = mask[b * LSEQ + c] > 0;
            cok[nf][1] = mask[b * LSEQ + c + 1] > 0;
        }
        #pragma unroll
        for (int mf = 0; mf < 4; mf++) {
            #pragma unroll
            for (int half = 0; half < 2; half++) {
                int qi = q0 + wm * 64 + mf * 16 + gid + half * 8;
                #pragma unroll
                for (int nf = 0; nf < 4; nf++) {
                    int c = ccol[nf];
                    if (SELF) {
                        int d0 = qi - c, d1 = d0 - 1;
                        sacc[mf][nf][half * 2]     += relb[g_bucket[d0 > 0 ? d0 : 0] * HEADS + h];
                        sacc[mf][nf][half * 2 + 1] += relb[g_bucket[d1 > 0 ? d1 : 0] * HEADS + h];
                        if (!((c     <= qi) && cok[nf][0])) sacc[mf][nf][half * 2]     += NEGINF;
                        if (!((c + 1 <= qi) && cok[nf][1])) sacc[mf][nf][half * 2 + 1] += NEGINF;
                    } else {
                        if (!cok[nf][0]) sacc[mf][nf][half * 2]     += NEGINF;
                        if (!cok[nf][1]) sacc[mf][nf][half * 2 + 1] += NEGINF;
                    }
                }
            }
        }

        // ---- partial row max ----
        #pragma unroll
        for (int mf = 0; mf < 4; mf++) {
            float mx0 = -1e30f, mx1 = -1e30f;
            #pragma unroll
            for (int nf = 0; nf < 4; nf++) {
                mx0 = fmaxf(mx0, fmaxf(sacc[mf][nf][0], sacc[mf][nf][1]));
                mx1 = fmaxf(mx1, fmaxf(sacc[mf][nf][2], sacc[mf][nf][3]));
            }
            mx0 = fmaxf(mx0, __shfl_xor_sync(0xffffffffu, mx0, 1));
            mx0 = fmaxf(mx0, __shfl_xor_sync(0xffffffffu, mx0, 2));
            mx1 = fmaxf(mx1, __shfl_xor_sync(0xffffffffu, mx1, 1));
            mx1 = fmaxf(mx1, __shfl_xor_sync(0xffffffffu, mx1, 2));
            if (tg == 0) {
                int r0 = wm * 64 + mf * 16 + gid;
                mpart[r0 * 4 + wn] = mx0;
                mpart[(r0 + 8) * 4 + wn] = mx1;
            }
        }
        __syncthreads();

        // ---- m_new, exp, P store (half), partial sums ----
        float* mold  = mrun + p * 128;
        float* mnewa = mrun + (p ^ 1) * 128;
        #pragma unroll
        for (int mf = 0; mf < 4; mf++) {
            #pragma unroll
            for (int half = 0; half < 2; half++) {
                int r = wm * 64 + mf * 16 + gid + half * 8;
                float mt = fmaxf(fmaxf(mpart[r * 4 + 0], mpart[r * 4 + 1]),
                                 fmaxf(mpart[r * 4 + 2], mpart[r * 4 + 3]));
                float mn = fmaxf(mold[r], mt);
                if (wn == 0 && tg == 0) mnewa[r] = mn;
                float sum = 0.f;
                #pragma unroll
                for (int nf = 0; nf < 4; nf++) {
                    float e0 = __expf(sacc[mf][nf][half * 2]     - mn);
                    float e1 = __expf(sacc[mf][nf][half * 2 + 1] - mn);
                    sum += e0 + e1;
                    int col = wn * 32 + nf * 8 + tg * 2;
                    *(__half2*)(smc + FP_OFF + r * 272 + col * 2) = __floats2half2_rn(e0, e1);
                }
                sum += __shfl_xor_sync(0xffffffffu, sum, 1);
                sum += __shfl_xor_sync(0xffffffffu, sum, 2);
                if (tg == 0) lpart[r * 4 + wn] = sum;
            }
        }
        __syncthreads();

        // ---- rescale O, update running sum ----
        #pragma unroll
        for (int mt2 = 0; mt2 < 2; mt2++) {
            #pragma unroll
            for (int half = 0; half < 2; half++) {
                int r = pm * 32 + mt2 * 16 + gid + half * 8;
                float rs = __expf(mold[r] - mnewa[r]);
                #pragma unroll
                for (int nf = 0; nf < 4; nf++) {
                    oacc[mt2][nf][half * 2]     *= rs;
                    oacc[mt2][nf][half * 2 + 1] *= rs;
                }
                if (pn == 0 && tg == 0)
                    lrun[r] = lrun[r] * rs + lpart[r * 4 + 0] + lpart[r * 4 + 1]
                                           + lpart[r * 4 + 2] + lpart[r * 4 + 3];
            }
        }

        // ---- P @ V ----
        #pragma unroll
        for (int ks = 0; ks < 8; ks++) {
            uint32_t af[2][4], bf[2][4];
            #pragma unroll
            for (int mt2 = 0; mt2 < 2; mt2++)
                ldsm4(af[mt2], S + FP_OFF + (pm * 32 + mt2 * 16 + (lane & 15)) * 272
                               + ks * 32 + (lane >> 4) * 16);
            #pragma unroll
            for (int g = 0; g < 2; g++)
                ldsm4t(bf[g], S + FV_OFF + (ks * 16 + ((lane >> 3) & 1) * 8 + (lane & 7)) * 144
                              + pn * 64 + g * 32 + (lane >> 4) * 16);
            #pragma unroll
            for (int mt2 = 0; mt2 < 2; mt2++)
                #pragma unroll
                for (int nt = 0; nt < 4; nt++)
                    mma_f16(oacc[mt2][nt], af[mt2],
                            bf[nt >> 1][(nt & 1) * 2], bf[nt >> 1][(nt & 1) * 2 + 1]);
        }

        __syncthreads();
        p ^= 1;
    }

    // ---- normalize, store half ----
    #pragma unroll
    for (int mt2 = 0; mt2 < 2; mt2++) {
        int rloc0 = pm * 32 + mt2 * 16 + gid;
        float inv0 = 1.0f / lrun[rloc0];
        float inv1 = 1.0f / lrun[rloc0 + 8];
        #pragma unroll
        for (int nf = 0; nf < 4; nf++) {
            int col = h * DKV + pn * 32 + nf * 8 + tg * 2;
            size_t row0 = (size_t)(b * LSEQ + q0 + rloc0);
            *(__half2*)(O + row0 * DMODEL + col)
                = __floats2half2_rn(oacc[mt2][nf][0] * inv0, oacc[mt2][nf][1] * inv0);
            *(__half2*)(O + (row0 + 8) * DMODEL + col)
                = __floats2half2_rn(oacc[mt2][nf][2] * inv1, oacc[mt2][nf][3] * inv1);
        }
    }
}

// ---------------- Orchestration -------------------------------------------
extern "C" void kernel_launch(void* const* d_in, const int* in_sizes, int n_in,
                              void* d_out, int out_size) {
    const float* enc    = (const float*)d_in[0];
    const float* hid    = (const float*)d_in[1];
    const float* ln1_w  = (const float*)d_in[2];
    const float* sa_q   = (const float*)d_in[3];
    const float* sa_k   = (const float*)d_in[4];
    const float* sa_v   = (const float*)d_in[5];
    const float* sa_o   = (const float*)d_in[6];
    const float* relb   = (const float*)d_in[7];
    const float* ln2_w  = (const float*)d_in[8];
    const float* ca_q   = (const float*)d_in[9];
    const float* ca_k   = (const float*)d_in[10];
    const float* ca_v   = (const float*)d_in[11];
    const float* ca_o   = (const float*)d_in[12];
    const float* ln3_w  = (const float*)d_in[13];
    const float* wi     = (const float*)d_in[14];
    const float* wo     = (const float*)d_in[15];
    const float* flnw   = (const float*)d_in[16];
    const int*   emask  = (const int*)d_in[17];
    const int*   dmask  = (const int*)d_in[18];
    float* out = (float*)d_out;

    __half *xn, *qkv, *kvx, *att, *encr, *ffn, *wh;
    float *h;
    cudaGetSymbolAddress((void**)&xn,   g_xnorm);
    cudaGetSymbolAddress((void**)&qkv,  g_qkv);
    cudaGetSymbolAddress((void**)&kvx,  g_kvx);
    cudaGetSymbolAddress((void**)&att,  g_att);
    cudaGetSymbolAddress((void**)&h,    g_h);
    cudaGetSymbolAddress((void**)&encr, g_encr);
    cudaGetSymbolAddress((void**)&ffn,  g_ffn);
    cudaGetSymbolAddress((void**)&wh,   g_wh);

    cudaFuncSetAttribute(hgemm<false,false,true>, cudaFuncAttributeMaxDynamicSharedMemorySize, GEMM_SMEM);
    cudaFuncSetAttribute(hgemm<false,true,false>, cudaFuncAttributeMaxDynamicSharedMemorySize, GEMM_SMEM);
    cudaFuncSetAttribute(hgemm<true,false,true>,  cudaFuncAttributeMaxDynamicSharedMemorySize, GEMM_SMEM);
    cudaFuncSetAttribute(flash_h<true>,  cudaFuncAttributeMaxDynamicSharedMemorySize, FL_SMEM);
    cudaFuncSetAttribute(flash_h<false>, cudaFuncAttributeMaxDynamicSharedMemorySize, FL_SMEM);

    dim3 tb2(256);
    dim3 gDD(4, 32);
    dim3 gQKV(12, 32);
    dim3 gKV(8, 32);
    dim3 gDF(16, 32);
    dim3 gFlash(LSEQ / 128, BATCH * HEADS);

    // ---- launch 1: all 8 DD weight transposes in one batched kernel ----
    TP8 tp;
    tp.src[0] = sa_q; tp.dst_off[0] = WH_QKV;
    tp.src[1] = sa_k; tp.dst_off[1] = WH_QKV + 1048576;
    tp.src[2] = sa_v; tp.dst_off[2] = WH_QKV + 2 * 1048576;
    tp.src[3] = ca_q; tp.dst_off[3] = WH_CAQ;
    tp.src[4] = ca_k; tp.dst_off[4] = WH_KVX;
    tp.src[5] = ca_v; tp.dst_off[5] = WH_KVX + 1048576;
    tp.src[6] = sa_o; tp.dst_off[6] = WH_SAO;
    tp.src[7] = ca_o; tp.dst_off[7] = WH_CAO;
    transpose_batch<<<dim3(16, 16, 8), tb2>>>(tp, wh);                          // 1
    transpose_h2<<<dim3(64, 16), tb2>>>(wi, wh + WH_WI, DMODEL, DFF);           // 2
    transpose_h2<<<dim3(16, 64), tb2>>>(wo, wh + WH_WO, DFF, DMODEL);           // 3
    bucket_kernel<<<1, 1024>>>();                                               // 4
    rms_kernel<true><<<TOK, 256>>>(hid, ln1_w, xn);                             // 5

    // ---- launch 6: the big fused QKV GEMM ----
    hgemm<false,false,true><<<gQKV, 256, GEMM_SMEM>>>(xn, wh + WH_QKV, nullptr, qkv, TOK, 3072, DMODEL);

    conv_half<<<(TOK * DMODEL / 4 + 255) / 256, 256>>>(enc, encr, TOK * DMODEL / 4);

    // ---- Self-attention ----
    flash_h<true><<<gFlash, 256, FL_SMEM>>>(qkv, 3072, qkv + 1024, 3072, qkv + 2048, 3072,
                                            relb, dmask, att);
    hgemm<false,true,false><<<gDD, 256, GEMM_SMEM>>>(att, wh + WH_SAO, hid, h, TOK, DMODEL, DMODEL);

    // ---- Cross-attention ----
    rms_kernel<true><<<TOK, 256>>>(h, ln2_w, xn);
    hgemm<false,false,true><<<gDD, 256, GEMM_SMEM>>>(xn, wh + WH_CAQ, nullptr, qkv, TOK, DMODEL, DMODEL);
    hgemm<false,false,true><<<gKV, 256, GEMM_SMEM>>>(encr, wh + WH_KVX, nullptr, kvx, TOK, 2048, DMODEL);
    flash_h<false><<<gFlash, 256, FL_SMEM>>>(qkv, 1024, kvx, 2048, kvx + 1024, 2048,
                                             nullptr, emask, att);
    hgemm<false,true,false><<<gDD, 256, GEMM_SMEM>>>(att, wh + WH_CAO, h, h, TOK, DMODEL, DMODEL);

    // ---- FFN ----
    rms_kernel<true><<<TOK, 256>>>(h, ln3_w, xn);
    hgemm<true,false,true><<<gDF, 256, GEMM_SMEM>>>(xn, wh + WH_WI, nullptr, ffn, TOK, DFF, DMODEL);
    hgemm<false,true,false><<<gDD, 256, GEMM_SMEM>>>(ffn, wh + WH_WO, h, h, TOK, DMODEL, DFF);

    // ---- Final norm ----
    rms_kernel<false><<<TOK, 256>>>(h, flnw, out);
}

// round 11
// speedup vs baseline: 1.0757x; 1.0757x over previous
#include <cuda_runtime.h>
#include <cuda_fp16.h>
#include <math.h>
#include <stdint.h>

// ---------------- Problem constants ----------------
#define BATCH 4
#define LSEQ  1024
#define DMODEL 1024
#define HEADS 16
#define DKV   64
#define DFF   4096
#define TOK   (BATCH * LSEQ)
#define NBUCK 32
#define NEGINF (-1e9f)

// ---------------- Scratch ----------------
__device__ __half g_xnorm[TOK * DMODEL];
__device__ __half g_qkv[TOK * 3072];
__device__ __half g_kvx[TOK * 2048];
__device__ __half g_att[TOK * DMODEL];
__device__ float  g_h[TOK * DMODEL];
__device__ __half g_encr[TOK * DMODEL];
__device__ __half g_ffn[TOK * DFF];
__device__ __half g_wh[16 * 1024 * 1024];   // fp16 weights, transposed [N][K]
__device__ int    g_bucket[LSEQ];

#define WH_QKV 0                        // [3072][1024]
#define WH_CAQ (3 * 1048576)            // [1024][1024]
#define WH_KVX (4 * 1048576)            // [2048][1024]
#define WH_SAO (6 * 1048576)
#define WH_CAO (7 * 1048576)
#define WH_WI  (8 * 1048576)            // [4096][1024]
#define WH_WO  (12 * 1048576)           // [1024][4096]

// ---------------- helpers ----------------
__device__ __forceinline__ void mma_f16(float (&d)[4], const uint32_t (&a)[4],
                                        uint32_t b0, uint32_t b1) {
    asm volatile(
        "mma.sync.aligned.m16n8k16.row.col.f32.f16.f16.f32 "
        "{%0,%1,%2,%3}, {%4,%5,%6,%7}, {%8,%9}, {%0,%1,%2,%3};"
        : "+f"(d[0]), "+f"(d[1]), "+f"(d[2]), "+f"(d[3])
        : "r"(a[0]), "r"(a[1]), "r"(a[2]), "r"(a[3]), "r"(b0), "r"(b1));
}
__device__ __forceinline__ void ldsm4(uint32_t (&r)[4], uint32_t addr) {
    asm volatile("ldmatrix.sync.aligned.m8n8.x4.shared.b16 {%0,%1,%2,%3}, [%4];"
                 : "=r"(r[0]), "=r"(r[1]), "=r"(r[2]), "=r"(r[3]) : "r"(addr));
}
__device__ __forceinline__ void ldsm4t(uint32_t (&r)[4], uint32_t addr) {
    asm volatile("ldmatrix.sync.aligned.m8n8.x4.trans.shared.b16 {%0,%1,%2,%3}, [%4];"
                 : "=r"(r[0]), "=r"(r[1]), "=r"(r[2]), "=r"(r[3]) : "r"(addr));
}
__device__ __forceinline__ void cp16s(uint32_t dst, const void* src) {
    asm volatile("cp.async.cg.shared.global [%0], [%1], 16;" :: "r"(dst), "l"(src));
}
__device__ __forceinline__ void cp_commit() { asm volatile("cp.async.commit_group;"); }
__device__ __forceinline__ void cp_wait0()  { asm volatile("cp.async.wait_group 0;" ::: "memory"); }

// ---------------- prep: batched 64x64 transpose fp32[1024][1024] -> fp16 ---
struct TP8 {
    const float* src[8];
    unsigned dst_off[8];
};

__global__ void __launch_bounds__(256)
transpose_batch(TP8 args, __half* __restrict__ whbase) {
    __shared__ float t[64][65];
    int z = blockIdx.z;
    const float* W = args.src[z];
    __half* Wt = whbase + args.dst_off[z];
    int n0 = blockIdx.x * 64, k0 = blockIdx.y * 64;
    int tid = threadIdx.x;
    int row = tid >> 2;
    int qc  = tid & 3;
    #pragma unroll
    for (int j = 0; j < 4; j++) {
        float4 v = *(const float4*)(W + (size_t)(k0 + row) * 1024 + n0 + qc * 16 + j * 4);
        t[row][qc * 16 + j * 4 + 0] = v.x;
        t[row][qc * 16 + j * 4 + 1] = v.y;
        t[row][qc * 16 + j * 4 + 2] = v.z;
        t[row][qc * 16 + j * 4 + 3] = v.w;
    }
    __syncthreads();
    #pragma unroll
    for (int j = 0; j < 2; j++) {
        __half hbuf[8];
        #pragma unroll
        for (int e = 0; e < 8; e++)
            hbuf[e] = __float2half(t[qc * 16 + j * 8 + e][row]);
        *(uint4*)(Wt + (size_t)(n0 + row) * 1024 + k0 + qc * 16 + j * 8) = *(uint4*)hbuf;
    }
}

__global__ void __launch_bounds__(256)
transpose_h2(const float* __restrict__ W, __half* __restrict__ Wt,
             int K, int N) {
    __shared__ float t[64][65];
    int n0 = blockIdx.x * 64, k0 = blockIdx.y * 64;
    int tid = threadIdx.x;
    int row = tid >> 2;
    int qc  = tid & 3;
    #pragma unroll
    for (int j = 0; j < 4; j++) {
        float4 v = *(const float4*)(W + (size_t)(k0 + row) * N + n0 + qc * 16 + j * 4);
        t[row][qc * 16 + j * 4 + 0] = v.x;
        t[row][qc * 16 + j * 4 + 1] = v.y;
        t[row][qc * 16 + j * 4 + 2] = v.z;
        t[row][qc * 16 + j * 4 + 3] = v.w;
    }
    __syncthreads();
    #pragma unroll
    for (int j = 0; j < 2; j++) {
        __half hbuf[8];
        #pragma unroll
        for (int e = 0; e < 8; e++)
            hbuf[e] = __float2half(t[qc * 16 + j * 8 + e][row]);
        *(uint4*)(Wt + (size_t)(n0 + row) * K + k0 + qc * 16 + j * 8) = *(uint4*)hbuf;
    }
}

__global__ void conv_half(const float* __restrict__ src, __half* __restrict__ dst, int n4) {
    int i = blockIdx.x * 256 + threadIdx.x;
    if (i < n4) {
        float4 v = ((const float4*)src)[i];
        __half2* d = (__half2*)(dst + (size_t)i * 4);
        d[0] = __floats2half2_rn(v.x, v.y);
        d[1] = __floats2half2_rn(v.z, v.w);
    }
}

// ---------------- RMS norm (vectorized) ----------------
template<bool HOUT>
__global__ void rms_kernel(const float* __restrict__ x,
                           const float* __restrict__ w, void* __restrict__ yv) {
    int row = blockIdx.x;
    int tid = threadIdx.x;
    float4 v = ((const float4*)(x + (size_t)row * DMODEL))[tid];
    float s = v.x * v.x + v.y * v.y + v.z * v.z + v.w * v.w;
    __shared__ float red[8];
    #pragma unroll
    for (int o = 16; o; o >>= 1) s += __shfl_xor_sync(0xffffffffu, s, o);
    if ((tid & 31) == 0) red[tid >> 5] = s;
    __syncthreads();
    if (tid < 8) {
        float t = red[tid];
        #pragma unroll
        for (int o = 4; o; o >>= 1) t += __shfl_xor_sync(0xffu, t, o);
        if (tid == 0) red[0] = rsqrtf(t * (1.0f / DMODEL) + 1e-6f);
    }
    __syncthreads();
    float inv = red[0];
    float4 wv = ((const float4*)w)[tid];
    float a = v.x * inv * wv.x, b = v.y * inv * wv.y;
    float c = v.z * inv * wv.z, d = v.w * inv * wv.w;
    if (HOUT) {
        __half2* yr = (__half2*)yv + (size_t)row * (DMODEL / 2);
        yr[tid * 2]     = __floats2half2_rn(a, b);
        yr[tid * 2 + 1] = __floats2half2_rn(c, d);
    } else {
        ((float4*)yv)[(size_t)row * (DMODEL / 4) + tid] = make_float4(a, b, c, d);
    }
}

// ---------------- fp16 GEMM (R7 config: 256 thr, 8 warps 2Mx4N, 64x32) ----
#define GSM_TILE 18432
#define GEMM_SMEM (4 * GSM_TILE)

template<bool RELU, bool RES, bool HOUT>
__global__ void __launch_bounds__(256, 2)
hgemm(const __half* __restrict__ A, const __half* __restrict__ B,
      const float* __restrict__ R, void* __restrict__ Cv,
      int M, int N, int K) {
    extern __shared__ char smc[];
    uint32_t S = (uint32_t)__cvta_generic_to_shared(smc);
    const int tid = threadIdx.x;
    const int warp = tid >> 5, lane = tid & 31;
    const int gid = lane >> 2, tg = lane & 3;
    const int wm = warp & 1, wn = warp >> 1;
    const int m0 = blockIdx.y * 128, n0 = blockIdx.x * 128;
    const __half* Ag = A + (size_t)m0 * K;
    const __half* Bg = B + (size_t)n0 * K;

    float acc[4][4][4];
    #pragma unroll
    for (int i = 0; i < 4; i++)
        #pragma unroll
        for (int j = 0; j < 4; j++)
            #pragma unroll
            for (int l = 0; l < 4; l++) acc[i][j][l] = 0.f;

    #define GLOAD(kt, s) do {                                                 \
        uint32_t ab = S + (s) * GSM_TILE;                                     \
        uint32_t bb = S + 2 * GSM_TILE + (s) * GSM_TILE;                      \
        _Pragma("unroll")                                                     \
        for (int i = 0; i < 4; i++) {                                         \
            int idx = tid + i * 256;                                          \
            int r = idx >> 3, c = idx & 7;                                    \
            cp16s(ab + r * 144 + c * 16, Ag + (size_t)r * K + (kt) + c * 8);  \
            cp16s(bb + r * 144 + c * 16, Bg + (size_t)r * K + (kt) + c * 8);  \
        }                                                                     \
        cp_commit();                                                          \
    } while (0)

    GLOAD(0, 0);
    cp_wait0();
    __syncthreads();

    int s = 0;
    for (int kt = 0; kt < K; kt += 64) {
        bool more = (kt + 64 < K);
        if (more) GLOAD(kt + 64, s ^ 1);
        uint32_t ab = S + s * GSM_TILE;
        uint32_t bb = S + 2 * GSM_TILE + s * GSM_TILE;
        #pragma unroll
        for (int ks = 0; ks < 4; ks++) {
            uint32_t af[4][4], bf[2][4];
            #pragma unroll
            for (int mt = 0; mt < 4; mt++)
                ldsm4(af[mt], ab + (wm * 64 + mt * 16 + (lane & 15)) * 144
                              + ks * 32 + (lane >> 4) * 16);
            #pragma unroll
            for (int g = 0; g < 2; g++)
                ldsm4(bf[g], bb + (wn * 32 + g * 16 + ((lane >> 4) << 3) + (lane & 7)) * 144
                             + ks * 32 + ((lane >> 3) & 1) * 16);
            #pragma unroll
            for (int mt = 0; mt < 4; mt++)
                #pragma unroll
                for (int nt = 0; nt < 4; nt++)
                    mma_f16(acc[mt][nt], af[mt],
                            bf[nt >> 1][(nt & 1) * 2], bf[nt >> 1][(nt & 1) * 2 + 1]);
        }
        if (more) cp_wait0();
        __syncthreads();
        s ^= 1;
    }

    #pragma unroll
    for (int mt = 0; mt < 4; mt++) {
        #pragma unroll
        for (int nt = 0; nt < 4; nt++) {
            int r0 = m0 + wm * 64 + mt * 16 + gid;
            int c  = n0 + wn * 32 + nt * 8 + tg * 2;
            float2 v0 = make_float2(acc[mt][nt][0], acc[mt][nt][1]);
            float2 v1 = make_float2(acc[mt][nt][2], acc[mt][nt][3]);
            if (RES) {
                float2 a0 = *(const float2*)(R + (size_t)r0 * N + c);
                float2 a1 = *(const float2*)(R + (size_t)(r0 + 8) * N + c);
                v0.x += a0.x; v0.y += a0.y; v1.x += a1.x; v1.y += a1.y;
            }
            if (RELU) {
                v0.x = fmaxf(v0.x, 0.f); v0.y = fmaxf(v0.y, 0.f);
                v1.x = fmaxf(v1.x, 0.f); v1.y = fmaxf(v1.y, 0.f);
            }
            if (HOUT) {
                __half* C = (__half*)Cv;
                *(__half2*)(C + (size_t)r0 * N + c)       = __floats2half2_rn(v0.x, v0.y);
                *(__half2*)(C + (size_t)(r0 + 8) * N + c) = __floats2half2_rn(v1.x, v1.y);
            } else {
                float* C = (float*)Cv;
                *(float2*)(C + (size_t)r0 * N + c) = v0;
                *(float2*)(C + (size_t)(r0 + 8) * N + c) = v1;
            }
        }
    }
    #undef GLOAD
}

// ---------------- T5 relative bucket table ----------------
__global__ void bucket_kernel() {
    int n = threadIdx.x;
    int b;
    if (n < 16) {
        b = n;
    } else {
        float nf = (float)n;
        int vl = 16 + (int)(logf(nf / 16.0f) / logf(8.0f) * 16.0f);
        b = vl < (NBUCK - 1) ? vl : (NBUCK - 1);
    }
    g_bucket[n] = b;
}

// ---------------- Fused fp16 flash attention ----------------
// Self-attention: qt mapped DESCENDING from blockIdx.x (longest tiles first,
// LPT packing for the causal-skip imbalance).
#define FQ_OFF 0
#define FK_OFF 18432
#define FV_OFF 36864
#define FP_OFF 55296
#define FMP_OFF 90112
#define FLP_OFF 92160
#define FMR_OFF 94208
#define FLR_OFF 95232
#define FL_SMEM 95744

template<bool SELF>
__global__ void __launch_bounds__(256)
flash_h(const __half* __restrict__ Qp, int qstride,
        const __half* __restrict__ Kp, int kstride,
        const __half* __restrict__ Vp, int vstride,
        const float* __restrict__ relb, const int* __restrict__ mask,
        __half* __restrict__ O) {
    extern __shared__ char smc[];
    uint32_t S = (uint32_t)__cvta_generic_to_shared(smc);
    float* mpart = (float*)(smc + FMP_OFF);
    float* lpart = (float*)(smc + FLP_OFF);
    float* mrun  = (float*)(smc + FMR_OFF);
    float* lrun  = (float*)(smc + FLR_OFF);

    int tid = threadIdx.x;
    int warp = tid >> 5, lane = tid & 31;
    int gid = lane >> 2, tg = lane & 3;
    int wm = warp & 1, wn = warp >> 1;
    int pm = warp & 3, pn = warp >> 2;
    int qt = SELF ? (gridDim.x - 1 - blockIdx.x) : blockIdx.x;
    int q0 = qt * 128;
    int bh = blockIdx.y;
    int b = bh >> 4, h = bh & 15;

    const __half* Qg = Qp + (size_t)(b * LSEQ + q0) * qstride + h * DKV;
    const __half* Kg = Kp + (size_t)(b * LSEQ) * kstride + h * DKV;
    const __half* Vg = Vp + (size_t)(b * LSEQ) * vstride + h * DKV;

    if (tid < 128) { mrun[tid] = -1e30f; lrun[tid] = 0.f; }

    #pragma unroll
    for (int i = 0; i < 4; i++) {
        int idx = tid + i * 256;
        int r = idx >> 3, c = idx & 7;
        cp16s(S + FQ_OFF + r * 144 + c * 16, Qg + (size_t)r * qstride + c * 8);
    }
    cp_commit();

    float oacc[2][4][4];
    #pragma unroll
    for (int i = 0; i < 2; i++)
        #pragma unroll
        for (int j = 0; j < 4; j++)
            #pragma unroll
            for (int l = 0; l < 4; l++) oacc[i][j][l] = 0.f;

    const int niter = SELF ? (qt + 1) : (LSEQ / 128);
    int p = 0;

    for (int it = 0; it < niter; it++) {
        int k0 = it * 128;
        #pragma unroll
        for (int i = 0; i < 4; i++) {
            int idx = tid + i * 256;
            int r = idx >> 3, c = idx & 7;
            cp16s(S + FK_OFF + r * 144 + c * 16, Kg + (size_t)(k0 + r) * kstride + c * 8);
            cp16s(S + FV_OFF + r * 144 + c * 16, Vg + (size_t)(k0 + r) * vstride + c * 8);
        }
        cp_commit();
        cp_wait0();
        __syncthreads();

        // ---- QK^T ----
        float sacc[4][4][4];
        #pragma unroll
        for (int i = 0; i < 4; i++)
            #pragma unroll
            for (int j = 0; j < 4; j++)
                #pragma unroll
                for (int l = 0; l < 4; l++) sacc[i][j][l] = 0.f;

        #pragma unroll
        for (int ks = 0; ks < 4; ks++) {
            uint32_t af[4][4], bf[2][4];
            #pragma unroll
            for (int mt = 0; mt < 4; mt++)
                ldsm4(af[mt], S + FQ_OFF + (wm * 64 + mt * 16 + (lane & 15)) * 144
                              + ks * 32 + (lane >> 4) * 16);
            #pragma unroll
            for (int g = 0; g < 2; g++)
                ldsm4(bf[g], S + FK_OFF + (wn * 32 + g * 16 + ((lane >> 4) << 3) + (lane & 7)) * 144
                             + ks * 32 + ((lane >> 3) & 1) * 16);
            #pragma unroll
            for (int mt = 0; mt < 4; mt++)
                #pragma unroll
                for (int nt = 0; nt < 4; nt++)
                    mma_f16(sacc[mt][nt], af[mt],
                            bf[nt >> 1][(nt & 1) * 2], bf[nt >> 1][(nt & 1) * 2 + 1]);
        }

        // ---- bias + mask ----
        bool cok[4][2];
        int ccol[4];
        #pragma unroll
        for (int nf = 0; nf < 4; nf++) {
            int c = k0 + wn * 32 + nf * 8 + tg * 2;
            ccol[nf] = c;
            cok[nf][0] = mask[b * LSEQ + c] > 0;
            cok[nf][1] = mask[b * LSEQ + c + 1] > 0;
        }
        #pragma unroll
        for (int mf = 0; mf < 4; mf++) {
            #pragma unroll
            for (int half = 0; half < 2; half++) {
                int qi = q0 + wm * 64 + mf * 16 + gid + half * 8;
                #pragma unroll
                for (int nf = 0; nf < 4; nf++) {
                    int c = ccol[nf];
                    if (SELF) {
                        int d0 = qi - c, d1 = d0 - 1;
                        sacc[mf][nf][half * 2]     += relb[g_bucket[d0 > 0 ? d0 : 0] * HEADS + h];
                        sacc[mf][nf][half * 2 + 1] += relb[g_bucket[d1 > 0 ? d1 : 0] * HEADS + h];
                        if (!((c     <= qi) && cok[nf][0])) sacc[mf][nf][half * 2]     += NEGINF;
                        if (!((c + 1 <= qi) && cok[nf][1])) sacc[mf][nf][half * 2 + 1] += NEGINF;
                    } else {
                        if (!cok[nf][0]) sacc[mf][nf][half * 2]     += NEGINF;
                        if (!cok[nf][1]) sacc[mf][nf][half * 2 + 1] += NEGINF;
                    }
                }
            }
        }

        // ---- partial row max ----
        #pragma unroll
        for (int mf = 0; mf < 4; mf++) {
            float mx0 = -1e30f, mx1 = -1e30f;
            #pragma unroll
            for (int nf = 0; nf < 4; nf++) {
                mx0 = fmaxf(mx0, fmaxf(sacc[mf][nf][0], sacc[mf][nf][1]));
                mx1 = fmaxf(mx1, fmaxf(sacc[mf][nf][2], sacc[mf][nf][3]));
            }
            mx0 = fmaxf(mx0, __shfl_xor_sync(0xffffffffu, mx0, 1));
            mx0 = fmaxf(mx0, __shfl_xor_sync(0xffffffffu, mx0, 2));
            mx1 = fmaxf(mx1, __shfl_xor_sync(0xffffffffu, mx1, 1));
            mx1 = fmaxf(mx1, __shfl_xor_sync(0xffffffffu, mx1, 2));
            if (tg == 0) {
                int r0 = wm * 64 + mf * 16 + gid;
                mpart[r0 * 4 + wn] = mx0;
                mpart[(r0 + 8) * 4 + wn] = mx1;
            }
        }
        __syncthreads();

        // ---- m_new, exp, P store (half), partial sums ----
        float* mold  = mrun + p * 128;
        float* mnewa = mrun + (p ^ 1) * 128;
        #pragma unroll
        for (int mf = 0; mf < 4; mf++) {
            #pragma unroll
            for (int half = 0; half < 2; half++) {
                int r = wm * 64 + mf * 16 + gid + half * 8;
                float mt = fmaxf(fmaxf(mpart[r * 4 + 0], mpart[r * 4 + 1]),
                                 fmaxf(mpart[r * 4 + 2], mpart[r * 4 + 3]));
                float mn = fmaxf(mold[r], mt);
                if (wn == 0 && tg == 0) mnewa[r] = mn;
                float sum = 0.f;
                #pragma unroll
                for (int nf = 0; nf < 4; nf++) {
                    float e0 = __expf(sacc[mf][nf][half * 2]     - mn);
                    float e1 = __expf(sacc[mf][nf][half * 2 + 1] - mn);
                    sum += e0 + e1;
                    int col = wn * 32 + nf * 8 + tg * 2;
                    *(__half2*)(smc + FP_OFF + r * 272 + col * 2) = __floats2half2_rn(e0, e1);
                }
                sum += __shfl_xor_sync(0xffffffffu, sum, 1);
                sum += __shfl_xor_sync(0xffffffffu, sum, 2);
                if (tg == 0) lpart[r * 4 + wn] = sum;
            }
        }
        __syncthreads();

        // ---- rescale O, update running sum ----
        #pragma unroll
        for (int mt2 = 0; mt2 < 2; mt2++) {
            #pragma unroll
            for (int half = 0; half < 2; half++) {
                int r = pm * 32 + mt2 * 16 + gid + half * 8;
                float rs = __expf(mold[r] - mnewa[r]);
                #pragma unroll
                for (int nf = 0; nf < 4; nf++) {
                    oacc[mt2][nf][half * 2]     *= rs;
                    oacc[mt2][nf][half * 2 + 1] *= rs;
                }
                if (pn == 0 && tg == 0)
                    lrun[r] = lrun[r] * rs + lpart[r * 4 + 0] + lpart[r * 4 + 1]
                                           + lpart[r * 4 + 2] + lpart[r * 4 + 3];
            }
        }

        // ---- P @ V ----
        #pragma unroll
        for (int ks = 0; ks < 8; ks++) {
            uint32_t af[2][4], bf[2][4];
            #pragma unroll
            for (int mt2 = 0; mt2 < 2; mt2++)
                ldsm4(af[mt2], S + FP_OFF + (pm * 32 + mt2 * 16 + (lane & 15)) * 272
                               + ks * 32 + (lane >> 4) * 16);
            #pragma unroll
            for (int g = 0; g < 2; g++)
                ldsm4t(bf[g], S + FV_OFF + (ks * 16 + ((lane >> 3) & 1) * 8 + (lane & 7)) * 144
                              + pn * 64 + g * 32 + (lane >> 4) * 16);
            #pragma unroll
            for (int mt2 = 0; mt2 < 2; mt2++)
                #pragma unroll
                for (int nt = 0; nt < 4; nt++)
                    mma_f16(oacc[mt2][nt], af[mt2],
                            bf[nt >> 1][(nt & 1) * 2], bf[nt >> 1][(nt & 1) * 2 + 1]);
        }

        __syncthreads();
        p ^= 1;
    }

    // ---- normalize, store half ----
    #pragma unroll
    for (int mt2 = 0; mt2 < 2; mt2++) {
        int rloc0 = pm * 32 + mt2 * 16 + gid;
        float inv0 = 1.0f / lrun[rloc0];
        float inv1 = 1.0f / lrun[rloc0 + 8];
        #pragma unroll
        for (int nf = 0; nf < 4; nf++) {
            int col = h * DKV + pn * 32 + nf * 8 + tg * 2;
            size_t row0 = (size_t)(b * LSEQ + q0 + rloc0);
            *(__half2*)(O + row0 * DMODEL + col)
                = __floats2half2_rn(oacc[mt2][nf][0] * inv0, oacc[mt2][nf][1] * inv0);
            *(__half2*)(O + (row0 + 8) * DMODEL + col)
                = __floats2half2_rn(oacc[mt2][nf][2] * inv1, oacc[mt2][nf][3] * inv1);
        }
    }
}

// ---------------- Orchestration -------------------------------------------
extern "C" void kernel_launch(void* const* d_in, const int* in_sizes, int n_in,
                              void* d_out, int out_size) {
    const float* enc    = (const float*)d_in[0];
    const float* hid    = (const float*)d_in[1];
    const float* ln1_w  = (const float*)d_in[2];
    const float* sa_q   = (const float*)d_in[3];
    const float* sa_k   = (const float*)d_in[4];
    const float* sa_v   = (const float*)d_in[5];
    const float* sa_o   = (const float*)d_in[6];
    const float* relb   = (const float*)d_in[7];
    const float* ln2_w  = (const float*)d_in[8];
    const float* ca_q   = (const float*)d_in[9];
    const float* ca_k   = (const float*)d_in[10];
    const float* ca_v   = (const float*)d_in[11];
    const float* ca_o   = (const float*)d_in[12];
    const float* ln3_w  = (const float*)d_in[13];
    const float* wi     = (const float*)d_in[14];
    const float* wo     = (const float*)d_in[15];
    const float* flnw   = (const float*)d_in[16];
    const int*   emask  = (const int*)d_in[17];
    const int*   dmask  = (const int*)d_in[18];
    float* out = (float*)d_out;

    __half *xn, *qkv, *kvx, *att, *encr, *ffn, *wh;
    float *h;
    cudaGetSymbolAddress((void**)&xn,   g_xnorm);
    cudaGetSymbolAddress((void**)&qkv,  g_qkv);
    cudaGetSymbolAddress((void**)&kvx,  g_kvx);
    cudaGetSymbolAddress((void**)&att,  g_att);
    cudaGetSymbolAddress((void**)&h,    g_h);
    cudaGetSymbolAddress((void**)&encr, g_encr);
    cudaGetSymbolAddress((void**)&ffn,  g_ffn);
    cudaGetSymbolAddress((void**)&wh,   g_wh);

    cudaFuncSetAttribute(hgemm<false,false,true>, cudaFuncAttributeMaxDynamicSharedMemorySize, GEMM_SMEM);
    cudaFuncSetAttribute(hgemm<false,true,false>, cudaFuncAttributeMaxDynamicSharedMemorySize, GEMM_SMEM);
    cudaFuncSetAttribute(hgemm<true,false,true>,  cudaFuncAttributeMaxDynamicSharedMemorySize, GEMM_SMEM);
    cudaFuncSetAttribute(flash_h<true>,  cudaFuncAttributeMaxDynamicSharedMemorySize, FL_SMEM);
    cudaFuncSetAttribute(flash_h<false>, cudaFuncAttributeMaxDynamicSharedMemorySize, FL_SMEM);

    dim3 tb2(256);
    dim3 gDD(8, 32);
    dim3 gQKV(24, 32);
    dim3 gKV(16, 32);
    dim3 gDF(32, 32);
    dim3 gFlash(LSEQ / 128, BATCH * HEADS);

    // ---- launch 1: all 8 DD weight transposes batched ----
    TP8 tp;
    tp.src[0] = sa_q; tp.dst_off[0] = WH_QKV;
    tp.src[1] = sa_k; tp.dst_off[1] = WH_QKV + 1048576;
    tp.src[2] = sa_v; tp.dst_off[2] = WH_QKV + 2 * 1048576;
    tp.src[3] = ca_q; tp.dst_off[3] = WH_CAQ;
    tp.src[4] = ca_k; tp.dst_off[4] = WH_KVX;
    tp.src[5] = ca_v; tp.dst_off[5] = WH_KVX + 1048576;
    tp.src[6] = sa_o; tp.dst_off[6] = WH_SAO;
    tp.src[7] = ca_o; tp.dst_off[7] = WH_CAO;
    transpose_batch<<<dim3(16, 16, 8), tb2>>>(tp, wh);                          // 1
    transpose_h2<<<dim3(64, 16), tb2>>>(wi, wh + WH_WI, DMODEL, DFF);           // 2
    transpose_h2<<<dim3(16, 64), tb2>>>(wo, wh + WH_WO, DFF, DMODEL);           // 3
    bucket_kernel<<<1, 1024>>>();                                               // 4
    rms_kernel<true><<<TOK, 256>>>(hid, ln1_w, xn);                             // 5

    // ---- launch 6: fused QKV GEMM ----
    hgemm<false,false,true><<<gQKV, 256, GEMM_SMEM>>>(xn, wh + WH_QKV, nullptr, qkv, TOK, 3072, DMODEL);

    conv_half<<<(TOK * DMODEL / 4 + 255) / 256, 256>>>(enc, encr, TOK * DMODEL / 4);

    // ---- Self-attention ----
    flash_h<true><<<gFlash, 256, FL_SMEM>>>(qkv, 3072, qkv + 1024, 3072, qkv + 2048, 3072,
                                            relb, dmask, att);
    hgemm<false,true,false><<<gDD, 256, GEMM_SMEM>>>(att, wh + WH_SAO, hid, h, TOK, DMODEL, DMODEL);

    // ---- Cross-attention ----
    rms_kernel<true><<<TOK, 256>>>(h, ln2_w, xn);
    hgemm<false,false,true><<<gDD, 256, GEMM_SMEM>>>(xn, wh + WH_CAQ, nullptr, qkv, TOK, DMODEL, DMODEL);
    hgemm<false,false,true><<<gKV, 256, GEMM_SMEM>>>(encr, wh + WH_KVX, nullptr, kvx, TOK, 2048, DMODEL);
    flash_h<false><<<gFlash, 256, FL_SMEM>>>(qkv, 1024, kvx, 2048, kvx + 1024, 2048,
                                             nullptr, emask, att);
    hgemm<false,true,false><<<gDD, 256, GEMM_SMEM>>>(att, wh + WH_CAO, h, h, TOK, DMODEL, DMODEL);

    // ---- FFN ----
    rms_kernel<true><<<TOK, 256>>>(h, ln3_w, xn);
    hgemm<true,false,true><<<gDF, 256, GEMM_SMEM>>>(xn, wh + WH_WI, nullptr, ffn, TOK, DFF, DMODEL);
    hgemm<false,true,false><<<gDD, 256, GEMM_SMEM>>>(ffn, wh + WH_WO, h, h, TOK, DMODEL, DFF);

    // ---- Final norm ----
    rms_kernel<false><<<TOK, 256>>>(h, flnw, out);
}

// round 13
// speedup vs baseline: 1.0764x; 1.0006x over previous
#include <cuda_runtime.h>
#include <cuda_fp16.h>
#include <math.h>
#include <stdint.h>

// ---------------- Problem constants ----------------
#define BATCH 4
#define LSEQ  1024
#define DMODEL 1024
#define HEADS 16
#define DKV   64
#define DFF   4096
#define TOK   (BATCH * LSEQ)
#define NBUCK 32
#define NEGINF (-1e9f)

// ---------------- Scratch ----------------
__device__ __half g_xnorm[TOK * DMODEL];
__device__ __half g_qkv[TOK * 3072];
__device__ __half g_kvx[TOK * 2048];
__device__ __half g_att[TOK * DMODEL];
__device__ float  g_h[TOK * DMODEL];
__device__ __half g_encr[TOK * DMODEL];
__device__ __half g_ffn[TOK * DFF];
__device__ __half g_wh[16 * 1024 * 1024];   // fp16 weights, transposed [N][K]
__device__ int    g_bucket[LSEQ];

#define WH_QKV 0                        // [3072][1024]
#define WH_CAQ (3 * 1048576)            // [1024][1024]
#define WH_KVX (4 * 1048576)            // [2048][1024]
#define WH_SAO (6 * 1048576)
#define WH_CAO (7 * 1048576)
#define WH_WI  (8 * 1048576)            // [4096][1024]
#define WH_WO  (12 * 1048576)           // [1024][4096]

// ---------------- helpers ----------------
__device__ __forceinline__ void mma_f16(float (&d)[4], const uint32_t (&a)[4],
                                        uint32_t b0, uint32_t b1) {
    asm volatile(
        "mma.sync.aligned.m16n8k16.row.col.f32.f16.f16.f32 "
        "{%0,%1,%2,%3}, {%4,%5,%6,%7}, {%8,%9}, {%0,%1,%2,%3};"
        : "+f"(d[0]), "+f"(d[1]), "+f"(d[2]), "+f"(d[3])
        : "r"(a[0]), "r"(a[1]), "r"(a[2]), "r"(a[3]), "r"(b0), "r"(b1));
}
__device__ __forceinline__ void ldsm4(uint32_t (&r)[4], uint32_t addr) {
    asm volatile("ldmatrix.sync.aligned.m8n8.x4.shared.b16 {%0,%1,%2,%3}, [%4];"
                 : "=r"(r[0]), "=r"(r[1]), "=r"(r[2]), "=r"(r[3]) : "r"(addr));
}
__device__ __forceinline__ void ldsm4t(uint32_t (&r)[4], uint32_t addr) {
    asm volatile("ldmatrix.sync.aligned.m8n8.x4.trans.shared.b16 {%0,%1,%2,%3}, [%4];"
                 : "=r"(r[0]), "=r"(r[1]), "=r"(r[2]), "=r"(r[3]) : "r"(addr));
}
__device__ __forceinline__ void cp16s(uint32_t dst, const void* src) {
    asm volatile("cp.async.cg.shared.global [%0], [%1], 16;" :: "r"(dst), "l"(src));
}
__device__ __forceinline__ void cp_commit() { asm volatile("cp.async.commit_group;"); }
__device__ __forceinline__ void cp_wait0()  { asm volatile("cp.async.wait_group 0;" ::: "memory"); }

// ---------------- prep: batched transpose + bucket table (z==8) -----------
struct TP8 {
    const float* src[8];
    unsigned dst_off[8];
};

__global__ void __launch_bounds__(256)
transpose_batch(TP8 args, __half* __restrict__ whbase) {
    int z = blockIdx.z;
    if (z == 8) {
        if (blockIdx.x == 0 && blockIdx.y == 0) {
            #pragma unroll
            for (int i = 0; i < 4; i++) {
                int n = threadIdx.x + i * 256;
                int b;
                if (n < 16) {
                    b = n;
                } else {
                    float nf = (float)n;
                    int vl = 16 + (int)(logf(nf / 16.0f) / logf(8.0f) * 16.0f);
                    b = vl < (NBUCK - 1) ? vl : (NBUCK - 1);
                }
                g_bucket[n] = b;
            }
        }
        return;
    }
    __shared__ float t[64][65];
    const float* W = args.src[z];
    __half* Wt = whbase + args.dst_off[z];
    int n0 = blockIdx.x * 64, k0 = blockIdx.y * 64;
    int tid = threadIdx.x;
    int row = tid >> 2;
    int qc  = tid & 3;
    #pragma unroll
    for (int j = 0; j < 4; j++) {
        float4 v = *(const float4*)(W + (size_t)(k0 + row) * 1024 + n0 + qc * 16 + j * 4);
        t[row][qc * 16 + j * 4 + 0] = v.x;
        t[row][qc * 16 + j * 4 + 1] = v.y;
        t[row][qc * 16 + j * 4 + 2] = v.z;
        t[row][qc * 16 + j * 4 + 3] = v.w;
    }
    __syncthreads();
    #pragma unroll
    for (int j = 0; j < 2; j++) {
        __half hbuf[8];
        #pragma unroll
        for (int e = 0; e < 8; e++)
            hbuf[e] = __float2half(t[qc * 16 + j * 8 + e][row]);
        *(uint4*)(Wt + (size_t)(n0 + row) * 1024 + k0 + qc * 16 + j * 8) = *(uint4*)hbuf;
    }
}

__global__ void __launch_bounds__(256)
transpose_h2(const float* __restrict__ W, __half* __restrict__ Wt,
             int K, int N) {
    __shared__ float t[64][65];
    int n0 = blockIdx.x * 64, k0 = blockIdx.y * 64;
    int tid = threadIdx.x;
    int row = tid >> 2;
    int qc  = tid & 3;
    #pragma unroll
    for (int j = 0; j < 4; j++) {
        float4 v = *(const float4*)(W + (size_t)(k0 + row) * N + n0 + qc * 16 + j * 4);
        t[row][qc * 16 + j * 4 + 0] = v.x;
        t[row][qc * 16 + j * 4 + 1] = v.y;
        t[row][qc * 16 + j * 4 + 2] = v.z;
        t[row][qc * 16 + j * 4 + 3] = v.w;
    }
    __syncthreads();
    #pragma unroll
    for (int j = 0; j < 2; j++) {
        __half hbuf[8];
        #pragma unroll
        for (int e = 0; e < 8; e++)
            hbuf[e] = __float2half(t[qc * 16 + j * 8 + e][row]);
        *(uint4*)(Wt + (size_t)(n0 + row) * K + k0 + qc * 16 + j * 8) = *(uint4*)hbuf;
    }
}

__global__ void conv_half(const float* __restrict__ src, __half* __restrict__ dst, int n4) {
    int i = blockIdx.x * 256 + threadIdx.x;
    if (i < n4) {
        float4 v = ((const float4*)src)[i];
        __half2* d = (__half2*)(dst + (size_t)i * 4);
        d[0] = __floats2half2_rn(v.x, v.y);
        d[1] = __floats2half2_rn(v.z, v.w);
    }
}

// ---------------- RMS norm (vectorized) ----------------
template<bool HOUT>
__global__ void rms_kernel(const float* __restrict__ x,
                           const float* __restrict__ w, void* __restrict__ yv) {
    int row = blockIdx.x;
    int tid = threadIdx.x;
    float4 v = ((const float4*)(x + (size_t)row * DMODEL))[tid];
    float s = v.x * v.x + v.y * v.y + v.z * v.z + v.w * v.w;
    __shared__ float red[8];
    #pragma unroll
    for (int o = 16; o; o >>= 1) s += __shfl_xor_sync(0xffffffffu, s, o);
    if ((tid & 31) == 0) red[tid >> 5] = s;
    __syncthreads();
    if (tid < 8) {
        float t = red[tid];
        #pragma unroll
        for (int o = 4; o; o >>= 1) t += __shfl_xor_sync(0xffu, t, o);
        if (tid == 0) red[0] = rsqrtf(t * (1.0f / DMODEL) + 1e-6f);
    }
    __syncthreads();
    float inv = red[0];
    float4 wv = ((const float4*)w)[tid];
    float a = v.x * inv * wv.x, b = v.y * inv * wv.y;
    float c = v.z * inv * wv.z, d = v.w * inv * wv.w;
    if (HOUT) {
        __half2* yr = (__half2*)yv + (size_t)row * (DMODEL / 2);
        yr[tid * 2]     = __floats2half2_rn(a, b);
        yr[tid * 2 + 1] = __floats2half2_rn(c, d);
    } else {
        ((float4*)yv)[(size_t)row * (DMODEL / 4) + tid] = make_float4(a, b, c, d);
    }
}

// ---------------- fp16 GEMM (R11 known-good: 2-stage, 8 warps 2Mx4N) ------
#define GSM_TILE 18432
#define GEMM_SMEM (4 * GSM_TILE)

template<bool RELU, bool RES, bool HOUT>
__global__ void __launch_bounds__(256, 2)
hgemm(const __half* __restrict__ A, const __half* __restrict__ B,
      const float* __restrict__ R, void* __restrict__ Cv,
      int M, int N, int K) {
    extern __shared__ char smc[];
    uint32_t S = (uint32_t)__cvta_generic_to_shared(smc);
    const int tid = threadIdx.x;
    const int warp = tid >> 5, lane = tid & 31;
    const int gid = lane >> 2, tg = lane & 3;
    const int wm = warp & 1, wn = warp >> 1;
    const int m0 = blockIdx.y * 128, n0 = blockIdx.x * 128;
    const __half* Ag = A + (size_t)m0 * K;
    const __half* Bg = B + (size_t)n0 * K;

    float acc[4][4][4];
    #pragma unroll
    for (int i = 0; i < 4; i++)
        #pragma unroll
        for (int j = 0; j < 4; j++)
            #pragma unroll
            for (int l = 0; l < 4; l++) acc[i][j][l] = 0.f;

    #define GLOAD(kt, s) do {                                                 \
        uint32_t ab = S + (s) * GSM_TILE;                                     \
        uint32_t bb = S + 2 * GSM_TILE + (s) * GSM_TILE;                      \
        _Pragma("unroll")                                                     \
        for (int i = 0; i < 4; i++) {                                         \
            int idx = tid + i * 256;                                          \
            int r = idx >> 3, c = idx & 7;                                    \
            cp16s(ab + r * 144 + c * 16, Ag + (size_t)r * K + (kt) + c * 8);  \
            cp16s(bb + r * 144 + c * 16, Bg + (size_t)r * K + (kt) + c * 8);  \
        }                                                                     \
        cp_commit();                                                          \
    } while (0)

    GLOAD(0, 0);
    cp_wait0();
    __syncthreads();

    int s = 0;
    for (int kt = 0; kt < K; kt += 64) {
        bool more = (kt + 64 < K);
        if (more) GLOAD(kt + 64, s ^ 1);
        uint32_t ab = S + s * GSM_TILE;
        uint32_t bb = S + 2 * GSM_TILE + s * GSM_TILE;
        #pragma unroll
        for (int ks = 0; ks < 4; ks++) {
            uint32_t af[4][4], bf[2][4];
            #pragma unroll
            for (int mt = 0; mt < 4; mt++)
                ldsm4(af[mt], ab + (wm * 64 + mt * 16 + (lane & 15)) * 144
                              + ks * 32 + (lane >> 4) * 16);
            #pragma unroll
            for (int g = 0; g < 2; g++)
                ldsm4(bf[g], bb + (wn * 32 + g * 16 + ((lane >> 4) << 3) + (lane & 7)) * 144
                             + ks * 32 + ((lane >> 3) & 1) * 16);
            #pragma unroll
            for (int mt = 0; mt < 4; mt++)
                #pragma unroll
                for (int nt = 0; nt < 4; nt++)
                    mma_f16(acc[mt][nt], af[mt],
                            bf[nt >> 1][(nt & 1) * 2], bf[nt >> 1][(nt & 1) * 2 + 1]);
        }
        if (more) cp_wait0();
        __syncthreads();
        s ^= 1;
    }

    #pragma unroll
    for (int mt = 0; mt < 4; mt++) {
        #pragma unroll
        for (int nt = 0; nt < 4; nt++) {
            int r0 = m0 + wm * 64 + mt * 16 + gid;
            int c  = n0 + wn * 32 + nt * 8 + tg * 2;
            float2 v0 = make_float2(acc[mt][nt][0], acc[mt][nt][1]);
            float2 v1 = make_float2(acc[mt][nt][2], acc[mt][nt][3]);
            if (RES) {
                float2 a0 = *(const float2*)(R + (size_t)r0 * N + c);
                float2 a1 = *(const float2*)(R + (size_t)(r0 + 8) * N + c);
                v0.x += a0.x; v0.y += a0.y; v1.x += a1.x; v1.y += a1.y;
            }
            if (RELU) {
                v0.x = fmaxf(v0.x, 0.f); v0.y = fmaxf(v0.y, 0.f);
                v1.x = fmaxf(v1.x, 0.f); v1.y = fmaxf(v1.y, 0.f);
            }
            if (HOUT) {
                __half* C = (__half*)Cv;
                *(__half2*)(C + (size_t)r0 * N + c)       = __floats2half2_rn(v0.x, v0.y);
                *(__half2*)(C + (size_t)(r0 + 8) * N + c) = __floats2half2_rn(v1.x, v1.y);
            } else {
                float* C = (float*)Cv;
                *(float2*)(C + (size_t)r0 * N + c) = v0;
                *(float2*)(C + (size_t)(r0 + 8) * N + c) = v1;
            }
        }
    }
    #undef GLOAD
}

// ---------------- Fused fp16 flash attention (LPT order for self) ---------
#define FQ_OFF 0
#define FK_OFF 18432
#define FV_OFF 36864
#define FP_OFF 55296
#define FMP_OFF 90112
#define FLP_OFF 92160
#define FMR_OFF 94208
#define FLR_OFF 95232
#define FL_SMEM 95744

template<bool SELF>
__global__ void __launch_bounds__(256)
flash_h(const __half* __restrict__ Qp, int qstride,
        const __half* __restrict__ Kp, int kstride,
        const __half* __restrict__ Vp, int vstride,
        const float* __restrict__ relb, const int* __restrict__ mask,
        __half* __restrict__ O) {
    extern __shared__ char smc[];
    uint32_t S = (uint32_t)__cvta_generic_to_shared(smc);
    float* mpart = (float*)(smc + FMP_OFF);
    float* lpart = (float*)(smc + FLP_OFF);
    float* mrun  = (float*)(smc + FMR_OFF);
    float* lrun  = (float*)(smc + FLR_OFF);

    int tid = threadIdx.x;
    int warp = tid >> 5, lane = tid & 31;
    int gid = lane >> 2, tg = lane & 3;
    int wm = warp & 1, wn = warp >> 1;
    int pm = warp & 3, pn = warp >> 2;
    int qt = SELF ? (gridDim.x - 1 - blockIdx.x) : blockIdx.x;
    int q0 = qt * 128;
    int bh = blockIdx.y;
    int b = bh >> 4, h = bh & 15;

    const __half* Qg = Qp + (size_t)(b * LSEQ + q0) * qstride + h * DKV;
    const __half* Kg = Kp + (size_t)(b * LSEQ) * kstride + h * DKV;
    const __half* Vg = Vp + (size_t)(b * LSEQ) * vstride + h * DKV;

    if (tid < 128) { mrun[tid] = -1e30f; lrun[tid] = 0.f; }

    #pragma unroll
    for (int i = 0; i < 4; i++) {
        int idx = tid + i * 256;
        int r = idx >> 3, c = idx & 7;
        cp16s(S + FQ_OFF + r * 144 + c * 16, Qg + (size_t)r * qstride + c * 8);
    }
    cp_commit();

    float oacc[2][4][4];
    #pragma unroll
    for (int i = 0; i < 2; i++)
        #pragma unroll
        for (int j = 0; j < 4; j++)
            #pragma unroll
            for (int l = 0; l < 4; l++) oacc[i][j][l] = 0.f;

    const int niter = SELF ? (qt + 1) : (LSEQ / 128);
    int p = 0;

    for (int it = 0; it < niter; it++) {
        int k0 = it * 128;
        #pragma unroll
        for (int i = 0; i < 4; i++) {
            int idx = tid + i * 256;
            int r = idx >> 3, c = idx & 7;
            cp16s(S + FK_OFF + r * 144 + c * 16, Kg + (size_t)(k0 + r) * kstride + c * 8);
            cp16s(S + FV_OFF + r * 144 + c * 16, Vg + (size_t)(k0 + r) * vstride + c * 8);
        }
        cp_commit();
        cp_wait0();
        __syncthreads();

        // ---- QK^T ----
        float sacc[4][4][4];
        #pragma unroll
        for (int i = 0; i < 4; i++)
            #pragma unroll
            for (int j = 0; j < 4; j++)
                #pragma unroll
                for (int l = 0; l < 4; l++) sacc[i][j][l] = 0.f;

        #pragma unroll
        for (int ks = 0; ks < 4; ks++) {
            uint32_t af[4][4], bf[2][4];
            #pragma unroll
            for (int mt = 0; mt < 4; mt++)
                ldsm4(af[mt], S + FQ_OFF + (wm * 64 + mt * 16 + (lane & 15)) * 144
                              + ks * 32 + (lane >> 4) * 16);
            #pragma unroll
            for (int g = 0; g < 2; g++)
                ldsm4(bf[g], S + FK_OFF + (wn * 32 + g * 16 + ((lane >> 4) << 3) + (lane & 7)) * 144
                             + ks * 32 + ((lane >> 3) & 1) * 16);
            #pragma unroll
            for (int mt = 0; mt < 4; mt++)
                #pragma unroll
                for (int nt = 0; nt < 4; nt++)
                    mma_f16(sacc[mt][nt], af[mt],
                            bf[nt >> 1][(nt & 1) * 2], bf[nt >> 1][(nt & 1) * 2 + 1]);
        }

        // ---- bias + mask ----
        bool cok[4][2];
        int ccol[4];
        #pragma unroll
        for (int nf = 0; nf < 4; nf++) {
            int c = k0 + wn * 32 + nf * 8 + tg * 2;
            ccol[nf] = c;
            cok[nf][0] = mask[b * LSEQ + c] > 0;
            cok[nf][1] = mask[b * LSEQ + c + 1] > 0;
        }
        #pragma unroll
        for (int mf = 0; mf < 4; mf++) {
            #pragma unroll
            for (int half = 0; half < 2; half++) {
                int qi = q0 + wm * 64 + mf * 16 + gid + half * 8;
                #pragma unroll
                for (int nf = 0; nf < 4; nf++) {
                    int c = ccol[nf];
                    if (SELF) {
                        int d0 = qi - c, d1 = d0 - 1;
                        sacc[mf][nf][half * 2]     += relb[g_bucket[d0 > 0 ? d0 : 0] * HEADS + h];
                        sacc[mf][nf][half * 2 + 1] += relb[g_bucket[d1 > 0 ? d1 : 0] * HEADS + h];
                        if (!((c     <= qi) && cok[nf][0])) sacc[mf][nf][half * 2]     += NEGINF;
                        if (!((c + 1 <= qi) && cok[nf][1])) sacc[mf][nf][half * 2 + 1] += NEGINF;
                    } else {
                        if (!cok[nf][0]) sacc[mf][nf][half * 2]     += NEGINF;
                        if (!cok[nf][1]) sacc[mf][nf][half * 2 + 1] += NEGINF;
                    }
                }
            }
        }

        // ---- partial row max ----
        #pragma unroll
        for (int mf = 0; mf < 4; mf++) {
            float mx0 = -1e30f, mx1 = -1e30f;
            #pragma unroll
            for (int nf = 0; nf < 4; nf++) {
                mx0 = fmaxf(mx0, fmaxf(sacc[mf][nf][0], sacc[mf][nf][1]));
                mx1 = fmaxf(mx1, fmaxf(sacc[mf][nf][2], sacc[mf][nf][3]));
            }
            mx0 = fmaxf(mx0, __shfl_xor_sync(0xffffffffu, mx0, 1));
            mx0 = fmaxf(mx0, __shfl_xor_sync(0xffffffffu, mx0, 2));
            mx1 = fmaxf(mx1, __shfl_xor_sync(0xffffffffu, mx1, 1));
            mx1 = fmaxf(mx1, __shfl_xor_sync(0xffffffffu, mx1, 2));
            if (tg == 0) {
                int r0 = wm * 64 + mf * 16 + gid;
                mpart[r0 * 4 + wn] = mx0;
                mpart[(r0 + 8) * 4 + wn] = mx1;
            }
        }
        __syncthreads();

        // ---- m_new, exp, P store (half), partial sums ----
        float* mold  = mrun + p * 128;
        float* mnewa = mrun + (p ^ 1) * 128;
        #pragma unroll
        for (int mf = 0; mf < 4; mf++) {
            #pragma unroll
            for (int half = 0; half < 2; half++) {
                int r = wm * 64 + mf * 16 + gid + half * 8;
                float mt = fmaxf(fmaxf(mpart[r * 4 + 0], mpart[r * 4 + 1]),
                                 fmaxf(mpart[r * 4 + 2], mpart[r * 4 + 3]));
                float mn = fmaxf(mold[r], mt);
                if (wn == 0 && tg == 0) mnewa[r] = mn;
                float sum = 0.f;
                #pragma unroll
                for (int nf = 0; nf < 4; nf++) {
                    float e0 = __expf(sacc[mf][nf][half * 2]     - mn);
                    float e1 = __expf(sacc[mf][nf][half * 2 + 1] - mn);
                    sum += e0 + e1;
                    int col = wn * 32 + nf * 8 + tg * 2;
                    *(__half2*)(smc + FP_OFF + r * 272 + col * 2) = __floats2half2_rn(e0, e1);
                }
                sum += __shfl_xor_sync(0xffffffffu, sum, 1);
                sum += __shfl_xor_sync(0xffffffffu, sum, 2);
                if (tg == 0) lpart[r * 4 + wn] = sum;
            }
        }
        __syncthreads();

        // ---- rescale O, update running sum ----
        #pragma unroll
        for (int mt2 = 0; mt2 < 2; mt2++) {
            #pragma unroll
            for (int half = 0; half < 2; half++) {
                int r = pm * 32 + mt2 * 16 + gid + half * 8;
                float rs = __expf(mold[r] - mnewa[r]);
                #pragma unroll
                for (int nf = 0; nf < 4; nf++) {
                    oacc[mt2][nf][half * 2]     *= rs;
                    oacc[mt2][nf][half * 2 + 1] *= rs;
                }
                if (pn == 0 && tg == 0)
                    lrun[r] = lrun[r] * rs + lpart[r * 4 + 0] + lpart[r * 4 + 1]
                                           + lpart[r * 4 + 2] + lpart[r * 4 + 3];
            }
        }

        // ---- P @ V ----
        #pragma unroll
        for (int ks = 0; ks < 8; ks++) {
            uint32_t af[2][4], bf[2][4];
            #pragma unroll
            for (int mt2 = 0; mt2 < 2; mt2++)
                ldsm4(af[mt2], S + FP_OFF + (pm * 32 + mt2 * 16 + (lane & 15)) * 272
                               + ks * 32 + (lane >> 4) * 16);
            #pragma unroll
            for (int g = 0; g < 2; g++)
                ldsm4t(bf[g], S + FV_OFF + (ks * 16 + ((lane >> 3) & 1) * 8 + (lane & 7)) * 144
                              + pn * 64 + g * 32 + (lane >> 4) * 16);
            #pragma unroll
            for (int mt2 = 0; mt2 < 2; mt2++)
                #pragma unroll
                for (int nt = 0; nt < 4; nt++)
                    mma_f16(oacc[mt2][nt], af[mt2],
                            bf[nt >> 1][(nt & 1) * 2], bf[nt >> 1][(nt & 1) * 2 + 1]);
        }

        __syncthreads();
        p ^= 1;
    }

    // ---- normalize, store half ----
    #pragma unroll
    for (int mt2 = 0; mt2 < 2; mt2++) {
        int rloc0 = pm * 32 + mt2 * 16 + gid;
        float inv0 = 1.0f / lrun[rloc0];
        float inv1 = 1.0f / lrun[rloc0 + 8];
        #pragma unroll
        for (int nf = 0; nf < 4; nf++) {
            int col = h * DKV + pn * 32 + nf * 8 + tg * 2;
            size_t row0 = (size_t)(b * LSEQ + q0 + rloc0);
            *(__half2*)(O + row0 * DMODEL + col)
                = __floats2half2_rn(oacc[mt2][nf][0] * inv0, oacc[mt2][nf][1] * inv0);
            *(__half2*)(O + (row0 + 8) * DMODEL + col)
                = __floats2half2_rn(oacc[mt2][nf][2] * inv1, oacc[mt2][nf][3] * inv1);
        }
    }
}

// ---------------- Orchestration -------------------------------------------
extern "C" void kernel_launch(void* const* d_in, const int* in_sizes, int n_in,
                              void* d_out, int out_size) {
    const float* enc    = (const float*)d_in[0];
    const float* hid    = (const float*)d_in[1];
    const float* ln1_w  = (const float*)d_in[2];
    const float* sa_q   = (const float*)d_in[3];
    const float* sa_k   = (const float*)d_in[4];
    const float* sa_v   = (const float*)d_in[5];
    const float* sa_o   = (const float*)d_in[6];
    const float* relb   = (const float*)d_in[7];
    const float* ln2_w  = (const float*)d_in[8];
    const float* ca_q   = (const float*)d_in[9];
    const float* ca_k   = (const float*)d_in[10];
    const float* ca_v   = (const float*)d_in[11];
    const float* ca_o   = (const float*)d_in[12];
    const float* ln3_w  = (const float*)d_in[13];
    const float* wi     = (const float*)d_in[14];
    const float* wo     = (const float*)d_in[15];
    const float* flnw   = (const float*)d_in[16];
    const int*   emask  = (const int*)d_in[17];
    const int*   dmask  = (const int*)d_in[18];
    float* out = (float*)d_out;

    __half *xn, *qkv, *kvx, *att, *encr, *ffn, *wh;
    float *h;
    cudaGetSymbolAddress((void**)&xn,   g_xnorm);
    cudaGetSymbolAddress((void**)&qkv,  g_qkv);
    cudaGetSymbolAddress((void**)&kvx,  g_kvx);
    cudaGetSymbolAddress((void**)&att,  g_att);
    cudaGetSymbolAddress((void**)&h,    g_h);
    cudaGetSymbolAddress((void**)&encr, g_encr);
    cudaGetSymbolAddress((void**)&ffn,  g_ffn);
    cudaGetSymbolAddress((void**)&wh,   g_wh);

    cudaFuncSetAttribute(hgemm<false,false,true>, cudaFuncAttributeMaxDynamicSharedMemorySize, GEMM_SMEM);
    cudaFuncSetAttribute(hgemm<false,true,false>, cudaFuncAttributeMaxDynamicSharedMemorySize, GEMM_SMEM);
    cudaFuncSetAttribute(hgemm<true,false,true>,  cudaFuncAttributeMaxDynamicSharedMemorySize, GEMM_SMEM);
    cudaFuncSetAttribute(flash_h<true>,  cudaFuncAttributeMaxDynamicSharedMemorySize, FL_SMEM);
    cudaFuncSetAttribute(flash_h<false>, cudaFuncAttributeMaxDynamicSharedMemorySize, FL_SMEM);

    dim3 tb2(256);
    dim3 gDD(8, 32);
    dim3 gQKV(24, 32);
    dim3 gKV(16, 32);
    dim3 gDF(32, 32);
    dim3 gFlash(LSEQ / 128, BATCH * HEADS);

    // ---- launch 1: 8 DD transposes + bucket table, batched ----
    TP8 tp;
    tp.src[0] = sa_q; tp.dst_off[0] = WH_QKV;
    tp.src[1] = sa_k; tp.dst_off[1] = WH_QKV + 1048576;
    tp.src[2] = sa_v; tp.dst_off[2] = WH_QKV + 2 * 1048576;
    tp.src[3] = ca_q; tp.dst_off[3] = WH_CAQ;
    tp.src[4] = ca_k; tp.dst_off[4] = WH_KVX;
    tp.src[5] = ca_v; tp.dst_off[5] = WH_KVX + 1048576;
    tp.src[6] = sa_o; tp.dst_off[6] = WH_SAO;
    tp.src[7] = ca_o; tp.dst_off[7] = WH_CAO;
    transpose_batch<<<dim3(16, 16, 9), tb2>>>(tp, wh);                          // 1
    transpose_h2<<<dim3(64, 16), tb2>>>(wi, wh + WH_WI, DMODEL, DFF);           // 2
    transpose_h2<<<dim3(16, 64), tb2>>>(wo, wh + WH_WO, DFF, DMODEL);           // 3
    conv_half<<<(TOK * DMODEL / 4 + 255) / 256, 256>>>(enc, encr, TOK * DMODEL / 4);  // 4
    rms_kernel<true><<<TOK, 256>>>(hid, ln1_w, xn);                             // 5

    // ---- launch 6: fused QKV GEMM ----
    hgemm<false,false,true><<<gQKV, 256, GEMM_SMEM>>>(xn, wh + WH_QKV, nullptr, qkv, TOK, 3072, DMODEL);

    // ---- Self-attention ----
    flash_h<true><<<gFlash, 256, FL_SMEM>>>(qkv, 3072, qkv + 1024, 3072, qkv + 2048, 3072,
                                            relb, dmask, att);
    hgemm<false,true,false><<<gDD, 256, GEMM_SMEM>>>(att, wh + WH_SAO, hid, h, TOK, DMODEL, DMODEL);

    // ---- Cross-attention ----
    rms_kernel<true><<<TOK, 256>>>(h, ln2_w, xn);
    hgemm<false,false,true><<<gDD, 256, GEMM_SMEM>>>(xn, wh + WH_CAQ, nullptr, qkv, TOK, DMODEL, DMODEL);
    hgemm<false,false,true><<<gKV, 256, GEMM_SMEM>>>(encr, wh + WH_KVX, nullptr, kvx, TOK, 2048, DMODEL);
    flash_h<false><<<gFlash, 256, FL_SMEM>>>(qkv, 1024, kvx, 2048, kvx + 1024, 2048,
                                             nullptr, emask, att);
    hgemm<false,true,false><<<gDD, 256, GEMM_SMEM>>>(att, wh + WH_CAO, h, h, TOK, DMODEL, DMODEL);

    // ---- FFN ----
    rms_kernel<true><<<TOK, 256>>>(h, ln3_w, xn);
    hgemm<true,false,true><<<gDF, 256, GEMM_SMEM>>>(xn, wh + WH_WI, nullptr, ffn, TOK, DFF, DMODEL);
    hgemm<false,true,false><<<gDD, 256, GEMM_SMEM>>>(ffn, wh + WH_WO, h, h, TOK, DMODEL, DFF);

    // ---- Final norm ----
    rms_kernel<false><<<TOK, 256>>>(h, flnw, out);
}

// round 14
// speedup vs baseline: 1.1517x; 1.0699x over previous
#include <cuda_runtime.h>
#include <cuda_fp16.h>
#include <math.h>
#include <stdint.h>

// ---------------- Problem constants ----------------
#define BATCH 4
#define LSEQ  1024
#define DMODEL 1024
#define HEADS 16
#define DKV   64
#define DFF   4096
#define TOK   (BATCH * LSEQ)
#define NBUCK 32
#define NEGINF (-1e9f)

// ---------------- Scratch ----------------
__device__ __half g_xnorm[TOK * DMODEL];
__device__ __half g_qkv[TOK * 3072];
__device__ __half g_kvx[TOK * 2048];
__device__ __half g_att[TOK * DMODEL];
__device__ float  g_h[TOK * DMODEL];
__device__ __half g_encr[TOK * DMODEL];
__device__ __half g_ffn[TOK * DFF];
__device__ __half g_wh[16 * 1024 * 1024];   // fp16 weights, transposed [N][K]
__device__ int    g_bucket[LSEQ];

#define WH_QKV 0                        // [3072][1024]
#define WH_CAQ (3 * 1048576)            // [1024][1024]
#define WH_KVX (4 * 1048576)            // [2048][1024]
#define WH_SAO (6 * 1048576)
#define WH_CAO (7 * 1048576)
#define WH_WI  (8 * 1048576)            // [4096][1024]
#define WH_WO  (12 * 1048576)           // [1024][4096]

// ---------------- helpers ----------------
__device__ __forceinline__ void mma_f16(float (&d)[4], const uint32_t (&a)[4],
                                        uint32_t b0, uint32_t b1) {
    asm volatile(
        "mma.sync.aligned.m16n8k16.row.col.f32.f16.f16.f32 "
        "{%0,%1,%2,%3}, {%4,%5,%6,%7}, {%8,%9}, {%0,%1,%2,%3};"
        : "+f"(d[0]), "+f"(d[1]), "+f"(d[2]), "+f"(d[3])
        : "r"(a[0]), "r"(a[1]), "r"(a[2]), "r"(a[3]), "r"(b0), "r"(b1));
}
__device__ __forceinline__ void ldsm4(uint32_t (&r)[4], uint32_t addr) {
    asm volatile("ldmatrix.sync.aligned.m8n8.x4.shared.b16 {%0,%1,%2,%3}, [%4];"
                 : "=r"(r[0]), "=r"(r[1]), "=r"(r[2]), "=r"(r[3]) : "r"(addr));
}
__device__ __forceinline__ void ldsm4t(uint32_t (&r)[4], uint32_t addr) {
    asm volatile("ldmatrix.sync.aligned.m8n8.x4.trans.shared.b16 {%0,%1,%2,%3}, [%4];"
                 : "=r"(r[0]), "=r"(r[1]), "=r"(r[2]), "=r"(r[3]) : "r"(addr));
}
__device__ __forceinline__ void cp16s(uint32_t dst, const void* src) {
    asm volatile("cp.async.cg.shared.global [%0], [%1], 16;" :: "r"(dst), "l"(src));
}
__device__ __forceinline__ void cp_commit() { asm volatile("cp.async.commit_group;"); }
__device__ __forceinline__ void cp_wait0()  { asm volatile("cp.async.wait_group 0;" ::: "memory"); }
__device__ __forceinline__ uint32_t packh2(float a, float b) {
    __half2 t = __floats2half2_rn(a, b);
    return *(uint32_t*)&t;
}

// ---------------- prep: batched transpose + bucket table (z==8) -----------
struct TP8 {
    const float* src[8];
    unsigned dst_off[8];
};

__global__ void __launch_bounds__(256)
transpose_batch(TP8 args, __half* __restrict__ whbase) {
    int z = blockIdx.z;
    if (z == 8) {
        if (blockIdx.x == 0 && blockIdx.y == 0) {
            #pragma unroll
            for (int i = 0; i < 4; i++) {
                int n = threadIdx.x + i * 256;
                int b;
                if (n < 16) {
                    b = n;
                } else {
                    float nf = (float)n;
                    int vl = 16 + (int)(logf(nf / 16.0f) / logf(8.0f) * 16.0f);
                    b = vl < (NBUCK - 1) ? vl : (NBUCK - 1);
                }
                g_bucket[n] = b;
            }
        }
        return;
    }
    __shared__ float t[64][65];
    const float* W = args.src[z];
    __half* Wt = whbase + args.dst_off[z];
    int n0 = blockIdx.x * 64, k0 = blockIdx.y * 64;
    int tid = threadIdx.x;
    int row = tid >> 2;
    int qc  = tid & 3;
    #pragma unroll
    for (int j = 0; j < 4; j++) {
        float4 v = *(const float4*)(W + (size_t)(k0 + row) * 1024 + n0 + qc * 16 + j * 4);
        t[row][qc * 16 + j * 4 + 0] = v.x;
        t[row][qc * 16 + j * 4 + 1] = v.y;
        t[row][qc * 16 + j * 4 + 2] = v.z;
        t[row][qc * 16 + j * 4 + 3] = v.w;
    }
    __syncthreads();
    #pragma unroll
    for (int j = 0; j < 2; j++) {
        __half hbuf[8];
        #pragma unroll
        for (int e = 0; e < 8; e++)
            hbuf[e] = __float2half(t[qc * 16 + j * 8 + e][row]);
        *(uint4*)(Wt + (size_t)(n0 + row) * 1024 + k0 + qc * 16 + j * 8) = *(uint4*)hbuf;
    }
}

__global__ void __launch_bounds__(256)
transpose_h2(const float* __restrict__ W, __half* __restrict__ Wt,
             int K, int N) {
    __shared__ float t[64][65];
    int n0 = blockIdx.x * 64, k0 = blockIdx.y * 64;
    int tid = threadIdx.x;
    int row = tid >> 2;
    int qc  = tid & 3;
    #pragma unroll
    for (int j = 0; j < 4; j++) {
        float4 v = *(const float4*)(W + (size_t)(k0 + row) * N + n0 + qc * 16 + j * 4);
        t[row][qc * 16 + j * 4 + 0] = v.x;
        t[row][qc * 16 + j * 4 + 1] = v.y;
        t[row][qc * 16 + j * 4 + 2] = v.z;
        t[row][qc * 16 + j * 4 + 3] = v.w;
    }
    __syncthreads();
    #pragma unroll
    for (int j = 0; j < 2; j++) {
        __half hbuf[8];
        #pragma unroll
        for (int e = 0; e < 8; e++)
            hbuf[e] = __float2half(t[qc * 16 + j * 8 + e][row]);
        *(uint4*)(Wt + (size_t)(n0 + row) * K + k0 + qc * 16 + j * 8) = *(uint4*)hbuf;
    }
}

__global__ void conv_half(const float* __restrict__ src, __half* __restrict__ dst, int n4) {
    int i = blockIdx.x * 256 + threadIdx.x;
    if (i < n4) {
        float4 v = ((const float4*)src)[i];
        __half2* d = (__half2*)(dst + (size_t)i * 4);
        d[0] = __floats2half2_rn(v.x, v.y);
        d[1] = __floats2half2_rn(v.z, v.w);
    }
}

// ---------------- RMS norm (vectorized) ----------------
template<bool HOUT>
__global__ void rms_kernel(const float* __restrict__ x,
                           const float* __restrict__ w, void* __restrict__ yv) {
    int row = blockIdx.x;
    int tid = threadIdx.x;
    float4 v = ((const float4*)(x + (size_t)row * DMODEL))[tid];
    float s = v.x * v.x + v.y * v.y + v.z * v.z + v.w * v.w;
    __shared__ float red[8];
    #pragma unroll
    for (int o = 16; o; o >>= 1) s += __shfl_xor_sync(0xffffffffu, s, o);
    if ((tid & 31) == 0) red[tid >> 5] = s;
    __syncthreads();
    if (tid < 8) {
        float t = red[tid];
        #pragma unroll
        for (int o = 4; o; o >>= 1) t += __shfl_xor_sync(0xffu, t, o);
        if (tid == 0) red[0] = rsqrtf(t * (1.0f / DMODEL) + 1e-6f);
    }
    __syncthreads();
    float inv = red[0];
    float4 wv = ((const float4*)w)[tid];
    float a = v.x * inv * wv.x, b = v.y * inv * wv.y;
    float c = v.z * inv * wv.z, d = v.w * inv * wv.w;
    if (HOUT) {
        __half2* yr = (__half2*)yv + (size_t)row * (DMODEL / 2);
        yr[tid * 2]     = __floats2half2_rn(a, b);
        yr[tid * 2 + 1] = __floats2half2_rn(c, d);
    } else {
        ((float4*)yv)[(size_t)row * (DMODEL / 4) + tid] = make_float4(a, b, c, d);
    }
}

// ---------------- fp16 GEMM (known-good: 2-stage, 8 warps 2Mx4N) ----------
#define GSM_TILE 18432
#define GEMM_SMEM (4 * GSM_TILE)

template<bool RELU, bool RES, bool HOUT>
__global__ void __launch_bounds__(256, 2)
hgemm(const __half* __restrict__ A, const __half* __restrict__ B,
      const float* __restrict__ R, void* __restrict__ Cv,
      int M, int N, int K) {
    extern __shared__ char smc[];
    uint32_t S = (uint32_t)__cvta_generic_to_shared(smc);
    const int tid = threadIdx.x;
    const int warp = tid >> 5, lane = tid & 31;
    const int gid = lane >> 2, tg = lane & 3;
    const int wm = warp & 1, wn = warp >> 1;
    const int m0 = blockIdx.y * 128, n0 = blockIdx.x * 128;
    const __half* Ag = A + (size_t)m0 * K;
    const __half* Bg = B + (size_t)n0 * K;

    float acc[4][4][4];
    #pragma unroll
    for (int i = 0; i < 4; i++)
        #pragma unroll
        for (int j = 0; j < 4; j++)
            #pragma unroll
            for (int l = 0; l < 4; l++) acc[i][j][l] = 0.f;

    #define GLOAD(kt, s) do {                                                 \
        uint32_t ab = S + (s) * GSM_TILE;                                     \
        uint32_t bb = S + 2 * GSM_TILE + (s) * GSM_TILE;                      \
        _Pragma("unroll")                                                     \
        for (int i = 0; i < 4; i++) {                                         \
            int idx = tid + i * 256;                                          \
            int r = idx >> 3, c = idx & 7;                                    \
            cp16s(ab + r * 144 + c * 16, Ag + (size_t)r * K + (kt) + c * 8);  \
            cp16s(bb + r * 144 + c * 16, Bg + (size_t)r * K + (kt) + c * 8);  \
        }                                                                     \
        cp_commit();                                                          \
    } while (0)

    GLOAD(0, 0);
    cp_wait0();
    __syncthreads();

    int s = 0;
    for (int kt = 0; kt < K; kt += 64) {
        bool more = (kt + 64 < K);
        if (more) GLOAD(kt + 64, s ^ 1);
        uint32_t ab = S + s * GSM_TILE;
        uint32_t bb = S + 2 * GSM_TILE + s * GSM_TILE;
        #pragma unroll
        for (int ks = 0; ks < 4; ks++) {
            uint32_t af[4][4], bf[2][4];
            #pragma unroll
            for (int mt = 0; mt < 4; mt++)
                ldsm4(af[mt], ab + (wm * 64 + mt * 16 + (lane & 15)) * 144
                              + ks * 32 + (lane >> 4) * 16);
            #pragma unroll
            for (int g = 0; g < 2; g++)
                ldsm4(bf[g], bb + (wn * 32 + g * 16 + ((lane >> 4) << 3) + (lane & 7)) * 144
                             + ks * 32 + ((lane >> 3) & 1) * 16);
            #pragma unroll
            for (int mt = 0; mt < 4; mt++)
                #pragma unroll
                for (int nt = 0; nt < 4; nt++)
                    mma_f16(acc[mt][nt], af[mt],
                            bf[nt >> 1][(nt & 1) * 2], bf[nt >> 1][(nt & 1) * 2 + 1]);
        }
        if (more) cp_wait0();
        __syncthreads();
        s ^= 1;
    }

    #pragma unroll
    for (int mt = 0; mt < 4; mt++) {
        #pragma unroll
        for (int nt = 0; nt < 4; nt++) {
            int r0 = m0 + wm * 64 + mt * 16 + gid;
            int c  = n0 + wn * 32 + nt * 8 + tg * 2;
            float2 v0 = make_float2(acc[mt][nt][0], acc[mt][nt][1]);
            float2 v1 = make_float2(acc[mt][nt][2], acc[mt][nt][3]);
            if (RES) {
                float2 a0 = *(const float2*)(R + (size_t)r0 * N + c);
                float2 a1 = *(const float2*)(R + (size_t)(r0 + 8) * N + c);
                v0.x += a0.x; v0.y += a0.y; v1.x += a1.x; v1.y += a1.y;
            }
            if (RELU) {
                v0.x = fmaxf(v0.x, 0.f); v0.y = fmaxf(v0.y, 0.f);
                v1.x = fmaxf(v1.x, 0.f); v1.y = fmaxf(v1.y, 0.f);
            }
            if (HOUT) {
                __half* C = (__half*)Cv;
                *(__half2*)(C + (size_t)r0 * N + c)       = __floats2half2_rn(v0.x, v0.y);
                *(__half2*)(C + (size_t)(r0 + 8) * N + c) = __floats2half2_rn(v1.x, v1.y);
            } else {
                float* C = (float*)Cv;
                *(float2*)(C + (size_t)r0 * N + c) = v0;
                *(float2*)(C + (size_t)(r0 + 8) * N + c) = v1;
            }
        }
    }
    #undef GLOAD
}

// ---------------- FA2 flash: register P, warp-local softmax ---------------
// Per CTA: 128 q rows, 8 warps; warp w owns rows [w*16, w*16+16), full key
// tile (128). smem: Q (once) + double-buffered K/V. P stays in registers via
// the m16n8 C-frag == m16k16 A-frag identity. 2 barriers/iter.
#define F2_Q   0
#define F2_KV0 18432
#define F2_STG 36864
#define FL_SMEM (18432 + 2 * 36864)

template<bool SELF>
__global__ void __launch_bounds__(256)
flash_h(const __half* __restrict__ Qp, int qstride,
        const __half* __restrict__ Kp, int kstride,
        const __half* __restrict__ Vp, int vstride,
        const float* __restrict__ relb, const int* __restrict__ mask,
        __half* __restrict__ O) {
    extern __shared__ char smc[];
    uint32_t S = (uint32_t)__cvta_generic_to_shared(smc);
    int tid = threadIdx.x;
    int warp = tid >> 5, lane = tid & 31;
    int gid = lane >> 2, tg = lane & 3;
    int qt = SELF ? (gridDim.x - 1 - blockIdx.x) : blockIdx.x;
    int q0 = qt * 128;
    int bh = blockIdx.y;
    int b = bh >> 4, h = bh & 15;

    const __half* Qg = Qp + (size_t)(b * LSEQ + q0) * qstride + h * DKV;
    const __half* Kg = Kp + (size_t)(b * LSEQ) * kstride + h * DKV;
    const __half* Vg = Vp + (size_t)(b * LSEQ) * vstride + h * DKV;
    const int* maskb = mask + b * LSEQ;

    #define KVLOAD(it, st) do {                                               \
        uint32_t kb = S + F2_KV0 + (st) * F2_STG;                             \
        uint32_t vb = kb + 18432;                                             \
        int kk0 = (it) * 128;                                                 \
        _Pragma("unroll")                                                     \
        for (int i = 0; i < 4; i++) {                                         \
            int idx = tid + i * 256;                                          \
            int r = idx >> 3, c = idx & 7;                                    \
            cp16s(kb + r * 144 + c * 16, Kg + (size_t)(kk0 + r) * kstride + c * 8); \
            cp16s(vb + r * 144 + c * 16, Vg + (size_t)(kk0 + r) * vstride + c * 8); \
        }                                                                     \
        cp_commit();                                                          \
    } while (0)

    // Q tile (once) + first K/V tile
    #pragma unroll
    for (int i = 0; i < 4; i++) {
        int idx = tid + i * 256;
        int r = idx >> 3, c = idx & 7;
        cp16s(S + F2_Q + r * 144 + c * 16, Qg + (size_t)r * qstride + c * 8);
    }
    KVLOAD(0, 0);

    float oacc[8][4];
    #pragma unroll
    for (int i = 0; i < 8; i++)
        #pragma unroll
        for (int l = 0; l < 4; l++) oacc[i][l] = 0.f;
    float m0 = -1e30f, m1 = -1e30f, l0 = 0.f, l1 = 0.f;

    const int niter = SELF ? (qt + 1) : (LSEQ / 128);
    const int qi0 = q0 + warp * 16 + gid;
    const int qi1 = qi0 + 8;

    cp_wait0();
    __syncthreads();

    int s = 0;
    for (int it = 0; it < niter; it++) {
        int k0 = it * 128;
        bool more = (it + 1 < niter);
        if (more) KVLOAD(it + 1, s ^ 1);
        uint32_t Kb = S + F2_KV0 + s * F2_STG;
        uint32_t Vb = Kb + 18432;

        // ---- QK^T: m16 x n128 x k64 per warp ----
        float sacc[16][4];
        #pragma unroll
        for (int j = 0; j < 16; j++)
            #pragma unroll
            for (int l = 0; l < 4; l++) sacc[j][l] = 0.f;

        #pragma unroll
        for (int ks = 0; ks < 4; ks++) {
            uint32_t af[4];
            ldsm4(af, S + F2_Q + (warp * 16 + (lane & 15)) * 144
                      + ks * 32 + (lane >> 4) * 16);
            #pragma unroll
            for (int g = 0; g < 8; g++) {
                uint32_t bf[4];
                ldsm4(bf, Kb + (g * 16 + ((lane >> 4) << 3) + (lane & 7)) * 144
                          + ks * 32 + ((lane >> 3) & 1) * 16);
                mma_f16(sacc[2 * g],     af, bf[0], bf[1]);
                mma_f16(sacc[2 * g + 1], af, bf[2], bf[3]);
            }
        }

        // ---- bias + mask ----
        #pragma unroll
        for (int j = 0; j < 16; j++) {
            int c = k0 + j * 8 + tg * 2;
            bool mk0 = maskb[c] > 0;
            bool mk1 = maskb[c + 1] > 0;
            if (SELF) {
                int d00 = qi0 - c, d01 = d00 - 1;
                int d10 = qi1 - c, d11 = d10 - 1;
                sacc[j][0] += relb[g_bucket[d00 > 0 ? d00 : 0] * HEADS + h];
                sacc[j][1] += relb[g_bucket[d01 > 0 ? d01 : 0] * HEADS + h];
                sacc[j][2] += relb[g_bucket[d10 > 0 ? d10 : 0] * HEADS + h];
                sacc[j][3] += relb[g_bucket[d11 > 0 ? d11 : 0] * HEADS + h];
                if (!((c     <= qi0) && mk0)) sacc[j][0] += NEGINF;
                if (!((c + 1 <= qi0) && mk1)) sacc[j][1] += NEGINF;
                if (!((c     <= qi1) && mk0)) sacc[j][2] += NEGINF;
                if (!((c + 1 <= qi1) && mk1)) sacc[j][3] += NEGINF;
            } else {
                if (!mk0) { sacc[j][0] += NEGINF; sacc[j][2] += NEGINF; }
                if (!mk1) { sacc[j][1] += NEGINF; sacc[j][3] += NEGINF; }
            }
        }

        // ---- warp-local online softmax (rows live in one 4-lane quad) ----
        float mt0 = -1e30f, mt1 = -1e30f;
        #pragma unroll
        for (int j = 0; j < 16; j++) {
            mt0 = fmaxf(mt0, fmaxf(sacc[j][0], sacc[j][1]));
            mt1 = fmaxf(mt1, fmaxf(sacc[j][2], sacc[j][3]));
        }
        mt0 = fmaxf(mt0, __shfl_xor_sync(0xffffffffu, mt0, 1));
        mt0 = fmaxf(mt0, __shfl_xor_sync(0xffffffffu, mt0, 2));
        mt1 = fmaxf(mt1, __shfl_xor_sync(0xffffffffu, mt1, 1));
        mt1 = fmaxf(mt1, __shfl_xor_sync(0xffffffffu, mt1, 2));
        float mn0 = fmaxf(m0, mt0), mn1 = fmaxf(m1, mt1);
        float rs0 = __expf(m0 - mn0), rs1 = __expf(m1 - mn1);
        float s0 = 0.f, s1 = 0.f;
        #pragma unroll
        for (int j = 0; j < 16; j++) {
            float e0 = __expf(sacc[j][0] - mn0);
            float e1 = __expf(sacc[j][1] - mn0);
            float e2 = __expf(sacc[j][2] - mn1);
            float e3 = __expf(sacc[j][3] - mn1);
            sacc[j][0] = e0; sacc[j][1] = e1; sacc[j][2] = e2; sacc[j][3] = e3;
            s0 += e0 + e1;
            s1 += e2 + e3;
        }
        s0 += __shfl_xor_sync(0xffffffffu, s0, 1);
        s0 += __shfl_xor_sync(0xffffffffu, s0, 2);
        s1 += __shfl_xor_sync(0xffffffffu, s1, 1);
        s1 += __shfl_xor_sync(0xffffffffu, s1, 2);
        l0 = l0 * rs0 + s0;
        l1 = l1 * rs1 + s1;
        m0 = mn0; m1 = mn1;
        #pragma unroll
        for (int nt = 0; nt < 8; nt++) {
            oacc[nt][0] *= rs0; oacc[nt][1] *= rs0;
            oacc[nt][2] *= rs1; oacc[nt][3] *= rs1;
        }

        // ---- pack P: C-frag -> A-frag identity ----
        uint32_t ph[8][4];
        #pragma unroll
        for (int t = 0; t < 8; t++) {
            ph[t][0] = packh2(sacc[2 * t][0],     sacc[2 * t][1]);
            ph[t][1] = packh2(sacc[2 * t][2],     sacc[2 * t][3]);
            ph[t][2] = packh2(sacc[2 * t + 1][0], sacc[2 * t + 1][1]);
            ph[t][3] = packh2(sacc[2 * t + 1][2], sacc[2 * t + 1][3]);
        }

        // ---- P @ V: m16 x n64 x k128 per warp ----
        #pragma unroll
        for (int t = 0; t < 8; t++) {
            #pragma unroll
            for (int g = 0; g < 4; g++) {
                uint32_t bf[4];
                ldsm4t(bf, Vb + (t * 16 + ((lane >> 3) & 1) * 8 + (lane & 7)) * 144
                           + g * 32 + (lane >> 4) * 16);
                mma_f16(oacc[2 * g],     ph[t], bf[0], bf[1]);
                mma_f16(oacc[2 * g + 1], ph[t], bf[2], bf[3]);
            }
        }

        if (more) cp_wait0();
        __syncthreads();
        s ^= 1;
    }

    // ---- normalize and store ----
    float inv0 = 1.0f / l0;
    float inv1 = 1.0f / l1;
    size_t row0 = (size_t)(b * LSEQ + qi0);
    size_t row1 = (size_t)(b * LSEQ + qi1);
    #pragma unroll
    for (int nt = 0; nt < 8; nt++) {
        int col = h * DKV + nt * 8 + tg * 2;
        *(__half2*)(O + row0 * DMODEL + col)
            = __floats2half2_rn(oacc[nt][0] * inv0, oacc[nt][1] * inv0);
        *(__half2*)(O + row1 * DMODEL + col)
            = __floats2half2_rn(oacc[nt][2] * inv1, oacc[nt][3] * inv1);
    }
    #undef KVLOAD
}

// ---------------- Orchestration -------------------------------------------
extern "C" void kernel_launch(void* const* d_in, const int* in_sizes, int n_in,
                              void* d_out, int out_size) {
    const float* enc    = (const float*)d_in[0];
    const float* hid    = (const float*)d_in[1];
    const float* ln1_w  = (const float*)d_in[2];
    const float* sa_q   = (const float*)d_in[3];
    const float* sa_k   = (const float*)d_in[4];
    const float* sa_v   = (const float*)d_in[5];
    const float* sa_o   = (const float*)d_in[6];
    const float* relb   = (const float*)d_in[7];
    const float* ln2_w  = (const float*)d_in[8];
    const float* ca_q   = (const float*)d_in[9];
    const float* ca_k   = (const float*)d_in[10];
    const float* ca_v   = (const float*)d_in[11];
    const float* ca_o   = (const float*)d_in[12];
    const float* ln3_w  = (const float*)d_in[13];
    const float* wi     = (const float*)d_in[14];
    const float* wo     = (const float*)d_in[15];
    const float* flnw   = (const float*)d_in[16];
    const int*   emask  = (const int*)d_in[17];
    const int*   dmask  = (const int*)d_in[18];
    float* out = (float*)d_out;

    __half *xn, *qkv, *kvx, *att, *encr, *ffn, *wh;
    float *h;
    cudaGetSymbolAddress((void**)&xn,   g_xnorm);
    cudaGetSymbolAddress((void**)&qkv,  g_qkv);
    cudaGetSymbolAddress((void**)&kvx,  g_kvx);
    cudaGetSymbolAddress((void**)&att,  g_att);
    cudaGetSymbolAddress((void**)&h,    g_h);
    cudaGetSymbolAddress((void**)&encr, g_encr);
    cudaGetSymbolAddress((void**)&ffn,  g_ffn);
    cudaGetSymbolAddress((void**)&wh,   g_wh);

    cudaFuncSetAttribute(hgemm<false,false,true>, cudaFuncAttributeMaxDynamicSharedMemorySize, GEMM_SMEM);
    cudaFuncSetAttribute(hgemm<false,true,false>, cudaFuncAttributeMaxDynamicSharedMemorySize, GEMM_SMEM);
    cudaFuncSetAttribute(hgemm<true,false,true>,  cudaFuncAttributeMaxDynamicSharedMemorySize, GEMM_SMEM);
    cudaFuncSetAttribute(flash_h<true>,  cudaFuncAttributeMaxDynamicSharedMemorySize, FL_SMEM);
    cudaFuncSetAttribute(flash_h<false>, cudaFuncAttributeMaxDynamicSharedMemorySize, FL_SMEM);

    dim3 tb2(256);
    dim3 gDD(8, 32);
    dim3 gQKV(24, 32);
    dim3 gKV(16, 32);
    dim3 gDF(32, 32);
    dim3 gFlash(LSEQ / 128, BATCH * HEADS);

    // ---- launch 1: 8 DD transposes + bucket table, batched ----
    TP8 tp;
    tp.src[0] = sa_q; tp.dst_off[0] = WH_QKV;
    tp.src[1] = sa_k; tp.dst_off[1] = WH_QKV + 1048576;
    tp.src[2] = sa_v; tp.dst_off[2] = WH_QKV + 2 * 1048576;
    tp.src[3] = ca_q; tp.dst_off[3] = WH_CAQ;
    tp.src[4] = ca_k; tp.dst_off[4] = WH_KVX;
    tp.src[5] = ca_v; tp.dst_off[5] = WH_KVX + 1048576;
    tp.src[6] = sa_o; tp.dst_off[6] = WH_SAO;
    tp.src[7] = ca_o; tp.dst_off[7] = WH_CAO;
    transpose_batch<<<dim3(16, 16, 9), tb2>>>(tp, wh);                          // 1
    transpose_h2<<<dim3(64, 16), tb2>>>(wi, wh + WH_WI, DMODEL, DFF);           // 2
    transpose_h2<<<dim3(16, 64), tb2>>>(wo, wh + WH_WO, DFF, DMODEL);           // 3
    conv_half<<<(TOK * DMODEL / 4 + 255) / 256, 256>>>(enc, encr, TOK * DMODEL / 4);  // 4
    rms_kernel<true><<<TOK, 256>>>(hid, ln1_w, xn);                             // 5

    // ---- launch 6: fused QKV GEMM ----
    hgemm<false,false,true><<<gQKV, 256, GEMM_SMEM>>>(xn, wh + WH_QKV, nullptr, qkv, TOK, 3072, DMODEL);

    // ---- Self-attention ----
    flash_h<true><<<gFlash, 256, FL_SMEM>>>(qkv, 3072, qkv + 1024, 3072, qkv + 2048, 3072,
                                            relb, dmask, att);
    hgemm<false,true,false><<<gDD, 256, GEMM_SMEM>>>(att, wh + WH_SAO, hid, h, TOK, DMODEL, DMODEL);

    // ---- Cross-attention ----
    rms_kernel<true><<<TOK, 256>>>(h, ln2_w, xn);
    hgemm<false,false,true><<<gDD, 256, GEMM_SMEM>>>(xn, wh + WH_CAQ, nullptr, qkv, TOK, DMODEL, DMODEL);
    hgemm<false,false,true><<<gKV, 256, GEMM_SMEM>>>(encr, wh + WH_KVX, nullptr, kvx, TOK, 2048, DMODEL);
    flash_h<false><<<gFlash, 256, FL_SMEM>>>(qkv, 1024, kvx, 2048, kvx + 1024, 2048,
                                             nullptr, emask, att);
    hgemm<false,true,false><<<gDD, 256, GEMM_SMEM>>>(att, wh + WH_CAO, h, h, TOK, DMODEL, DMODEL);

    // ---- FFN ----
    rms_kernel<true><<<TOK, 256>>>(h, ln3_w, xn);
    hgemm<true,false,true><<<gDF, 256, GEMM_SMEM>>>(xn, wh + WH_WI, nullptr, ffn, TOK, DFF, DMODEL);
    hgemm<false,true,false><<<gDD, 256, GEMM_SMEM>>>(ffn, wh + WH_WO, h, h, TOK, DMODEL, DFF);

    // ---- Final norm ----
    rms_kernel<false><<<TOK, 256>>>(h, flnw, out);
}

// round 15
// speedup vs baseline: 1.1687x; 1.0148x over previous
#include <cuda_runtime.h>
#include <cuda_fp16.h>
#include <math.h>
#include <stdint.h>

// ---------------- Problem constants ----------------
#define BATCH 4
#define LSEQ  1024
#define DMODEL 1024
#define HEADS 16
#define DKV   64
#define DFF   4096
#define TOK   (BATCH * LSEQ)
#define NBUCK 32
#define NEGINF (-1e9f)

// ---------------- Scratch ----------------
__device__ __half g_xnorm[TOK * DMODEL];
__device__ __half g_qkv[TOK * 3072];
__device__ __half g_kvx[TOK * 2048];
__device__ __half g_att[TOK * DMODEL];
__device__ float  g_h[TOK * DMODEL];
__device__ __half g_encr[TOK * DMODEL];
__device__ __half g_ffn[TOK * DFF];
__device__ __half g_wh[16 * 1024 * 1024];   // fp16 weights, transposed [N][K]
__device__ int    g_bucket[LSEQ];

#define WH_QKV 0                        // [3072][1024]
#define WH_CAQ (3 * 1048576)            // [1024][1024]  (contiguous with KVX -> [3072][1024])
#define WH_KVX (4 * 1048576)            // [2048][1024]
#define WH_SAO (6 * 1048576)
#define WH_CAO (7 * 1048576)
#define WH_WI  (8 * 1048576)            // [4096][1024]
#define WH_WO  (12 * 1048576)           // [1024][4096]

// ---------------- helpers ----------------
__device__ __forceinline__ void mma_f16(float (&d)[4], const uint32_t (&a)[4],
                                        uint32_t b0, uint32_t b1) {
    asm volatile(
        "mma.sync.aligned.m16n8k16.row.col.f32.f16.f16.f32 "
        "{%0,%1,%2,%3}, {%4,%5,%6,%7}, {%8,%9}, {%0,%1,%2,%3};"
        : "+f"(d[0]), "+f"(d[1]), "+f"(d[2]), "+f"(d[3])
        : "r"(a[0]), "r"(a[1]), "r"(a[2]), "r"(a[3]), "r"(b0), "r"(b1));
}
__device__ __forceinline__ void ldsm4(uint32_t (&r)[4], uint32_t addr) {
    asm volatile("ldmatrix.sync.aligned.m8n8.x4.shared.b16 {%0,%1,%2,%3}, [%4];"
                 : "=r"(r[0]), "=r"(r[1]), "=r"(r[2]), "=r"(r[3]) : "r"(addr));
}
__device__ __forceinline__ void ldsm4t(uint32_t (&r)[4], uint32_t addr) {
    asm volatile("ldmatrix.sync.aligned.m8n8.x4.trans.shared.b16 {%0,%1,%2,%3}, [%4];"
                 : "=r"(r[0]), "=r"(r[1]), "=r"(r[2]), "=r"(r[3]) : "r"(addr));
}
__device__ __forceinline__ void cp16s(uint32_t dst, const void* src) {
    asm volatile("cp.async.cg.shared.global [%0], [%1], 16;" :: "r"(dst), "l"(src));
}
__device__ __forceinline__ void cp_commit() { asm volatile("cp.async.commit_group;"); }
__device__ __forceinline__ void cp_wait0()  { asm volatile("cp.async.wait_group 0;" ::: "memory"); }
__device__ __forceinline__ uint32_t packh2(float a, float b) {
    __half2 t = __floats2half2_rn(a, b);
    return *(uint32_t*)&t;
}

// ---------------- prep: batched transpose + bucket table (z==8) -----------
struct TP8 {
    const float* src[8];
    unsigned dst_off[8];
};

__global__ void __launch_bounds__(256)
transpose_batch(TP8 args, __half* __restrict__ whbase) {
    int z = blockIdx.z;
    if (z == 8) {
        if (blockIdx.x == 0 && blockIdx.y == 0) {
            #pragma unroll
            for (int i = 0; i < 4; i++) {
                int n = threadIdx.x + i * 256;
                int b;
                if (n < 16) {
                    b = n;
                } else {
                    float nf = (float)n;
                    int vl = 16 + (int)(logf(nf / 16.0f) / logf(8.0f) * 16.0f);
                    b = vl < (NBUCK - 1) ? vl : (NBUCK - 1);
                }
                g_bucket[n] = b;
            }
        }
        return;
    }
    __shared__ float t[64][65];
    const float* W = args.src[z];
    __half* Wt = whbase + args.dst_off[z];
    int n0 = blockIdx.x * 64, k0 = blockIdx.y * 64;
    int tid = threadIdx.x;
    int row = tid >> 2;
    int qc  = tid & 3;
    #pragma unroll
    for (int j = 0; j < 4; j++) {
        float4 v = *(const float4*)(W + (size_t)(k0 + row) * 1024 + n0 + qc * 16 + j * 4);
        t[row][qc * 16 + j * 4 + 0] = v.x;
        t[row][qc * 16 + j * 4 + 1] = v.y;
        t[row][qc * 16 + j * 4 + 2] = v.z;
        t[row][qc * 16 + j * 4 + 3] = v.w;
    }
    __syncthreads();
    #pragma unroll
    for (int j = 0; j < 2; j++) {
        __half hbuf[8];
        #pragma unroll
        for (int e = 0; e < 8; e++)
            hbuf[e] = __float2half(t[qc * 16 + j * 8 + e][row]);
        *(uint4*)(Wt + (size_t)(n0 + row) * 1024 + k0 + qc * 16 + j * 8) = *(uint4*)hbuf;
    }
}

// ---------------- prep2: wi transpose (z=0), wo transpose (z=1), conv (z=2)
__global__ void __launch_bounds__(256)
prep_misc(const float* __restrict__ wi, const float* __restrict__ wo,
          const float* __restrict__ enc, __half* __restrict__ whbase,
          __half* __restrict__ encr) {
    int z = blockIdx.z;
    int bx = blockIdx.x;
    int tid = threadIdx.x;
    if (z == 2) {
        // conv enc -> half: 1,048,576 float4 over 1024 blocks x 4 iters
        #pragma unroll
        for (int j = 0; j < 4; j++) {
            int i = bx * 1024 + j * 256 + tid;
            float4 v = ((const float4*)enc)[i];
            __half2* d = (__half2*)(encr + (size_t)i * 4);
            d[0] = __floats2half2_rn(v.x, v.y);
            d[1] = __floats2half2_rn(v.z, v.w);
        }
        return;
    }
    const float* W;
    __half* Wt;
    int K, N, n0, k0;
    if (z == 0) {   // wi: [1024][4096] -> [4096][1024]; 64 n-blocks, 16 k-blocks
        W = wi; Wt = whbase + WH_WI; K = DMODEL; N = DFF;
        n0 = (bx & 63) * 64; k0 = (bx >> 6) * 64;
    } else {        // wo: [4096][1024] -> [1024][4096]; 16 n-blocks, 64 k-blocks
        W = wo; Wt = whbase + WH_WO; K = DFF; N = DMODEL;
        n0 = (bx & 15) * 64; k0 = (bx >> 4) * 64;
    }
    __shared__ float t[64][65];
    int row = tid >> 2;
    int qc  = tid & 3;
    #pragma unroll
    for (int j = 0; j < 4; j++) {
        float4 v = *(const float4*)(W + (size_t)(k0 + row) * N + n0 + qc * 16 + j * 4);
        t[row][qc * 16 + j * 4 + 0] = v.x;
        t[row][qc * 16 + j * 4 + 1] = v.y;
        t[row][qc * 16 + j * 4 + 2] = v.z;
        t[row][qc * 16 + j * 4 + 3] = v.w;
    }
    __syncthreads();
    #pragma unroll
    for (int j = 0; j < 2; j++) {
        __half hbuf[8];
        #pragma unroll
        for (int e = 0; e < 8; e++)
            hbuf[e] = __float2half(t[qc * 16 + j * 8 + e][row]);
        *(uint4*)(Wt + (size_t)(n0 + row) * K + k0 + qc * 16 + j * 8) = *(uint4*)hbuf;
    }
}

// ---------------- RMS norm (vectorized) ----------------
template<bool HOUT>
__global__ void rms_kernel(const float* __restrict__ x,
                           const float* __restrict__ w, void* __restrict__ yv) {
    int row = blockIdx.x;
    int tid = threadIdx.x;
    float4 v = ((const float4*)(x + (size_t)row * DMODEL))[tid];
    float s = v.x * v.x + v.y * v.y + v.z * v.z + v.w * v.w;
    __shared__ float red[8];
    #pragma unroll
    for (int o = 16; o; o >>= 1) s += __shfl_xor_sync(0xffffffffu, s, o);
    if ((tid & 31) == 0) red[tid >> 5] = s;
    __syncthreads();
    if (tid < 8) {
        float t = red[tid];
        #pragma unroll
        for (int o = 4; o; o >>= 1) t += __shfl_xor_sync(0xffu, t, o);
        if (tid == 0) red[0] = rsqrtf(t * (1.0f / DMODEL) + 1e-6f);
    }
    __syncthreads();
    float inv = red[0];
    float4 wv = ((const float4*)w)[tid];
    float a = v.x * inv * wv.x, b = v.y * inv * wv.y;
    float c = v.z * inv * wv.z, d = v.w * inv * wv.w;
    if (HOUT) {
        __half2* yr = (__half2*)yv + (size_t)row * (DMODEL / 2);
        yr[tid * 2]     = __floats2half2_rn(a, b);
        yr[tid * 2 + 1] = __floats2half2_rn(c, d);
    } else {
        ((float4*)yv)[(size_t)row * (DMODEL / 4) + tid] = make_float4(a, b, c, d);
    }
}

// ---------------- fp16 GEMM (known-good: 2-stage, 8 warps 2Mx4N) ----------
// DUAL: blocks with blockIdx.x < splitX read A1 and write C1[TOK][1024];
//       others read A2, write C2[TOK][2048] at col (n0 - 1024).
#define GSM_TILE 18432
#define GEMM_SMEM (4 * GSM_TILE)

template<bool RELU, bool RES, bool HOUT, bool DUAL>
__global__ void __launch_bounds__(256, 2)
hgemm(const __half* __restrict__ A, const __half* __restrict__ B,
      const float* __restrict__ R, void* __restrict__ Cv,
      int M, int N, int K,
      const __half* A2 = nullptr, void* Cv2 = nullptr) {
    extern __shared__ char smc[];
    uint32_t S = (uint32_t)__cvta_generic_to_shared(smc);
    const int tid = threadIdx.x;
    const int warp = tid >> 5, lane = tid & 31;
    const int gid = lane >> 2, tg = lane & 3;
    const int wm = warp & 1, wn = warp >> 1;
    const int m0 = blockIdx.y * 128;
    int n0 = blockIdx.x * 128;
    const __half* Asel = A;
    void* Csel = Cv;
    int Nc = N, c0 = n0;
    if (DUAL && n0 >= 1024) {
        Asel = A2; Csel = Cv2; Nc = 2048; c0 = n0 - 1024;
    } else if (DUAL) {
        Nc = 1024;
    }
    const __half* Ag = Asel + (size_t)m0 * K;
    const __half* Bg = B + (size_t)n0 * K;

    float acc[4][4][4];
    #pragma unroll
    for (int i = 0; i < 4; i++)
        #pragma unroll
        for (int j = 0; j < 4; j++)
            #pragma unroll
            for (int l = 0; l < 4; l++) acc[i][j][l] = 0.f;

    #define GLOAD(kt, s) do {                                                 \
        uint32_t ab = S + (s) * GSM_TILE;                                     \
        uint32_t bb = S + 2 * GSM_TILE + (s) * GSM_TILE;                      \
        _Pragma("unroll")                                                     \
        for (int i = 0; i < 4; i++) {                                         \
            int idx = tid + i * 256;                                          \
            int r = idx >> 3, c = idx & 7;                                    \
            cp16s(ab + r * 144 + c * 16, Ag + (size_t)r * K + (kt) + c * 8);  \
            cp16s(bb + r * 144 + c * 16, Bg + (size_t)r * K + (kt) + c * 8);  \
        }                                                                     \
        cp_commit();                                                          \
    } while (0)

    GLOAD(0, 0);
    cp_wait0();
    __syncthreads();

    int s = 0;
    for (int kt = 0; kt < K; kt += 64) {
        bool more = (kt + 64 < K);
        if (more) GLOAD(kt + 64, s ^ 1);
        uint32_t ab = S + s * GSM_TILE;
        uint32_t bb = S + 2 * GSM_TILE + s * GSM_TILE;
        #pragma unroll
        for (int ks = 0; ks < 4; ks++) {
            uint32_t af[4][4], bf[2][4];
            #pragma unroll
            for (int mt = 0; mt < 4; mt++)
                ldsm4(af[mt], ab + (wm * 64 + mt * 16 + (lane & 15)) * 144
                              + ks * 32 + (lane >> 4) * 16);
            #pragma unroll
            for (int g = 0; g < 2; g++)
                ldsm4(bf[g], bb + (wn * 32 + g * 16 + ((lane >> 4) << 3) + (lane & 7)) * 144
                             + ks * 32 + ((lane >> 3) & 1) * 16);
            #pragma unroll
            for (int mt = 0; mt < 4; mt++)
                #pragma unroll
                for (int nt = 0; nt < 4; nt++)
                    mma_f16(acc[mt][nt], af[mt],
                            bf[nt >> 1][(nt & 1) * 2], bf[nt >> 1][(nt & 1) * 2 + 1]);
        }
        if (more) cp_wait0();
        __syncthreads();
        s ^= 1;
    }

    #pragma unroll
    for (int mt = 0; mt < 4; mt++) {
        #pragma unroll
        for (int nt = 0; nt < 4; nt++) {
            int r0 = m0 + wm * 64 + mt * 16 + gid;
            int c  = c0 + wn * 32 + nt * 8 + tg * 2;
            float2 v0 = make_float2(acc[mt][nt][0], acc[mt][nt][1]);
            float2 v1 = make_float2(acc[mt][nt][2], acc[mt][nt][3]);
            if (RES) {
                float2 a0 = *(const float2*)(R + (size_t)r0 * Nc + c);
                float2 a1 = *(const float2*)(R + (size_t)(r0 + 8) * Nc + c);
                v0.x += a0.x; v0.y += a0.y; v1.x += a1.x; v1.y += a1.y;
            }
            if (RELU) {
                v0.x = fmaxf(v0.x, 0.f); v0.y = fmaxf(v0.y, 0.f);
                v1.x = fmaxf(v1.x, 0.f); v1.y = fmaxf(v1.y, 0.f);
            }
            if (HOUT) {
                __half* C = (__half*)Csel;
                *(__half2*)(C + (size_t)r0 * Nc + c)       = __floats2half2_rn(v0.x, v0.y);
                *(__half2*)(C + (size_t)(r0 + 8) * Nc + c) = __floats2half2_rn(v1.x, v1.y);
            } else {
                float* C = (float*)Csel;
                *(float2*)(C + (size_t)r0 * Nc + c) = v0;
                *(float2*)(C + (size_t)(r0 + 8) * Nc + c) = v1;
            }
        }
    }
    #undef GLOAD
}

// ---------------- FA2 flash: register P, warp-local softmax ---------------
#define F2_Q   0
#define F2_KV0 18432
#define F2_STG 36864
#define FL_SMEM (18432 + 2 * 36864)

template<bool SELF>
__global__ void __launch_bounds__(256)
flash_h(const __half* __restrict__ Qp, int qstride,
        const __half* __restrict__ Kp, int kstride,
        const __half* __restrict__ Vp, int vstride,
        const float* __restrict__ relb, const int* __restrict__ mask,
        __half* __restrict__ O) {
    extern __shared__ char smc[];
    uint32_t S = (uint32_t)__cvta_generic_to_shared(smc);
    int tid = threadIdx.x;
    int warp = tid >> 5, lane = tid & 31;
    int gid = lane >> 2, tg = lane & 3;
    int qt = SELF ? (gridDim.x - 1 - blockIdx.x) : blockIdx.x;
    int q0 = qt * 128;
    int bh = blockIdx.y;
    int b = bh >> 4, h = bh & 15;

    const __half* Qg = Qp + (size_t)(b * LSEQ + q0) * qstride + h * DKV;
    const __half* Kg = Kp + (size_t)(b * LSEQ) * kstride + h * DKV;
    const __half* Vg = Vp + (size_t)(b * LSEQ) * vstride + h * DKV;
    const int* maskb = mask + b * LSEQ;

    #define KVLOAD(it, st) do {                                               \
        uint32_t kb = S + F2_KV0 + (st) * F2_STG;                             \
        uint32_t vb = kb + 18432;                                             \
        int kk0 = (it) * 128;                                                 \
        _Pragma("unroll")                                                     \
        for (int i = 0; i < 4; i++) {                                         \
            int idx = tid + i * 256;                                          \
            int r = idx >> 3, c = idx & 7;                                    \
            cp16s(kb + r * 144 + c * 16, Kg + (size_t)(kk0 + r) * kstride + c * 8); \
            cp16s(vb + r * 144 + c * 16, Vg + (size_t)(kk0 + r) * vstride + c * 8); \
        }                                                                     \
        cp_commit();                                                          \
    } while (0)

    #pragma unroll
    for (int i = 0; i < 4; i++) {
        int idx = tid + i * 256;
        int r = idx >> 3, c = idx & 7;
        cp16s(S + F2_Q + r * 144 + c * 16, Qg + (size_t)r * qstride + c * 8);
    }
    KVLOAD(0, 0);

    float oacc[8][4];
    #pragma unroll
    for (int i = 0; i < 8; i++)
        #pragma unroll
        for (int l = 0; l < 4; l++) oacc[i][l] = 0.f;
    float m0 = -1e30f, m1 = -1e30f, l0 = 0.f, l1 = 0.f;

    const int niter = SELF ? (qt + 1) : (LSEQ / 128);
    const int qi0 = q0 + warp * 16 + gid;
    const int qi1 = qi0 + 8;

    cp_wait0();
    __syncthreads();

    int s = 0;
    for (int it = 0; it < niter; it++) {
        int k0 = it * 128;
        bool more = (it + 1 < niter);
        if (more) KVLOAD(it + 1, s ^ 1);
        uint32_t Kb = S + F2_KV0 + s * F2_STG;
        uint32_t Vb = Kb + 18432;

        float sacc[16][4];
        #pragma unroll
        for (int j = 0; j < 16; j++)
            #pragma unroll
            for (int l = 0; l < 4; l++) sacc[j][l] = 0.f;

        #pragma unroll
        for (int ks = 0; ks < 4; ks++) {
            uint32_t af[4];
            ldsm4(af, S + F2_Q + (warp * 16 + (lane & 15)) * 144
                      + ks * 32 + (lane >> 4) * 16);
            #pragma unroll
            for (int g = 0; g < 8; g++) {
                uint32_t bf[4];
                ldsm4(bf, Kb + (g * 16 + ((lane >> 4) << 3) + (lane & 7)) * 144
                          + ks * 32 + ((lane >> 3) & 1) * 16);
                mma_f16(sacc[2 * g],     af, bf[0], bf[1]);
                mma_f16(sacc[2 * g + 1], af, bf[2], bf[3]);
            }
        }

        #pragma unroll
        for (int j = 0; j < 16; j++) {
            int c = k0 + j * 8 + tg * 2;
            bool mk0 = maskb[c] > 0;
            bool mk1 = maskb[c + 1] > 0;
            if (SELF) {
                int d00 = qi0 - c, d01 = d00 - 1;
                int d10 = qi1 - c, d11 = d10 - 1;
                sacc[j][0] += relb[g_bucket[d00 > 0 ? d00 : 0] * HEADS + h];
                sacc[j][1] += relb[g_bucket[d01 > 0 ? d01 : 0] * HEADS + h];
                sacc[j][2] += relb[g_bucket[d10 > 0 ? d10 : 0] * HEADS + h];
                sacc[j][3] += relb[g_bucket[d11 > 0 ? d11 : 0] * HEADS + h];
                if (!((c     <= qi0) && mk0)) sacc[j][0] += NEGINF;
                if (!((c + 1 <= qi0) && mk1)) sacc[j][1] += NEGINF;
                if (!((c     <= qi1) && mk0)) sacc[j][2] += NEGINF;
                if (!((c + 1 <= qi1) && mk1)) sacc[j][3] += NEGINF;
            } else {
                if (!mk0) { sacc[j][0] += NEGINF; sacc[j][2] += NEGINF; }
                if (!mk1) { sacc[j][1] += NEGINF; sacc[j][3] += NEGINF; }
            }
        }

        float mt0 = -1e30f, mt1 = -1e30f;
        #pragma unroll
        for (int j = 0; j < 16; j++) {
            mt0 = fmaxf(mt0, fmaxf(sacc[j][0], sacc[j][1]));
            mt1 = fmaxf(mt1, fmaxf(sacc[j][2], sacc[j][3]));
        }
        mt0 = fmaxf(mt0, __shfl_xor_sync(0xffffffffu, mt0, 1));
        mt0 = fmaxf(mt0, __shfl_xor_sync(0xffffffffu, mt0, 2));
        mt1 = fmaxf(mt1, __shfl_xor_sync(0xffffffffu, mt1, 1));
        mt1 = fmaxf(mt1, __shfl_xor_sync(0xffffffffu, mt1, 2));
        float mn0 = fmaxf(m0, mt0), mn1 = fmaxf(m1, mt1);
        float rs0 = __expf(m0 - mn0), rs1 = __expf(m1 - mn1);
        float s0 = 0.f, s1 = 0.f;
        #pragma unroll
        for (int j = 0; j < 16; j++) {
            float e0 = __expf(sacc[j][0] - mn0);
            float e1 = __expf(sacc[j][1] - mn0);
            float e2 = __expf(sacc[j][2] - mn1);
            float e3 = __expf(sacc[j][3] - mn1);
            sacc[j][0] = e0; sacc[j][1] = e1; sacc[j][2] = e2; sacc[j][3] = e3;
            s0 += e0 + e1;
            s1 += e2 + e3;
        }
        s0 += __shfl_xor_sync(0xffffffffu, s0, 1);
        s0 += __shfl_xor_sync(0xffffffffu, s0, 2);
        s1 += __shfl_xor_sync(0xffffffffu, s1, 1);
        s1 += __shfl_xor_sync(0xffffffffu, s1, 2);
        l0 = l0 * rs0 + s0;
        l1 = l1 * rs1 + s1;
        m0 = mn0; m1 = mn1;
        #pragma unroll
        for (int nt = 0; nt < 8; nt++) {
            oacc[nt][0] *= rs0; oacc[nt][1] *= rs0;
            oacc[nt][2] *= rs1; oacc[nt][3] *= rs1;
        }

        uint32_t ph[8][4];
        #pragma unroll
        for (int t = 0; t < 8; t++) {
            ph[t][0] = packh2(sacc[2 * t][0],     sacc[2 * t][1]);
            ph[t][1] = packh2(sacc[2 * t][2],     sacc[2 * t][3]);
            ph[t][2] = packh2(sacc[2 * t + 1][0], sacc[2 * t + 1][1]);
            ph[t][3] = packh2(sacc[2 * t + 1][2], sacc[2 * t + 1][3]);
        }

        #pragma unroll
        for (int t = 0; t < 8; t++) {
            #pragma unroll
            for (int g = 0; g < 4; g++) {
                uint32_t bf[4];
                ldsm4t(bf, Vb + (t * 16 + ((lane >> 3) & 1) * 8 + (lane & 7)) * 144
                           + g * 32 + (lane >> 4) * 16);
                mma_f16(oacc[2 * g],     ph[t], bf[0], bf[1]);
                mma_f16(oacc[2 * g + 1], ph[t], bf[2], bf[3]);
            }
        }

        if (more) cp_wait0();
        __syncthreads();
        s ^= 1;
    }

    float inv0 = 1.0f / l0;
    float inv1 = 1.0f / l1;
    size_t row0 = (size_t)(b * LSEQ + qi0);
    size_t row1 = (size_t)(b * LSEQ + qi1);
    #pragma unroll
    for (int nt = 0; nt < 8; nt++) {
        int col = h * DKV + nt * 8 + tg * 2;
        *(__half2*)(O + row0 * DMODEL + col)
            = __floats2half2_rn(oacc[nt][0] * inv0, oacc[nt][1] * inv0);
        *(__half2*)(O + row1 * DMODEL + col)
            = __floats2half2_rn(oacc[nt][2] * inv1, oacc[nt][3] * inv1);
    }
    #undef KVLOAD
}

// ---------------- Orchestration -------------------------------------------
extern "C" void kernel_launch(void* const* d_in, const int* in_sizes, int n_in,
                              void* d_out, int out_size) {
    const float* enc    = (const float*)d_in[0];
    const float* hid    = (const float*)d_in[1];
    const float* ln1_w  = (const float*)d_in[2];
    const float* sa_q   = (const float*)d_in[3];
    const float* sa_k   = (const float*)d_in[4];
    const float* sa_v   = (const float*)d_in[5];
    const float* sa_o   = (const float*)d_in[6];
    const float* relb   = (const float*)d_in[7];
    const float* ln2_w  = (const float*)d_in[8];
    const float* ca_q   = (const float*)d_in[9];
    const float* ca_k   = (const float*)d_in[10];
    const float* ca_v   = (const float*)d_in[11];
    const float* ca_o   = (const float*)d_in[12];
    const float* ln3_w  = (const float*)d_in[13];
    const float* wi     = (const float*)d_in[14];
    const float* wo     = (const float*)d_in[15];
    const float* flnw   = (const float*)d_in[16];
    const int*   emask  = (const int*)d_in[17];
    const int*   dmask  = (const int*)d_in[18];
    float* out = (float*)d_out;

    __half *xn, *qkv, *kvx, *att, *encr, *ffn, *wh;
    float *h;
    cudaGetSymbolAddress((void**)&xn,   g_xnorm);
    cudaGetSymbolAddress((void**)&qkv,  g_qkv);
    cudaGetSymbolAddress((void**)&kvx,  g_kvx);
    cudaGetSymbolAddress((void**)&att,  g_att);
    cudaGetSymbolAddress((void**)&h,    g_h);
    cudaGetSymbolAddress((void**)&encr, g_encr);
    cudaGetSymbolAddress((void**)&ffn,  g_ffn);
    cudaGetSymbolAddress((void**)&wh,   g_wh);

    cudaFuncSetAttribute(hgemm<false,false,true,false>, cudaFuncAttributeMaxDynamicSharedMemorySize, GEMM_SMEM);
    cudaFuncSetAttribute(hgemm<false,false,true,true>,  cudaFuncAttributeMaxDynamicSharedMemorySize, GEMM_SMEM);
    cudaFuncSetAttribute(hgemm<false,true,false,false>, cudaFuncAttributeMaxDynamicSharedMemorySize, GEMM_SMEM);
    cudaFuncSetAttribute(hgemm<true,false,true,false>,  cudaFuncAttributeMaxDynamicSharedMemorySize, GEMM_SMEM);
    cudaFuncSetAttribute(flash_h<true>,  cudaFuncAttributeMaxDynamicSharedMemorySize, FL_SMEM);
    cudaFuncSetAttribute(flash_h<false>, cudaFuncAttributeMaxDynamicSharedMemorySize, FL_SMEM);

    dim3 tb2(256);
    dim3 gDD(8, 32);
    dim3 gQKV(24, 32);
    dim3 gCROSS(24, 32);            // merged cross Q (8) + KV (16) column blocks
    dim3 gDF(32, 32);
    dim3 gFlash(LSEQ / 128, BATCH * HEADS);

    // ---- launch 1: 8 DD transposes + bucket table, batched ----
    TP8 tp;
    tp.src[0] = sa_q; tp.dst_off[0] = WH_QKV;
    tp.src[1] = sa_k; tp.dst_off[1] = WH_QKV + 1048576;
    tp.src[2] = sa_v; tp.dst_off[2] = WH_QKV + 2 * 1048576;
    tp.src[3] = ca_q; tp.dst_off[3] = WH_CAQ;
    tp.src[4] = ca_k; tp.dst_off[4] = WH_KVX;
    tp.src[5] = ca_v; tp.dst_off[5] = WH_KVX + 1048576;
    tp.src[6] = sa_o; tp.dst_off[6] = WH_SAO;
    tp.src[7] = ca_o; tp.dst_off[7] = WH_CAO;
    transpose_batch<<<dim3(16, 16, 9), tb2>>>(tp, wh);                          // 1
    prep_misc<<<dim3(1024, 1, 3), tb2>>>(wi, wo, enc, wh, encr);                // 2
    rms_kernel<true><<<TOK, 256>>>(hid, ln1_w, xn);                             // 3

    // ---- fused QKV GEMM ----
    hgemm<false,false,true,false><<<gQKV, 256, GEMM_SMEM>>>(xn, wh + WH_QKV, nullptr, qkv, TOK, 3072, DMODEL);

    // ---- Self-attention ----
    flash_h<true><<<gFlash, 256, FL_SMEM>>>(qkv, 3072, qkv + 1024, 3072, qkv + 2048, 3072,
                                            relb, dmask, att);
    hgemm<false,true,false,false><<<gDD, 256, GEMM_SMEM>>>(att, wh + WH_SAO, hid, h, TOK, DMODEL, DMODEL);

    // ---- Cross-attention (merged Q + KV projection) ----
    rms_kernel<true><<<TOK, 256>>>(h, ln2_w, xn);
    hgemm<false,false,true,true><<<gCROSS, 256, GEMM_SMEM>>>(xn, wh + WH_CAQ, nullptr, qkv,
                                                             TOK, 3072, DMODEL, encr, kvx);
    flash_h<false><<<gFlash, 256, FL_SMEM>>>(qkv, 1024, kvx, 2048, kvx + 1024, 2048,
                                             nullptr, emask, att);
    hgemm<false,true,false,false><<<gDD, 256, GEMM_SMEM>>>(att, wh + WH_CAO, h, h, TOK, DMODEL, DMODEL);

    // ---- FFN ----
    rms_kernel<true><<<TOK, 256>>>(h, ln3_w, xn);
    hgemm<true,false,true,false><<<gDF, 256, GEMM_SMEM>>>(xn, wh + WH_WI, nullptr, ffn, TOK, DFF, DMODEL);
    hgemm<false,true,false,false><<<gDD, 256, GEMM_SMEM>>>(ffn, wh + WH_WO, h, h, TOK, DMODEL, DFF);

    // ---- Final norm ----
    rms_kernel<false><<<TOK, 256>>>(h, flnw, out);
}

// round 16
// speedup vs baseline: 1.1784x; 1.0083x over previous
#include <cuda_runtime.h>
#include <cuda_fp16.h>
#include <math.h>
#include <stdint.h>

// ---------------- Problem constants ----------------
#define BATCH 4
#define LSEQ  1024
#define DMODEL 1024
#define HEADS 16
#define DKV   64
#define DFF   4096
#define TOK   (BATCH * LSEQ)
#define NBUCK 32
#define NEGINF (-1e9f)

// ---------------- Scratch ----------------
__device__ __half g_xnorm[TOK * DMODEL];
__device__ __half g_qkv[TOK * 3072];
__device__ __half g_kvx[TOK * 2048];
__device__ __half g_att[TOK * DMODEL];
__device__ float  g_h[TOK * DMODEL];
__device__ __half g_encr[TOK * DMODEL];
__device__ __half g_ffn[TOK * DFF];
__device__ __half g_wh[16 * 1024 * 1024];   // fp16 weights, transposed [N][K]
__device__ int    g_bucket[LSEQ];

#define WH_QKV 0                        // [3072][1024]
#define WH_CAQ (3 * 1048576)            // [1024][1024]  (contiguous with KVX -> [3072][1024])
#define WH_KVX (4 * 1048576)            // [2048][1024]
#define WH_SAO (6 * 1048576)
#define WH_CAO (7 * 1048576)
#define WH_WI  (8 * 1048576)            // [4096][1024]
#define WH_WO  (12 * 1048576)           // [1024][4096]

// ---------------- helpers ----------------
__device__ __forceinline__ void mma_f16(float (&d)[4], const uint32_t (&a)[4],
                                        uint32_t b0, uint32_t b1) {
    asm volatile(
        "mma.sync.aligned.m16n8k16.row.col.f32.f16.f16.f32 "
        "{%0,%1,%2,%3}, {%4,%5,%6,%7}, {%8,%9}, {%0,%1,%2,%3};"
        : "+f"(d[0]), "+f"(d[1]), "+f"(d[2]), "+f"(d[3])
        : "r"(a[0]), "r"(a[1]), "r"(a[2]), "r"(a[3]), "r"(b0), "r"(b1));
}
__device__ __forceinline__ void ldsm4(uint32_t (&r)[4], uint32_t addr) {
    asm volatile("ldmatrix.sync.aligned.m8n8.x4.shared.b16 {%0,%1,%2,%3}, [%4];"
                 : "=r"(r[0]), "=r"(r[1]), "=r"(r[2]), "=r"(r[3]) : "r"(addr));
}
__device__ __forceinline__ void ldsm4t(uint32_t (&r)[4], uint32_t addr) {
    asm volatile("ldmatrix.sync.aligned.m8n8.x4.trans.shared.b16 {%0,%1,%2,%3}, [%4];"
                 : "=r"(r[0]), "=r"(r[1]), "=r"(r[2]), "=r"(r[3]) : "r"(addr));
}
__device__ __forceinline__ void cp16s(uint32_t dst, const void* src) {
    asm volatile("cp.async.cg.shared.global [%0], [%1], 16;" :: "r"(dst), "l"(src));
}
__device__ __forceinline__ void cp_commit() { asm volatile("cp.async.commit_group;"); }
__device__ __forceinline__ void cp_wait0()  { asm volatile("cp.async.wait_group 0;" ::: "memory"); }
__device__ __forceinline__ uint32_t packh2(float a, float b) {
    __half2 t = __floats2half2_rn(a, b);
    return *(uint32_t*)&t;
}

// ---------------- prep: batched transpose + bucket table (z==8) -----------
struct TP8 {
    const float* src[8];
    unsigned dst_off[8];
};

__global__ void __launch_bounds__(256)
transpose_batch(TP8 args, __half* __restrict__ whbase) {
    int z = blockIdx.z;
    if (z == 8) {
        if (blockIdx.x == 0 && blockIdx.y == 0) {
            #pragma unroll
            for (int i = 0; i < 4; i++) {
                int n = threadIdx.x + i * 256;
                int b;
                if (n < 16) {
                    b = n;
                } else {
                    float nf = (float)n;
                    int vl = 16 + (int)(logf(nf / 16.0f) / logf(8.0f) * 16.0f);
                    b = vl < (NBUCK - 1) ? vl : (NBUCK - 1);
                }
                g_bucket[n] = b;
            }
        }
        return;
    }
    __shared__ float t[64][65];
    const float* W = args.src[z];
    __half* Wt = whbase + args.dst_off[z];
    int n0 = blockIdx.x * 64, k0 = blockIdx.y * 64;
    int tid = threadIdx.x;
    int row = tid >> 2;
    int qc  = tid & 3;
    #pragma unroll
    for (int j = 0; j < 4; j++) {
        float4 v = *(const float4*)(W + (size_t)(k0 + row) * 1024 + n0 + qc * 16 + j * 4);
        t[row][qc * 16 + j * 4 + 0] = v.x;
        t[row][qc * 16 + j * 4 + 1] = v.y;
        t[row][qc * 16 + j * 4 + 2] = v.z;
        t[row][qc * 16 + j * 4 + 3] = v.w;
    }
    __syncthreads();
    #pragma unroll
    for (int j = 0; j < 2; j++) {
        __half hbuf[8];
        #pragma unroll
        for (int e = 0; e < 8; e++)
            hbuf[e] = __float2half(t[qc * 16 + j * 8 + e][row]);
        *(uint4*)(Wt + (size_t)(n0 + row) * 1024 + k0 + qc * 16 + j * 8) = *(uint4*)hbuf;
    }
}

// ---------------- prep2: wi transpose (z=0), wo transpose (z=1), conv (z=2)
__global__ void __launch_bounds__(256)
prep_misc(const float* __restrict__ wi, const float* __restrict__ wo,
          const float* __restrict__ enc, __half* __restrict__ whbase,
          __half* __restrict__ encr) {
    int z = blockIdx.z;
    int bx = blockIdx.x;
    int tid = threadIdx.x;
    if (z == 2) {
        #pragma unroll
        for (int j = 0; j < 4; j++) {
            int i = bx * 1024 + j * 256 + tid;
            float4 v = ((const float4*)enc)[i];
            __half2* d = (__half2*)(encr + (size_t)i * 4);
            d[0] = __floats2half2_rn(v.x, v.y);
            d[1] = __floats2half2_rn(v.z, v.w);
        }
        return;
    }
    const float* W;
    __half* Wt;
    int K, N, n0, k0;
    if (z == 0) {
        W = wi; Wt = whbase + WH_WI; K = DMODEL; N = DFF;
        n0 = (bx & 63) * 64; k0 = (bx >> 6) * 64;
    } else {
        W = wo; Wt = whbase + WH_WO; K = DFF; N = DMODEL;
        n0 = (bx & 15) * 64; k0 = (bx >> 4) * 64;
    }
    __shared__ float t[64][65];
    int row = tid >> 2;
    int qc  = tid & 3;
    #pragma unroll
    for (int j = 0; j < 4; j++) {
        float4 v = *(const float4*)(W + (size_t)(k0 + row) * N + n0 + qc * 16 + j * 4);
        t[row][qc * 16 + j * 4 + 0] = v.x;
        t[row][qc * 16 + j * 4 + 1] = v.y;
        t[row][qc * 16 + j * 4 + 2] = v.z;
        t[row][qc * 16 + j * 4 + 3] = v.w;
    }
    __syncthreads();
    #pragma unroll
    for (int j = 0; j < 2; j++) {
        __half hbuf[8];
        #pragma unroll
        for (int e = 0; e < 8; e++)
            hbuf[e] = __float2half(t[qc * 16 + j * 8 + e][row]);
        *(uint4*)(Wt + (size_t)(n0 + row) * K + k0 + qc * 16 + j * 8) = *(uint4*)hbuf;
    }
}

// ---------------- RMS norm (vectorized) ----------------
template<bool HOUT>
__global__ void rms_kernel(const float* __restrict__ x,
                           const float* __restrict__ w, void* __restrict__ yv) {
    int row = blockIdx.x;
    int tid = threadIdx.x;
    float4 v = ((const float4*)(x + (size_t)row * DMODEL))[tid];
    float s = v.x * v.x + v.y * v.y + v.z * v.z + v.w * v.w;
    __shared__ float red[8];
    #pragma unroll
    for (int o = 16; o; o >>= 1) s += __shfl_xor_sync(0xffffffffu, s, o);
    if ((tid & 31) == 0) red[tid >> 5] = s;
    __syncthreads();
    if (tid < 8) {
        float t = red[tid];
        #pragma unroll
        for (int o = 4; o; o >>= 1) t += __shfl_xor_sync(0xffu, t, o);
        if (tid == 0) red[0] = rsqrtf(t * (1.0f / DMODEL) + 1e-6f);
    }
    __syncthreads();
    float inv = red[0];
    float4 wv = ((const float4*)w)[tid];
    float a = v.x * inv * wv.x, b = v.y * inv * wv.y;
    float c = v.z * inv * wv.z, d = v.w * inv * wv.w;
    if (HOUT) {
        __half2* yr = (__half2*)yv + (size_t)row * (DMODEL / 2);
        yr[tid * 2]     = __floats2half2_rn(a, b);
        yr[tid * 2 + 1] = __floats2half2_rn(c, d);
    } else {
        ((float4*)yv)[(size_t)row * (DMODEL / 4) + tid] = make_float4(a, b, c, d);
    }
}

// ---------------- fp16 GEMM (known-good: 2-stage, 8 warps 2Mx4N) ----------
#define GSM_TILE 18432
#define GEMM_SMEM (4 * GSM_TILE)

template<bool RELU, bool RES, bool HOUT, bool DUAL>
__global__ void __launch_bounds__(256, 2)
hgemm(const __half* __restrict__ A, const __half* __restrict__ B,
      const float* __restrict__ R, void* __restrict__ Cv,
      int M, int N, int K,
      const __half* A2 = nullptr, void* Cv2 = nullptr) {
    extern __shared__ char smc[];
    uint32_t S = (uint32_t)__cvta_generic_to_shared(smc);
    const int tid = threadIdx.x;
    const int warp = tid >> 5, lane = tid & 31;
    const int gid = lane >> 2, tg = lane & 3;
    const int wm = warp & 1, wn = warp >> 1;
    const int m0 = blockIdx.y * 128;
    int n0 = blockIdx.x * 128;
    const __half* Asel = A;
    void* Csel = Cv;
    int Nc = N, c0 = n0;
    if (DUAL && n0 >= 1024) {
        Asel = A2; Csel = Cv2; Nc = 2048; c0 = n0 - 1024;
    } else if (DUAL) {
        Nc = 1024;
    }
    const __half* Ag = Asel + (size_t)m0 * K;
    const __half* Bg = B + (size_t)n0 * K;

    float acc[4][4][4];
    #pragma unroll
    for (int i = 0; i < 4; i++)
        #pragma unroll
        for (int j = 0; j < 4; j++)
            #pragma unroll
            for (int l = 0; l < 4; l++) acc[i][j][l] = 0.f;

    #define GLOAD(kt, s) do {                                                 \
        uint32_t ab = S + (s) * GSM_TILE;                                     \
        uint32_t bb = S + 2 * GSM_TILE + (s) * GSM_TILE;                      \
        _Pragma("unroll")                                                     \
        for (int i = 0; i < 4; i++) {                                         \
            int idx = tid + i * 256;                                          \
            int r = idx >> 3, c = idx & 7;                                    \
            cp16s(ab + r * 144 + c * 16, Ag + (size_t)r * K + (kt) + c * 8);  \
            cp16s(bb + r * 144 + c * 16, Bg + (size_t)r * K + (kt) + c * 8);  \
        }                                                                     \
        cp_commit();                                                          \
    } while (0)

    GLOAD(0, 0);
    cp_wait0();
    __syncthreads();

    int s = 0;
    for (int kt = 0; kt < K; kt += 64) {
        bool more = (kt + 64 < K);
        if (more) GLOAD(kt + 64, s ^ 1);
        uint32_t ab = S + s * GSM_TILE;
        uint32_t bb = S + 2 * GSM_TILE + s * GSM_TILE;
        #pragma unroll
        for (int ks = 0; ks < 4; ks++) {
            uint32_t af[4][4], bf[2][4];
            #pragma unroll
            for (int mt = 0; mt < 4; mt++)
                ldsm4(af[mt], ab + (wm * 64 + mt * 16 + (lane & 15)) * 144
                              + ks * 32 + (lane >> 4) * 16);
            #pragma unroll
            for (int g = 0; g < 2; g++)
                ldsm4(bf[g], bb + (wn * 32 + g * 16 + ((lane >> 4) << 3) + (lane & 7)) * 144
                             + ks * 32 + ((lane >> 3) & 1) * 16);
            #pragma unroll
            for (int mt = 0; mt < 4; mt++)
                #pragma unroll
                for (int nt = 0; nt < 4; nt++)
                    mma_f16(acc[mt][nt], af[mt],
                            bf[nt >> 1][(nt & 1) * 2], bf[nt >> 1][(nt & 1) * 2 + 1]);
        }
        if (more) cp_wait0();
        __syncthreads();
        s ^= 1;
    }

    #pragma unroll
    for (int mt = 0; mt < 4; mt++) {
        #pragma unroll
        for (int nt = 0; nt < 4; nt++) {
            int r0 = m0 + wm * 64 + mt * 16 + gid;
            int c  = c0 + wn * 32 + nt * 8 + tg * 2;
            float2 v0 = make_float2(acc[mt][nt][0], acc[mt][nt][1]);
            float2 v1 = make_float2(acc[mt][nt][2], acc[mt][nt][3]);
            if (RES) {
                float2 a0 = *(const float2*)(R + (size_t)r0 * Nc + c);
                float2 a1 = *(const float2*)(R + (size_t)(r0 + 8) * Nc + c);
                v0.x += a0.x; v0.y += a0.y; v1.x += a1.x; v1.y += a1.y;
            }
            if (RELU) {
                v0.x = fmaxf(v0.x, 0.f); v0.y = fmaxf(v0.y, 0.f);
                v1.x = fmaxf(v1.x, 0.f); v1.y = fmaxf(v1.y, 0.f);
            }
            if (HOUT) {
                __half* C = (__half*)Csel;
                *(__half2*)(C + (size_t)r0 * Nc + c)       = __floats2half2_rn(v0.x, v0.y);
                *(__half2*)(C + (size_t)(r0 + 8) * Nc + c) = __floats2half2_rn(v1.x, v1.y);
            } else {
                float* C = (float*)Csel;
                *(float2*)(C + (size_t)r0 * Nc + c) = v0;
                *(float2*)(C + (size_t)(r0 + 8) * Nc + c) = v1;
            }
        }
    }
    #undef GLOAD
}

// ---------------- FA2 flash: register P, warp-local softmax ---------------
// 64-key-half processing halves the live register set -> 2 CTAs/SM.
#define F2_Q   0
#define F2_KV0 18432
#define F2_STG 36864
#define FL_SMEM (18432 + 2 * 36864)

template<bool SELF>
__global__ void __launch_bounds__(256, 2)
flash_h(const __half* __restrict__ Qp, int qstride,
        const __half* __restrict__ Kp, int kstride,
        const __half* __restrict__ Vp, int vstride,
        const float* __restrict__ relb, const int* __restrict__ mask,
        __half* __restrict__ O) {
    extern __shared__ char smc[];
    uint32_t S = (uint32_t)__cvta_generic_to_shared(smc);
    int tid = threadIdx.x;
    int warp = tid >> 5, lane = tid & 31;
    int gid = lane >> 2, tg = lane & 3;
    int qt = SELF ? (gridDim.x - 1 - blockIdx.x) : blockIdx.x;
    int q0 = qt * 128;
    int bh = blockIdx.y;
    int b = bh >> 4, h = bh & 15;

    const __half* Qg = Qp + (size_t)(b * LSEQ + q0) * qstride + h * DKV;
    const __half* Kg = Kp + (size_t)(b * LSEQ) * kstride + h * DKV;
    const __half* Vg = Vp + (size_t)(b * LSEQ) * vstride + h * DKV;
    const int* maskb = mask + b * LSEQ;

    #define KVLOAD(it, st) do {                                               \
        uint32_t kb = S + F2_KV0 + (st) * F2_STG;                             \
        uint32_t vb = kb + 18432;                                             \
        int kk0 = (it) * 128;                                                 \
        _Pragma("unroll")                                                     \
        for (int i = 0; i < 4; i++) {                                         \
            int idx = tid + i * 256;                                          \
            int r = idx >> 3, c = idx & 7;                                    \
            cp16s(kb + r * 144 + c * 16, Kg + (size_t)(kk0 + r) * kstride + c * 8); \
            cp16s(vb + r * 144 + c * 16, Vg + (size_t)(kk0 + r) * vstride + c * 8); \
        }                                                                     \
        cp_commit();                                                          \
    } while (0)

    #pragma unroll
    for (int i = 0; i < 4; i++) {
        int idx = tid + i * 256;
        int r = idx >> 3, c = idx & 7;
        cp16s(S + F2_Q + r * 144 + c * 16, Qg + (size_t)r * qstride + c * 8);
    }
    KVLOAD(0, 0);

    float oacc[8][4];
    #pragma unroll
    for (int i = 0; i < 8; i++)
        #pragma unroll
        for (int l = 0; l < 4; l++) oacc[i][l] = 0.f;
    float m0 = -1e30f, m1 = -1e30f, l0 = 0.f, l1 = 0.f;

    const int niter = SELF ? (qt + 1) : (LSEQ / 128);
    const int qi0 = q0 + warp * 16 + gid;
    const int qi1 = qi0 + 8;

    cp_wait0();
    __syncthreads();

    int s = 0;
    for (int it = 0; it < niter; it++) {
        bool more = (it + 1 < niter);
        if (more) KVLOAD(it + 1, s ^ 1);
        uint32_t Kb = S + F2_KV0 + s * F2_STG;
        uint32_t Vb = Kb + 18432;

        // process the 128-key tile as two 64-key halves (register economy)
        #pragma unroll
        for (int c2 = 0; c2 < 2; c2++) {
            int kh0 = it * 128 + c2 * 64;

            // ---- QK^T: m16 x n64 x k64 per warp ----
            float sacc[8][4];
            #pragma unroll
            for (int j = 0; j < 8; j++)
                #pragma unroll
                for (int l = 0; l < 4; l++) sacc[j][l] = 0.f;

            #pragma unroll
            for (int ks = 0; ks < 4; ks++) {
                uint32_t af[4];
                ldsm4(af, S + F2_Q + (warp * 16 + (lane & 15)) * 144
                          + ks * 32 + (lane >> 4) * 16);
                #pragma unroll
                for (int g = 0; g < 4; g++) {
                    uint32_t bf[4];
                    ldsm4(bf, Kb + (c2 * 64 + g * 16 + ((lane >> 4) << 3) + (lane & 7)) * 144
                              + ks * 32 + ((lane >> 3) & 1) * 16);
                    mma_f16(sacc[2 * g],     af, bf[0], bf[1]);
                    mma_f16(sacc[2 * g + 1], af, bf[2], bf[3]);
                }
            }

            // ---- bias + mask ----
            #pragma unroll
            for (int j = 0; j < 8; j++) {
                int c = kh0 + j * 8 + tg * 2;
                bool mk0 = maskb[c] > 0;
                bool mk1 = maskb[c + 1] > 0;
                if (SELF) {
                    int d00 = qi0 - c, d01 = d00 - 1;
                    int d10 = qi1 - c, d11 = d10 - 1;
                    sacc[j][0] += relb[g_bucket[d00 > 0 ? d00 : 0] * HEADS + h];
                    sacc[j][1] += relb[g_bucket[d01 > 0 ? d01 : 0] * HEADS + h];
                    sacc[j][2] += relb[g_bucket[d10 > 0 ? d10 : 0] * HEADS + h];
                    sacc[j][3] += relb[g_bucket[d11 > 0 ? d11 : 0] * HEADS + h];
                    if (!((c     <= qi0) && mk0)) sacc[j][0] += NEGINF;
                    if (!((c + 1 <= qi0) && mk1)) sacc[j][1] += NEGINF;
                    if (!((c     <= qi1) && mk0)) sacc[j][2] += NEGINF;
                    if (!((c + 1 <= qi1) && mk1)) sacc[j][3] += NEGINF;
                } else {
                    if (!mk0) { sacc[j][0] += NEGINF; sacc[j][2] += NEGINF; }
                    if (!mk1) { sacc[j][1] += NEGINF; sacc[j][3] += NEGINF; }
                }
            }

            // ---- warp-local online softmax ----
            float mt0 = -1e30f, mt1 = -1e30f;
            #pragma unroll
            for (int j = 0; j < 8; j++) {
                mt0 = fmaxf(mt0, fmaxf(sacc[j][0], sacc[j][1]));
                mt1 = fmaxf(mt1, fmaxf(sacc[j][2], sacc[j][3]));
            }
            mt0 = fmaxf(mt0, __shfl_xor_sync(0xffffffffu, mt0, 1));
            mt0 = fmaxf(mt0, __shfl_xor_sync(0xffffffffu, mt0, 2));
            mt1 = fmaxf(mt1, __shfl_xor_sync(0xffffffffu, mt1, 1));
            mt1 = fmaxf(mt1, __shfl_xor_sync(0xffffffffu, mt1, 2));
            float mn0 = fmaxf(m0, mt0), mn1 = fmaxf(m1, mt1);
            float rs0 = __expf(m0 - mn0), rs1 = __expf(m1 - mn1);
            float s0 = 0.f, s1 = 0.f;
            #pragma unroll
            for (int j = 0; j < 8; j++) {
                float e0 = __expf(sacc[j][0] - mn0);
                float e1 = __expf(sacc[j][1] - mn0);
                float e2 = __expf(sacc[j][2] - mn1);
                float e3 = __expf(sacc[j][3] - mn1);
                sacc[j][0] = e0; sacc[j][1] = e1; sacc[j][2] = e2; sacc[j][3] = e3;
                s0 += e0 + e1;
                s1 += e2 + e3;
            }
            s0 += __shfl_xor_sync(0xffffffffu, s0, 1);
            s0 += __shfl_xor_sync(0xffffffffu, s0, 2);
            s1 += __shfl_xor_sync(0xffffffffu, s1, 1);
            s1 += __shfl_xor_sync(0xffffffffu, s1, 2);
            l0 = l0 * rs0 + s0;
            l1 = l1 * rs1 + s1;
            m0 = mn0; m1 = mn1;
            #pragma unroll
            for (int nt = 0; nt < 8; nt++) {
                oacc[nt][0] *= rs0; oacc[nt][1] *= rs0;
                oacc[nt][2] *= rs1; oacc[nt][3] *= rs1;
            }

            // ---- pack P (C-frag -> A-frag identity), then P @ V ----
            uint32_t ph[4][4];
            #pragma unroll
            for (int t = 0; t < 4; t++) {
                ph[t][0] = packh2(sacc[2 * t][0],     sacc[2 * t][1]);
                ph[t][1] = packh2(sacc[2 * t][2],     sacc[2 * t][3]);
                ph[t][2] = packh2(sacc[2 * t + 1][0], sacc[2 * t + 1][1]);
                ph[t][3] = packh2(sacc[2 * t + 1][2], sacc[2 * t + 1][3]);
            }
            #pragma unroll
            for (int t = 0; t < 4; t++) {
                #pragma unroll
                for (int g = 0; g < 4; g++) {
                    uint32_t bf[4];
                    ldsm4t(bf, Vb + (c2 * 64 + t * 16 + ((lane >> 3) & 1) * 8 + (lane & 7)) * 144
                               + g * 32 + (lane >> 4) * 16);
                    mma_f16(oacc[2 * g],     ph[t], bf[0], bf[1]);
                    mma_f16(oacc[2 * g + 1], ph[t], bf[2], bf[3]);
                }
            }
        }

        if (more) cp_wait0();
        __syncthreads();
        s ^= 1;
    }

    float inv0 = 1.0f / l0;
    float inv1 = 1.0f / l1;
    size_t row0 = (size_t)(b * LSEQ + qi0);
    size_t row1 = (size_t)(b * LSEQ + qi1);
    #pragma unroll
    for (int nt = 0; nt < 8; nt++) {
        int col = h * DKV + nt * 8 + tg * 2;
        *(__half2*)(O + row0 * DMODEL + col)
            = __floats2half2_rn(oacc[nt][0] * inv0, oacc[nt][1] * inv0);
        *(__half2*)(O + row1 * DMODEL + col)
            = __floats2half2_rn(oacc[nt][2] * inv1, oacc[nt][3] * inv1);
    }
    #undef KVLOAD
}

// ---------------- Orchestration -------------------------------------------
extern "C" void kernel_launch(void* const* d_in, const int* in_sizes, int n_in,
                              void* d_out, int out_size) {
    const float* enc    = (const float*)d_in[0];
    const float* hid    = (const float*)d_in[1];
    const float* ln1_w  = (const float*)d_in[2];
    const float* sa_q   = (const float*)d_in[3];
    const float* sa_k   = (const float*)d_in[4];
    const float* sa_v   = (const float*)d_in[5];
    const float* sa_o   = (const float*)d_in[6];
    const float* relb   = (const float*)d_in[7];
    const float* ln2_w  = (const float*)d_in[8];
    const float* ca_q   = (const float*)d_in[9];
    const float* ca_k   = (const float*)d_in[10];
    const float* ca_v   = (const float*)d_in[11];
    const float* ca_o   = (const float*)d_in[12];
    const float* ln3_w  = (const float*)d_in[13];
    const float* wi     = (const float*)d_in[14];
    const float* wo     = (const float*)d_in[15];
    const float* flnw   = (const float*)d_in[16];
    const int*   emask  = (const int*)d_in[17];
    const int*   dmask  = (const int*)d_in[18];
    float* out = (float*)d_out;

    __half *xn, *qkv, *kvx, *att, *encr, *ffn, *wh;
    float *h;
    cudaGetSymbolAddress((void**)&xn,   g_xnorm);
    cudaGetSymbolAddress((void**)&qkv,  g_qkv);
    cudaGetSymbolAddress((void**)&kvx,  g_kvx);
    cudaGetSymbolAddress((void**)&att,  g_att);
    cudaGetSymbolAddress((void**)&h,    g_h);
    cudaGetSymbolAddress((void**)&encr, g_encr);
    cudaGetSymbolAddress((void**)&ffn,  g_ffn);
    cudaGetSymbolAddress((void**)&wh,   g_wh);

    cudaFuncSetAttribute(hgemm<false,false,true,false>, cudaFuncAttributeMaxDynamicSharedMemorySize, GEMM_SMEM);
    cudaFuncSetAttribute(hgemm<false,false,true,true>,  cudaFuncAttributeMaxDynamicSharedMemorySize, GEMM_SMEM);
    cudaFuncSetAttribute(hgemm<false,true,false,false>, cudaFuncAttributeMaxDynamicSharedMemorySize, GEMM_SMEM);
    cudaFuncSetAttribute(hgemm<true,false,true,false>,  cudaFuncAttributeMaxDynamicSharedMemorySize, GEMM_SMEM);
    cudaFuncSetAttribute(flash_h<true>,  cudaFuncAttributeMaxDynamicSharedMemorySize, FL_SMEM);
    cudaFuncSetAttribute(flash_h<false>, cudaFuncAttributeMaxDynamicSharedMemorySize, FL_SMEM);

    dim3 tb2(256);
    dim3 gDD(8, 32);
    dim3 gQKV(24, 32);
    dim3 gCROSS(24, 32);
    dim3 gDF(32, 32);
    dim3 gFlash(LSEQ / 128, BATCH * HEADS);

    // ---- launch 1: 8 DD transposes + bucket table, batched ----
    TP8 tp;
    tp.src[0] = sa_q; tp.dst_off[0] = WH_QKV;
    tp.src[1] = sa_k; tp.dst_off[1] = WH_QKV + 1048576;
    tp.src[2] = sa_v; tp.dst_off[2] = WH_QKV + 2 * 1048576;
    tp.src[3] = ca_q; tp.dst_off[3] = WH_CAQ;
    tp.src[4] = ca_k; tp.dst_off[4] = WH_KVX;
    tp.src[5] = ca_v; tp.dst_off[5] = WH_KVX + 1048576;
    tp.src[6] = sa_o; tp.dst_off[6] = WH_SAO;
    tp.src[7] = ca_o; tp.dst_off[7] = WH_CAO;
    transpose_batch<<<dim3(16, 16, 9), tb2>>>(tp, wh);
    prep_misc<<<dim3(1024, 1, 3), tb2>>>(wi, wo, enc, wh, encr);
    rms_kernel<true><<<TOK, 256>>>(hid, ln1_w, xn);

    // ---- fused QKV GEMM ----
    hgemm<false,false,true,false><<<gQKV, 256, GEMM_SMEM>>>(xn, wh + WH_QKV, nullptr, qkv, TOK, 3072, DMODEL);

    // ---- Self-attention ----
    flash_h<true><<<gFlash, 256, FL_SMEM>>>(qkv, 3072, qkv + 1024, 3072, qkv + 2048, 3072,
                                            relb, dmask, att);
    hgemm<false,true,false,false><<<gDD, 256, GEMM_SMEM>>>(att, wh + WH_SAO, hid, h, TOK, DMODEL, DMODEL);

    // ---- Cross-attention (merged Q + KV projection) ----
    rms_kernel<true><<<TOK, 256>>>(h, ln2_w, xn);
    hgemm<false,false,true,true><<<gCROSS, 256, GEMM_SMEM>>>(xn, wh + WH_CAQ, nullptr, qkv,
                                                             TOK, 3072, DMODEL, encr, kvx);
    flash_h<false><<<gFlash, 256, FL_SMEM>>>(qkv, 1024, kvx, 2048, kvx + 1024, 2048,
                                             nullptr, emask, att);
    hgemm<false,true,false,false><<<gDD, 256, GEMM_SMEM>>>(att, wh + WH_CAO, h, h, TOK, DMODEL, DMODEL);

    // ---- FFN ----
    rms_kernel<true><<<TOK, 256>>>(h, ln3_w, xn);
    hgemm<true,false,true,false><<<gDF, 256, GEMM_SMEM>>>(xn, wh + WH_WI, nullptr, ffn, TOK, DFF, DMODEL);
    hgemm<false,true,false,false><<<gDD, 256, GEMM_SMEM>>>(ffn, wh + WH_WO, h, h, TOK, DMODEL, DFF);

    // ---- Final norm ----
    rms_kernel<false><<<TOK, 256>>>(h, flnw, out);
}

// round 17
// speedup vs baseline: 1.1894x; 1.0093x over previous
#include <cuda_runtime.h>
#include <cuda_fp16.h>
#include <math.h>
#include <stdint.h>

// ---------------- Problem constants ----------------
#define BATCH 4
#define LSEQ  1024
#define DMODEL 1024
#define HEADS 16
#define DKV   64
#define DFF   4096
#define TOK   (BATCH * LSEQ)
#define NBUCK 32
#define NEGINF (-1e9f)

// ---------------- Scratch ----------------
__device__ __half g_xnorm[TOK * DMODEL];
__device__ __half g_qkv[TOK * 3072];
__device__ __half g_kvx[TOK * 2048];
__device__ __half g_att[TOK * DMODEL];
__device__ float  g_h[TOK * DMODEL];
__device__ __half g_encr[TOK * DMODEL];
__device__ __half g_ffn[TOK * DFF];
__device__ __half g_wh[16 * 1024 * 1024];   // fp16 weights, transposed [N][K]
__device__ int    g_bucket[LSEQ];

#define WH_QKV 0                        // [3072][1024]
#define WH_CAQ (3 * 1048576)            // [1024][1024]  (contiguous with KVX -> [3072][1024])
#define WH_KVX (4 * 1048576)            // [2048][1024]
#define WH_SAO (6 * 1048576)
#define WH_CAO (7 * 1048576)
#define WH_WI  (8 * 1048576)            // [4096][1024]
#define WH_WO  (12 * 1048576)           // [1024][4096]

// ---------------- helpers ----------------
#define GDEP_WAIT()   asm volatile("griddepcontrol.wait;" ::: "memory")
#define GDEP_LAUNCH() asm volatile("griddepcontrol.launch_dependents;")

__device__ __forceinline__ void mma_f16(float (&d)[4], const uint32_t (&a)[4],
                                        uint32_t b0, uint32_t b1) {
    asm volatile(
        "mma.sync.aligned.m16n8k16.row.col.f32.f16.f16.f32 "
        "{%0,%1,%2,%3}, {%4,%5,%6,%7}, {%8,%9}, {%0,%1,%2,%3};"
        : "+f"(d[0]), "+f"(d[1]), "+f"(d[2]), "+f"(d[3])
        : "r"(a[0]), "r"(a[1]), "r"(a[2]), "r"(a[3]), "r"(b0), "r"(b1));
}
__device__ __forceinline__ void ldsm4(uint32_t (&r)[4], uint32_t addr) {
    asm volatile("ldmatrix.sync.aligned.m8n8.x4.shared.b16 {%0,%1,%2,%3}, [%4];"
                 : "=r"(r[0]), "=r"(r[1]), "=r"(r[2]), "=r"(r[3]) : "r"(addr));
}
__device__ __forceinline__ void ldsm4t(uint32_t (&r)[4], uint32_t addr) {
    asm volatile("ldmatrix.sync.aligned.m8n8.x4.trans.shared.b16 {%0,%1,%2,%3}, [%4];"
                 : "=r"(r[0]), "=r"(r[1]), "=r"(r[2]), "=r"(r[3]) : "r"(addr));
}
__device__ __forceinline__ void cp16s(uint32_t dst, const void* src) {
    asm volatile("cp.async.cg.shared.global [%0], [%1], 16;" :: "r"(dst), "l"(src));
}
__device__ __forceinline__ void cp_commit() { asm volatile("cp.async.commit_group;"); }
__device__ __forceinline__ void cp_wait0()  { asm volatile("cp.async.wait_group 0;" ::: "memory"); }
__device__ __forceinline__ uint32_t packh2(float a, float b) {
    __half2 t = __floats2half2_rn(a, b);
    return *(uint32_t*)&t;
}

// ---------------- prep: batched transpose + bucket table (z==8) -----------
struct TP8 {
    const float* src[8];
    unsigned dst_off[8];
};

__global__ void __launch_bounds__(256)
transpose_batch(TP8 args, __half* __restrict__ whbase) {
    GDEP_WAIT();
    int z = blockIdx.z;
    if (z == 8) {
        if (blockIdx.x == 0 && blockIdx.y == 0) {
            #pragma unroll
            for (int i = 0; i < 4; i++) {
                int n = threadIdx.x + i * 256;
                int b;
                if (n < 16) {
                    b = n;
                } else {
                    float nf = (float)n;
                    int vl = 16 + (int)(logf(nf / 16.0f) / logf(8.0f) * 16.0f);
                    b = vl < (NBUCK - 1) ? vl : (NBUCK - 1);
                }
                g_bucket[n] = b;
            }
        }
        GDEP_LAUNCH();
        return;
    }
    __shared__ float t[64][65];
    const float* W = args.src[z];
    __half* Wt = whbase + args.dst_off[z];
    int n0 = blockIdx.x * 64, k0 = blockIdx.y * 64;
    int tid = threadIdx.x;
    int row = tid >> 2;
    int qc  = tid & 3;
    #pragma unroll
    for (int j = 0; j < 4; j++) {
        float4 v = *(const float4*)(W + (size_t)(k0 + row) * 1024 + n0 + qc * 16 + j * 4);
        t[row][qc * 16 + j * 4 + 0] = v.x;
        t[row][qc * 16 + j * 4 + 1] = v.y;
        t[row][qc * 16 + j * 4 + 2] = v.z;
        t[row][qc * 16 + j * 4 + 3] = v.w;
    }
    __syncthreads();
    GDEP_LAUNCH();
    #pragma unroll
    for (int j = 0; j < 2; j++) {
        __half hbuf[8];
        #pragma unroll
        for (int e = 0; e < 8; e++)
            hbuf[e] = __float2half(t[qc * 16 + j * 8 + e][row]);
        *(uint4*)(Wt + (size_t)(n0 + row) * 1024 + k0 + qc * 16 + j * 8) = *(uint4*)hbuf;
    }
}

// ---------------- prep2: wi transpose (z=0), wo transpose (z=1), conv (z=2)
__global__ void __launch_bounds__(256)
prep_misc(const float* __restrict__ wi, const float* __restrict__ wo,
          const float* __restrict__ enc, __half* __restrict__ whbase,
          __half* __restrict__ encr) {
    GDEP_WAIT();
    int z = blockIdx.z;
    int bx = blockIdx.x;
    int tid = threadIdx.x;
    if (z == 2) {
        GDEP_LAUNCH();
        #pragma unroll
        for (int j = 0; j < 4; j++) {
            int i = bx * 1024 + j * 256 + tid;
            float4 v = ((const float4*)enc)[i];
            __half2* d = (__half2*)(encr + (size_t)i * 4);
            d[0] = __floats2half2_rn(v.x, v.y);
            d[1] = __floats2half2_rn(v.z, v.w);
        }
        return;
    }
    const float* W;
    __half* Wt;
    int K, N, n0, k0;
    if (z == 0) {
        W = wi; Wt = whbase + WH_WI; K = DMODEL; N = DFF;
        n0 = (bx & 63) * 64; k0 = (bx >> 6) * 64;
    } else {
        W = wo; Wt = whbase + WH_WO; K = DFF; N = DMODEL;
        n0 = (bx & 15) * 64; k0 = (bx >> 4) * 64;
    }
    __shared__ float t[64][65];
    int row = tid >> 2;
    int qc  = tid & 3;
    #pragma unroll
    for (int j = 0; j < 4; j++) {
        float4 v = *(const float4*)(W + (size_t)(k0 + row) * N + n0 + qc * 16 + j * 4);
        t[row][qc * 16 + j * 4 + 0] = v.x;
        t[row][qc * 16 + j * 4 + 1] = v.y;
        t[row][qc * 16 + j * 4 + 2] = v.z;
        t[row][qc * 16 + j * 4 + 3] = v.w;
    }
    __syncthreads();
    GDEP_LAUNCH();
    #pragma unroll
    for (int j = 0; j < 2; j++) {
        __half hbuf[8];
        #pragma unroll
        for (int e = 0; e < 8; e++)
            hbuf[e] = __float2half(t[qc * 16 + j * 8 + e][row]);
        *(uint4*)(Wt + (size_t)(n0 + row) * K + k0 + qc * 16 + j * 8) = *(uint4*)hbuf;
    }
}

// ---------------- RMS norm (vectorized) ----------------
template<bool HOUT>
__global__ void rms_kernel(const float* __restrict__ x,
                           const float* __restrict__ w, void* __restrict__ yv) {
    GDEP_WAIT();
    int row = blockIdx.x;
    int tid = threadIdx.x;
    float4 v = ((const float4*)(x + (size_t)row * DMODEL))[tid];
    float s = v.x * v.x + v.y * v.y + v.z * v.z + v.w * v.w;
    __shared__ float red[8];
    #pragma unroll
    for (int o = 16; o; o >>= 1) s += __shfl_xor_sync(0xffffffffu, s, o);
    if ((tid & 31) == 0) red[tid >> 5] = s;
    __syncthreads();
    if (tid < 8) {
        float t = red[tid];
        #pragma unroll
        for (int o = 4; o; o >>= 1) t += __shfl_xor_sync(0xffu, t, o);
        if (tid == 0) red[0] = rsqrtf(t * (1.0f / DMODEL) + 1e-6f);
    }
    __syncthreads();
    GDEP_LAUNCH();
    float inv = red[0];
    float4 wv = ((const float4*)w)[tid];
    float a = v.x * inv * wv.x, b = v.y * inv * wv.y;
    float c = v.z * inv * wv.z, d = v.w * inv * wv.w;
    if (HOUT) {
        __half2* yr = (__half2*)yv + (size_t)row * (DMODEL / 2);
        yr[tid * 2]     = __floats2half2_rn(a, b);
        yr[tid * 2 + 1] = __floats2half2_rn(c, d);
    } else {
        ((float4*)yv)[(size_t)row * (DMODEL / 4) + tid] = make_float4(a, b, c, d);
    }
}

// ---------------- fp16 GEMM (2-stage, 8 warps 2Mx4N) + PDL -----------------
// Prologue: B (weights, predecessor-independent) loaded BEFORE griddep wait.
#define GSM_TILE 18432
#define GEMM_SMEM (4 * GSM_TILE)

template<bool RELU, bool RES, bool HOUT, bool DUAL>
__global__ void __launch_bounds__(256, 2)
hgemm(const __half* __restrict__ A, const __half* __restrict__ B,
      const float* __restrict__ R, void* __restrict__ Cv,
      int M, int N, int K,
      const __half* A2, void* Cv2) {
    extern __shared__ char smc[];
    uint32_t S = (uint32_t)__cvta_generic_to_shared(smc);
    const int tid = threadIdx.x;
    const int warp = tid >> 5, lane = tid & 31;
    const int gid = lane >> 2, tg = lane & 3;
    const int wm = warp & 1, wn = warp >> 1;
    const int m0 = blockIdx.y * 128;
    int n0 = blockIdx.x * 128;
    const __half* Asel = A;
    void* Csel = Cv;
    int Nc = N, c0 = n0;
    if (DUAL && n0 >= 1024) {
        Asel = A2; Csel = Cv2; Nc = 2048; c0 = n0 - 1024;
    } else if (DUAL) {
        Nc = 1024;
    }
    const __half* Ag = Asel + (size_t)m0 * K;
    const __half* Bg = B + (size_t)n0 * K;

    float acc[4][4][4];
    #pragma unroll
    for (int i = 0; i < 4; i++)
        #pragma unroll
        for (int j = 0; j < 4; j++)
            #pragma unroll
            for (int l = 0; l < 4; l++) acc[i][j][l] = 0.f;

    // ---- prologue: B tile stage 0 (independent) before dependency wait ----
    {
        uint32_t bb = S + 2 * GSM_TILE;
        #pragma unroll
        for (int i = 0; i < 4; i++) {
            int idx = tid + i * 256;
            int r = idx >> 3, c = idx & 7;
            cp16s(bb + r * 144 + c * 16, Bg + (size_t)r * K + c * 8);
        }
        cp_commit();
    }
    GDEP_WAIT();
    {
        uint32_t ab = S;
        #pragma unroll
        for (int i = 0; i < 4; i++) {
            int idx = tid + i * 256;
            int r = idx >> 3, c = idx & 7;
            cp16s(ab + r * 144 + c * 16, Ag + (size_t)r * K + c * 8);
        }
        cp_commit();
    }

    #define GLOAD(kt, s) do {                                                 \
        uint32_t ab = S + (s) * GSM_TILE;                                     \
        uint32_t bb = S + 2 * GSM_TILE + (s) * GSM_TILE;                      \
        _Pragma("unroll")                                                     \
        for (int i = 0; i < 4; i++) {                                         \
            int idx = tid + i * 256;                                          \
            int r = idx >> 3, c = idx & 7;                                    \
            cp16s(ab + r * 144 + c * 16, Ag + (size_t)r * K + (kt) + c * 8);  \
            cp16s(bb + r * 144 + c * 16, Bg + (size_t)r * K + (kt) + c * 8);  \
        }                                                                     \
        cp_commit();                                                          \
    } while (0)

    cp_wait0();
    __syncthreads();

    int s = 0;
    for (int kt = 0; kt < K; kt += 64) {
        bool more = (kt + 64 < K);
        if (more) GLOAD(kt + 64, s ^ 1);
        uint32_t ab = S + s * GSM_TILE;
        uint32_t bb = S + 2 * GSM_TILE + s * GSM_TILE;
        #pragma unroll
        for (int ks = 0; ks < 4; ks++) {
            uint32_t af[4][4], bf[2][4];
            #pragma unroll
            for (int mt = 0; mt < 4; mt++)
                ldsm4(af[mt], ab + (wm * 64 + mt * 16 + (lane & 15)) * 144
                              + ks * 32 + (lane >> 4) * 16);
            #pragma unroll
            for (int g = 0; g < 2; g++)
                ldsm4(bf[g], bb + (wn * 32 + g * 16 + ((lane >> 4) << 3) + (lane & 7)) * 144
                             + ks * 32 + ((lane >> 3) & 1) * 16);
            #pragma unroll
            for (int mt = 0; mt < 4; mt++)
                #pragma unroll
                for (int nt = 0; nt < 4; nt++)
                    mma_f16(acc[mt][nt], af[mt],
                            bf[nt >> 1][(nt & 1) * 2], bf[nt >> 1][(nt & 1) * 2 + 1]);
        }
        if (more) cp_wait0();
        __syncthreads();
        s ^= 1;
    }

    GDEP_LAUNCH();

    #pragma unroll
    for (int mt = 0; mt < 4; mt++) {
        #pragma unroll
        for (int nt = 0; nt < 4; nt++) {
            int r0 = m0 + wm * 64 + mt * 16 + gid;
            int c  = c0 + wn * 32 + nt * 8 + tg * 2;
            float2 v0 = make_float2(acc[mt][nt][0], acc[mt][nt][1]);
            float2 v1 = make_float2(acc[mt][nt][2], acc[mt][nt][3]);
            if (RES) {
                float2 a0 = *(const float2*)(R + (size_t)r0 * Nc + c);
                float2 a1 = *(const float2*)(R + (size_t)(r0 + 8) * Nc + c);
                v0.x += a0.x; v0.y += a0.y; v1.x += a1.x; v1.y += a1.y;
            }
            if (RELU) {
                v0.x = fmaxf(v0.x, 0.f); v0.y = fmaxf(v0.y, 0.f);
                v1.x = fmaxf(v1.x, 0.f); v1.y = fmaxf(v1.y, 0.f);
            }
            if (HOUT) {
                __half* C = (__half*)Csel;
                *(__half2*)(C + (size_t)r0 * Nc + c)       = __floats2half2_rn(v0.x, v0.y);
                *(__half2*)(C + (size_t)(r0 + 8) * Nc + c) = __floats2half2_rn(v1.x, v1.y);
            } else {
                float* C = (float*)Csel;
                *(float2*)(C + (size_t)r0 * Nc + c) = v0;
                *(float2*)(C + (size_t)(r0 + 8) * Nc + c) = v1;
            }
        }
    }
    #undef GLOAD
}

// ---------------- FA2 flash: register P, warp-local softmax ---------------
#define F2_Q   0
#define F2_KV0 18432
#define F2_STG 36864
#define FL_SMEM (18432 + 2 * 36864)

template<bool SELF>
__global__ void __launch_bounds__(256, 2)
flash_h(const __half* __restrict__ Qp, int qstride,
        const __half* __restrict__ Kp, int kstride,
        const __half* __restrict__ Vp, int vstride,
        const float* __restrict__ relb, const int* __restrict__ mask,
        __half* __restrict__ O) {
    GDEP_WAIT();
    extern __shared__ char smc[];
    uint32_t S = (uint32_t)__cvta_generic_to_shared(smc);
    int tid = threadIdx.x;
    int warp = tid >> 5, lane = tid & 31;
    int gid = lane >> 2, tg = lane & 3;
    int qt = SELF ? (gridDim.x - 1 - blockIdx.x) : blockIdx.x;
    int q0 = qt * 128;
    int bh = blockIdx.y;
    int b = bh >> 4, h = bh & 15;

    const __half* Qg = Qp + (size_t)(b * LSEQ + q0) * qstride + h * DKV;
    const __half* Kg = Kp + (size_t)(b * LSEQ) * kstride + h * DKV;
    const __half* Vg = Vp + (size_t)(b * LSEQ) * vstride + h * DKV;
    const int* maskb = mask + b * LSEQ;

    #define KVLOAD(it, st) do {                                               \
        uint32_t kb = S + F2_KV0 + (st) * F2_STG;                             \
        uint32_t vb = kb + 18432;                                             \
        int kk0 = (it) * 128;                                                 \
        _Pragma("unroll")                                                     \
        for (int i = 0; i < 4; i++) {                                         \
            int idx = tid + i * 256;                                          \
            int r = idx >> 3, c = idx & 7;                                    \
            cp16s(kb + r * 144 + c * 16, Kg + (size_t)(kk0 + r) * kstride + c * 8); \
            cp16s(vb + r * 144 + c * 16, Vg + (size_t)(kk0 + r) * vstride + c * 8); \
        }                                                                     \
        cp_commit();                                                          \
    } while (0)

    #pragma unroll
    for (int i = 0; i < 4; i++) {
        int idx = tid + i * 256;
        int r = idx >> 3, c = idx & 7;
        cp16s(S + F2_Q + r * 144 + c * 16, Qg + (size_t)r * qstride + c * 8);
    }
    KVLOAD(0, 0);

    float oacc[8][4];
    #pragma unroll
    for (int i = 0; i < 8; i++)
        #pragma unroll
        for (int l = 0; l < 4; l++) oacc[i][l] = 0.f;
    float m0 = -1e30f, m1 = -1e30f, l0 = 0.f, l1 = 0.f;

    const int niter = SELF ? (qt + 1) : (LSEQ / 128);
    const int qi0 = q0 + warp * 16 + gid;
    const int qi1 = qi0 + 8;

    cp_wait0();
    __syncthreads();

    int s = 0;
    for (int it = 0; it < niter; it++) {
        bool more = (it + 1 < niter);
        if (more) KVLOAD(it + 1, s ^ 1);
        uint32_t Kb = S + F2_KV0 + s * F2_STG;
        uint32_t Vb = Kb + 18432;

        #pragma unroll
        for (int c2 = 0; c2 < 2; c2++) {
            int kh0 = it * 128 + c2 * 64;

            float sacc[8][4];
            #pragma unroll
            for (int j = 0; j < 8; j++)
                #pragma unroll
                for (int l = 0; l < 4; l++) sacc[j][l] = 0.f;

            #pragma unroll
            for (int ks = 0; ks < 4; ks++) {
                uint32_t af[4];
                ldsm4(af, S + F2_Q + (warp * 16 + (lane & 15)) * 144
                          + ks * 32 + (lane >> 4) * 16);
                #pragma unroll
                for (int g = 0; g < 4; g++) {
                    uint32_t bf[4];
                    ldsm4(bf, Kb + (c2 * 64 + g * 16 + ((lane >> 4) << 3) + (lane & 7)) * 144
                              + ks * 32 + ((lane >> 3) & 1) * 16);
                    mma_f16(sacc[2 * g],     af, bf[0], bf[1]);
                    mma_f16(sacc[2 * g + 1], af, bf[2], bf[3]);
                }
            }

            #pragma unroll
            for (int j = 0; j < 8; j++) {
                int c = kh0 + j * 8 + tg * 2;
                bool mk0 = maskb[c] > 0;
                bool mk1 = maskb[c + 1] > 0;
                if (SELF) {
                    int d00 = qi0 - c, d01 = d00 - 1;
                    int d10 = qi1 - c, d11 = d10 - 1;
                    sacc[j][0] += relb[g_bucket[d00 > 0 ? d00 : 0] * HEADS + h];
                    sacc[j][1] += relb[g_bucket[d01 > 0 ? d01 : 0] * HEADS + h];
                    sacc[j][2] += relb[g_bucket[d10 > 0 ? d10 : 0] * HEADS + h];
                    sacc[j][3] += relb[g_bucket[d11 > 0 ? d11 : 0] * HEADS + h];
                    if (!((c     <= qi0) && mk0)) sacc[j][0] += NEGINF;
                    if (!((c + 1 <= qi0) && mk1)) sacc[j][1] += NEGINF;
                    if (!((c     <= qi1) && mk0)) sacc[j][2] += NEGINF;
                    if (!((c + 1 <= qi1) && mk1)) sacc[j][3] += NEGINF;
                } else {
                    if (!mk0) { sacc[j][0] += NEGINF; sacc[j][2] += NEGINF; }
                    if (!mk1) { sacc[j][1] += NEGINF; sacc[j][3] += NEGINF; }
                }
            }

            float mt0 = -1e30f, mt1 = -1e30f;
            #pragma unroll
            for (int j = 0; j < 8; j++) {
                mt0 = fmaxf(mt0, fmaxf(sacc[j][0], sacc[j][1]));
                mt1 = fmaxf(mt1, fmaxf(sacc[j][2], sacc[j][3]));
            }
            mt0 = fmaxf(mt0, __shfl_xor_sync(0xffffffffu, mt0, 1));
            mt0 = fmaxf(mt0, __shfl_xor_sync(0xffffffffu, mt0, 2));
            mt1 = fmaxf(mt1, __shfl_xor_sync(0xffffffffu, mt1, 1));
            mt1 = fmaxf(mt1, __shfl_xor_sync(0xffffffffu, mt1, 2));
            float mn0 = fmaxf(m0, mt0), mn1 = fmaxf(m1, mt1);
            float rs0 = __expf(m0 - mn0), rs1 = __expf(m1 - mn1);
            float s0 = 0.f, s1 = 0.f;
            #pragma unroll
            for (int j = 0; j < 8; j++) {
                float e0 = __expf(sacc[j][0] - mn0);
                float e1 = __expf(sacc[j][1] - mn0);
                float e2 = __expf(sacc[j][2] - mn1);
                float e3 = __expf(sacc[j][3] - mn1);
                sacc[j][0] = e0; sacc[j][1] = e1; sacc[j][2] = e2; sacc[j][3] = e3;
                s0 += e0 + e1;
                s1 += e2 + e3;
            }
            s0 += __shfl_xor_sync(0xffffffffu, s0, 1);
            s0 += __shfl_xor_sync(0xffffffffu, s0, 2);
            s1 += __shfl_xor_sync(0xffffffffu, s1, 1);
            s1 += __shfl_xor_sync(0xffffffffu, s1, 2);
            l0 = l0 * rs0 + s0;
            l1 = l1 * rs1 + s1;
            m0 = mn0; m1 = mn1;
            #pragma unroll
            for (int nt = 0; nt < 8; nt++) {
                oacc[nt][0] *= rs0; oacc[nt][1] *= rs0;
                oacc[nt][2] *= rs1; oacc[nt][3] *= rs1;
            }

            uint32_t ph[4][4];
            #pragma unroll
            for (int t = 0; t < 4; t++) {
                ph[t][0] = packh2(sacc[2 * t][0],     sacc[2 * t][1]);
                ph[t][1] = packh2(sacc[2 * t][2],     sacc[2 * t][3]);
                ph[t][2] = packh2(sacc[2 * t + 1][0], sacc[2 * t + 1][1]);
                ph[t][3] = packh2(sacc[2 * t + 1][2], sacc[2 * t + 1][3]);
            }
            #pragma unroll
            for (int t = 0; t < 4; t++) {
                #pragma unroll
                for (int g = 0; g < 4; g++) {
                    uint32_t bf[4];
                    ldsm4t(bf, Vb + (c2 * 64 + t * 16 + ((lane >> 3) & 1) * 8 + (lane & 7)) * 144
                               + g * 32 + (lane >> 4) * 16);
                    mma_f16(oacc[2 * g],     ph[t], bf[0], bf[1]);
                    mma_f16(oacc[2 * g + 1], ph[t], bf[2], bf[3]);
                }
            }
        }

        if (more) cp_wait0();
        __syncthreads();
        s ^= 1;
    }

    GDEP_LAUNCH();

    float inv0 = 1.0f / l0;
    float inv1 = 1.0f / l1;
    size_t row0 = (size_t)(b * LSEQ + qi0);
    size_t row1 = (size_t)(b * LSEQ + qi1);
    #pragma unroll
    for (int nt = 0; nt < 8; nt++) {
        int col = h * DKV + nt * 8 + tg * 2;
        *(__half2*)(O + row0 * DMODEL + col)
            = __floats2half2_rn(oacc[nt][0] * inv0, oacc[nt][1] * inv0);
        *(__half2*)(O + row1 * DMODEL + col)
            = __floats2half2_rn(oacc[nt][2] * inv1, oacc[nt][3] * inv1);
    }
    #undef KVLOAD
}

// ---------------- Orchestration -------------------------------------------
extern "C" void kernel_launch(void* const* d_in, const int* in_sizes, int n_in,
                              void* d_out, int out_size) {
    const float* enc    = (const float*)d_in[0];
    const float* hid    = (const float*)d_in[1];
    const float* ln1_w  = (const float*)d_in[2];
    const float* sa_q   = (const float*)d_in[3];
    const float* sa_k   = (const float*)d_in[4];
    const float* sa_v   = (const float*)d_in[5];
    const float* sa_o   = (const float*)d_in[6];
    const float* relb   = (const float*)d_in[7];
    const float* ln2_w  = (const float*)d_in[8];
    const float* ca_q   = (const float*)d_in[9];
    const float* ca_k   = (const float*)d_in[10];
    const float* ca_v   = (const float*)d_in[11];
    const float* ca_o   = (const float*)d_in[12];
    const float* ln3_w  = (const float*)d_in[13];
    const float* wi     = (const float*)d_in[14];
    const float* wo     = (const float*)d_in[15];
    const float* flnw   = (const float*)d_in[16];
    const int*   emask  = (const int*)d_in[17];
    const int*   dmask  = (const int*)d_in[18];
    float* out = (float*)d_out;

    __half *xn, *qkv, *kvx, *att, *encr, *ffn, *wh;
    float *h;
    cudaGetSymbolAddress((void**)&xn,   g_xnorm);
    cudaGetSymbolAddress((void**)&qkv,  g_qkv);
    cudaGetSymbolAddress((void**)&kvx,  g_kvx);
    cudaGetSymbolAddress((void**)&att,  g_att);
    cudaGetSymbolAddress((void**)&h,    g_h);
    cudaGetSymbolAddress((void**)&encr, g_encr);
    cudaGetSymbolAddress((void**)&ffn,  g_ffn);
    cudaGetSymbolAddress((void**)&wh,   g_wh);

    cudaFuncSetAttribute(hgemm<false,false,true,false>, cudaFuncAttributeMaxDynamicSharedMemorySize, GEMM_SMEM);
    cudaFuncSetAttribute(hgemm<false,false,true,true>,  cudaFuncAttributeMaxDynamicSharedMemorySize, GEMM_SMEM);
    cudaFuncSetAttribute(hgemm<false,true,false,false>, cudaFuncAttributeMaxDynamicSharedMemorySize, GEMM_SMEM);
    cudaFuncSetAttribute(hgemm<true,false,true,false>,  cudaFuncAttributeMaxDynamicSharedMemorySize, GEMM_SMEM);
    cudaFuncSetAttribute(flash_h<true>,  cudaFuncAttributeMaxDynamicSharedMemorySize, FL_SMEM);
    cudaFuncSetAttribute(flash_h<false>, cudaFuncAttributeMaxDynamicSharedMemorySize, FL_SMEM);

    // PDL launch config (ProgrammaticStreamSerialization on every node)
    cudaLaunchConfig_t cfg = {};
    cudaLaunchAttribute at[1];
    at[0].id = cudaLaunchAttributeProgrammaticStreamSerialization;
    at[0].val.programmaticStreamSerializationAllowed = 1;
    cfg.attrs = at;
    cfg.numAttrs = 1;
    cfg.stream = 0;

    #define LPDL(kern, grid, block, smem, ...) do {                          \
        cfg.gridDim = grid; cfg.blockDim = dim3(block);                      \
        cfg.dynamicSmemBytes = smem;                                         \
        cudaLaunchKernelEx(&cfg, kern, __VA_ARGS__);                         \
    } while (0)

    dim3 gDD(8, 32);
    dim3 gQKV(24, 32);
    dim3 gCROSS(24, 32);
    dim3 gDF(32, 32);
    dim3 gFlash(LSEQ / 128, BATCH * HEADS);

    TP8 tp;
    tp.src[0] = sa_q; tp.dst_off[0] = WH_QKV;
    tp.src[1] = sa_k; tp.dst_off[1] = WH_QKV + 1048576;
    tp.src[2] = sa_v; tp.dst_off[2] = WH_QKV + 2 * 1048576;
    tp.src[3] = ca_q; tp.dst_off[3] = WH_CAQ;
    tp.src[4] = ca_k; tp.dst_off[4] = WH_KVX;
    tp.src[5] = ca_v; tp.dst_off[5] = WH_KVX + 1048576;
    tp.src[6] = sa_o; tp.dst_off[6] = WH_SAO;
    tp.src[7] = ca_o; tp.dst_off[7] = WH_CAO;

    LPDL(transpose_batch, dim3(16, 16, 9), 256, 0, tp, wh);
    LPDL(prep_misc, dim3(1024, 1, 3), 256, 0, wi, wo, enc, wh, encr);
    LPDL(rms_kernel<true>, dim3(TOK), 256, 0, hid, ln1_w, (void*)xn);

    // ---- fused QKV GEMM ----
    LPDL((hgemm<false,false,true,false>), gQKV, 256, GEMM_SMEM,
         (const __half*)xn, (const __half*)(wh + WH_QKV), (const float*)nullptr,
         (void*)qkv, TOK, 3072, DMODEL, (const __half*)nullptr, (void*)nullptr);

    // ---- Self-attention ----
    LPDL(flash_h<true>, gFlash, 256, FL_SMEM,
         (const __half*)qkv, 3072, (const __half*)(qkv + 1024), 3072,
         (const __half*)(qkv + 2048), 3072, relb, dmask, att);
    LPDL((hgemm<false,true,false,false>), gDD, 256, GEMM_SMEM,
         (const __half*)att, (const __half*)(wh + WH_SAO), (const float*)hid,
         (void*)h, TOK, DMODEL, DMODEL, (const __half*)nullptr, (void*)nullptr);

    // ---- Cross-attention (merged Q + KV projection) ----
    LPDL(rms_kernel<true>, dim3(TOK), 256, 0, (const float*)h, ln2_w, (void*)xn);
    LPDL((hgemm<false,false,true,true>), gCROSS, 256, GEMM_SMEM,
         (const __half*)xn, (const __half*)(wh + WH_CAQ), (const float*)nullptr,
         (void*)qkv, TOK, 3072, DMODEL, (const __half*)encr, (void*)kvx);
    LPDL(flash_h<false>, gFlash, 256, FL_SMEM,
         (const __half*)qkv, 1024, (const __half*)kvx, 2048,
         (const __half*)(kvx + 1024), 2048, (const float*)nullptr, emask, att);
    LPDL((hgemm<false,true,false,false>), gDD, 256, GEMM_SMEM,
         (const __half*)att, (const __half*)(wh + WH_CAO), (const float*)h,
         (void*)h, TOK, DMODEL, DMODEL, (const __half*)nullptr, (void*)nullptr);

    // ---- FFN ----
    LPDL(rms_kernel<true>, dim3(TOK), 256, 0, (const float*)h, ln3_w, (void*)xn);
    LPDL((hgemm<true,false,true,false>), gDF, 256, GEMM_SMEM,
         (const __half*)xn, (const __half*)(wh + WH_WI), (const float*)nullptr,
         (void*)ffn, TOK, DFF, DMODEL, (const __half*)nullptr, (void*)nullptr);
    LPDL((hgemm<false,true,false,false>), gDD, 256, GEMM_SMEM,
         (const __half*)ffn, (const __half*)(wh + WH_WO), (const float*)h,
         (void*)h, TOK, DMODEL, DFF, (const __half*)nullptr, (void*)nullptr);

    // ---- Final norm ----
    LPDL(rms_kernel<false>, dim3(TOK), 256, 0, (const float*)h, flnw, (void*)out);

    #undef LPDL
}